// round 3
// baseline (speedup 1.0000x reference)
#include <cuda_runtime.h>
#include <math.h>
#include <stdint.h>

// ---------------- problem constants ----------------
#define BB   32
#define SS   512
#define HH   512
#define NHD  8
#define DK   64
#define KW   7
#define NV   33      // 2*16+1 relative buckets
#define ROWS (BB*SS)            // 16384
#define TOT  (BB*SS*HH)         // 8388608

// ---------------- scratch (device globals: allocation-guard safe) ----------------
__device__ float g_n[TOT];   // LN output
__device__ float g_h[TOT];   // dwconv out / attention out
__device__ float g_q[TOT];
__device__ float g_k[TOT];
__device__ float g_v[TOT];

// ---------------- positional encoding + mask add ----------------
__global__ void pos_add_kernel(const float* __restrict__ x,
                               const int* __restrict__ mask,
                               float* __restrict__ out) {
    int idx = blockIdx.x * 256 + threadIdx.x;
    int h = idx & (HH - 1);
    int s = (idx >> 9) & (SS - 1);
    int b = idx >> 18;
    float pe = 0.f;
    if (s > 0) {
        float pos = (float)(s - 1);
        int i2 = h & ~1;
        float div = expf((float)i2 * (-9.210340371976184f / (float)HH));
        float ang = pos * div;
        pe = (h & 1) ? cosf(ang) : sinf(ang);
    }
    out[idx] = x[idx] + pe * (float)mask[(b << 9) + s];
}

// ---------------- layer norm (one block per row, 256 thr, 2 elems/thr) ----------------
__global__ void ln_kernel(const float* __restrict__ x,
                          const float* __restrict__ gg,
                          const float* __restrict__ bb,
                          float* __restrict__ out) {
    int row = blockIdx.x;
    const float* xr = x + (size_t)row * HH;
    int t = threadIdx.x;
    float v0 = xr[t], v1 = xr[t + 256];
    float s = v0 + v1, sq = v0 * v0 + v1 * v1;
#pragma unroll
    for (int o = 16; o > 0; o >>= 1) {
        s  += __shfl_xor_sync(0xffffffffu, s, o);
        sq += __shfl_xor_sync(0xffffffffu, sq, o);
    }
    __shared__ float ss[8], ssq[8];
    __shared__ float s_mean, s_rstd;
    int w = t >> 5, l = t & 31;
    if (l == 0) { ss[w] = s; ssq[w] = sq; }
    __syncthreads();
    if (t == 0) {
        float S1 = 0.f, S2 = 0.f;
#pragma unroll
        for (int i = 0; i < 8; i++) { S1 += ss[i]; S2 += ssq[i]; }
        float mean = S1 * (1.f / HH);
        float var = S2 * (1.f / HH) - mean * mean;
        s_mean = mean;
        s_rstd = rsqrtf(var + 1e-5f);
    }
    __syncthreads();
    float mean = s_mean, r = s_rstd;
    float* orow = out + (size_t)row * HH;
    orow[t]       = (v0 - mean) * r * gg[t] + bb[t];
    orow[t + 256] = (v1 - mean) * r * gg[t + 256] + bb[t + 256];
}

// ---------------- depthwise conv (k=7, pad=3 along S) ----------------
__global__ void dwconv_kernel(const float* __restrict__ n,
                              const float* __restrict__ w,
                              const float* __restrict__ bias,
                              float* __restrict__ out) {
    int idx = blockIdx.x * 256 + threadIdx.x;
    int c = idx & (HH - 1);
    int s = (idx >> 9) & (SS - 1);
    int b = idx >> 18;
    float acc = bias[c];
    const float* base = n + ((size_t)b * SS) * HH + c;
#pragma unroll
    for (int t = 0; t < KW; t++) {
        int sp = s + t - KW / 2;
        if (sp >= 0 && sp < SS)
            acc += base[(size_t)sp * HH] * w[c * KW + t];
    }
    out[idx] = acc;
}

// ---------------- SGEMM: C[m,n] = act(A[m,:]·W[n,:] + bias[n]) (+ res) ----------------
// A: MxK row-major, W: NxK row-major (torch Linear), 128x128x16 tile, 8x8/thread
template <bool RELU, bool RES>
__global__ void __launch_bounds__(256, 2)
gemm_kernel(const float* __restrict__ A, const float* __restrict__ W,
            const float* __restrict__ bias, const float* res,
            float* out, int Mdim, int Ndim, int Kdim) {
    __shared__ float As[16][132];
    __shared__ float Ws[16][132];
    int bm = blockIdx.y * 128, bn = blockIdx.x * 128;
    int tid = threadIdx.x;
    int tx = tid & 15, ty = tid >> 4;
    float acc[8][8];
#pragma unroll
    for (int i = 0; i < 8; i++)
#pragma unroll
        for (int j = 0; j < 8; j++) acc[i][j] = 0.f;

    for (int k0 = 0; k0 < Kdim; k0 += 16) {
#pragma unroll
        for (int i = 0; i < 2; i++) {
            int idx = tid + (i << 8);        // 0..511
            int row = idx >> 2;
            int c4 = (idx & 3) << 2;
            float4 v = *(const float4*)(A + (size_t)(bm + row) * Kdim + k0 + c4);
            As[c4][row] = v.x; As[c4 + 1][row] = v.y;
            As[c4 + 2][row] = v.z; As[c4 + 3][row] = v.w;
        }
#pragma unroll
        for (int i = 0; i < 2; i++) {
            int idx = tid + (i << 8);
            int row = idx >> 2;
            int c4 = (idx & 3) << 2;
            float4 v = *(const float4*)(W + (size_t)(bn + row) * Kdim + k0 + c4);
            Ws[c4][row] = v.x; Ws[c4 + 1][row] = v.y;
            Ws[c4 + 2][row] = v.z; Ws[c4 + 3][row] = v.w;
        }
        __syncthreads();
#pragma unroll
        for (int k = 0; k < 16; k++) {
            float a[8], bvv[8];
            *(float4*)&a[0]  = *(const float4*)&As[k][ty * 8];
            *(float4*)&a[4]  = *(const float4*)&As[k][ty * 8 + 4];
            *(float4*)&bvv[0] = *(const float4*)&Ws[k][tx * 8];
            *(float4*)&bvv[4] = *(const float4*)&Ws[k][tx * 8 + 4];
#pragma unroll
            for (int i = 0; i < 8; i++)
#pragma unroll
                for (int j = 0; j < 8; j++)
                    acc[i][j] = fmaf(a[i], bvv[j], acc[i][j]);
        }
        __syncthreads();
    }
#pragma unroll
    for (int i = 0; i < 8; i++) {
        int m = bm + ty * 8 + i;
#pragma unroll
        for (int j = 0; j < 8; j += 4) {
            int n0 = bn + tx * 8 + j;
            float4 bq = *(const float4*)(bias + n0);
            float4 o4;
            o4.x = acc[i][j + 0] + bq.x;
            o4.y = acc[i][j + 1] + bq.y;
            o4.z = acc[i][j + 2] + bq.z;
            o4.w = acc[i][j + 3] + bq.w;
            if (RELU) {
                o4.x = fmaxf(o4.x, 0.f); o4.y = fmaxf(o4.y, 0.f);
                o4.z = fmaxf(o4.z, 0.f); o4.w = fmaxf(o4.w, 0.f);
            }
            if (RES) {
                float4 rr = *(const float4*)(res + (size_t)m * Ndim + n0);
                o4.x += rr.x; o4.y += rr.y; o4.z += rr.z; o4.w += rr.w;
            }
            *(float4*)(out + (size_t)m * Ndim + n0) = o4;
        }
    }
}

// ---------------- attention with relative position buckets ----------------
// grid (S/16, NH, B), 256 threads, dynamic smem ~66KB
#define TQ 16
__global__ void __launch_bounds__(256)
attn_kernel(const float* __restrict__ Q, const float* __restrict__ K,
            const float* __restrict__ Vv, const float* __restrict__ EK,
            const float* __restrict__ EV, float* __restrict__ O) {
    int qt = blockIdx.x, h = blockIdx.y, b = blockIdx.z;
    int q0 = qt * TQ;
    extern __shared__ float sm[];
    float* qs   = sm;                    // TQ*DK            = 1024
    float* sc   = qs + TQ * DK;          // TQ*SS            = 8192
    float* kt   = sc + TQ * SS;          // 64*65            = 4160
    float* eb   = kt + 64 * 65;          // NV*65            = 2145
    float* rdot = eb + NV * 65;          // TQ*NV            = 528
    float* wsum = rdot + TQ * NV;        // TQ*NV            = 528
    float* rsum = wsum + TQ * NV;        // TQ               = 16
    int tid = threadIdx.x;

    size_t bh_off = ((size_t)b * SS) * HH + h * DK;

    // load Q tile (16x64)
#pragma unroll
    for (int r = 0; r < 4; r++) {
        int idx = tid + (r << 8);
        int qq = idx >> 6, d = idx & 63;
        qs[qq * DK + d] = Q[bh_off + (size_t)(q0 + qq) * HH + d];
    }
    // load embed_k (33x64) into eb
    for (int idx = tid; idx < NV * DK; idx += 256) {
        int r = idx >> 6, d = idx & 63;
        eb[r * 65 + d] = EK[idx];
    }
    __syncthreads();

    // rdot[q][j] = qs[q]·embed_k[j]
    for (int idx = tid; idx < TQ * NV; idx += 256) {
        int qq = idx / NV, j = idx - qq * NV;
        const float* qp = qs + qq * DK;
        const float* ep = eb + j * 65;
        float a = 0.f;
#pragma unroll
        for (int d = 0; d < DK; d++) a = fmaf(qp[d], ep[d], a);
        rdot[idx] = a;
    }
    __syncthreads();

    // ---- scores: sc[q][k] = q·k + rdot[q][bucket(k-q)] ----
    {
        int kk = tid & 31;    // keys kk, kk+32
        int qp = tid >> 5;    // queries 2qp, 2qp+1
        for (int kt0 = 0; kt0 < SS; kt0 += 64) {
            for (int idx = tid; idx < 64 * DK; idx += 256) {
                int rr = idx >> 6, d = idx & 63;
                kt[rr * 65 + d] = K[bh_off + (size_t)(kt0 + rr) * HH + d];
            }
            __syncthreads();
            float a00 = 0.f, a01 = 0.f, a10 = 0.f, a11 = 0.f;
            const float* q0p = qs + (2 * qp) * DK;
            const float* q1p = q0p + DK;
            const float* k0p = kt + kk * 65;
            const float* k1p = kt + (kk + 32) * 65;
#pragma unroll
            for (int d = 0; d < DK; d++) {
                float qa = q0p[d], qb = q1p[d], ka = k0p[d], kb = k1p[d];
                a00 = fmaf(qa, ka, a00); a01 = fmaf(qa, kb, a01);
                a10 = fmaf(qb, ka, a10); a11 = fmaf(qb, kb, a11);
            }
            int kg0 = kt0 + kk, kg1 = kt0 + kk + 32;
            int qg0 = q0 + 2 * qp, qg1 = qg0 + 1;
            int d00 = kg0 - qg0; d00 = d00 < -16 ? -16 : (d00 > 16 ? 16 : d00);
            int d01 = kg1 - qg0; d01 = d01 < -16 ? -16 : (d01 > 16 ? 16 : d01);
            int d10 = kg0 - qg1; d10 = d10 < -16 ? -16 : (d10 > 16 ? 16 : d10);
            int d11 = kg1 - qg1; d11 = d11 < -16 ? -16 : (d11 > 16 ? 16 : d11);
            sc[(2 * qp) * SS + kg0]     = a00 + rdot[(2 * qp) * NV + d00 + 16];
            sc[(2 * qp) * SS + kg1]     = a01 + rdot[(2 * qp) * NV + d01 + 16];
            sc[(2 * qp + 1) * SS + kg0] = a10 + rdot[(2 * qp + 1) * NV + d10 + 16];
            sc[(2 * qp + 1) * SS + kg1] = a11 + rdot[(2 * qp + 1) * NV + d11 + 16];
            __syncthreads();
        }
    }

    // ---- softmax rows + bucket weight sums ----
    {
        int w = tid >> 5, l = tid & 31;
        for (int rr = w; rr < TQ; rr += 8) {
            float* row = sc + rr * SS;
            int qg = q0 + rr;
            float mx = -1e30f;
            for (int k = l; k < SS; k += 32) mx = fmaxf(mx, row[k]);
#pragma unroll
            for (int o = 16; o > 0; o >>= 1)
                mx = fmaxf(mx, __shfl_xor_sync(0xffffffffu, mx, o));
            float sum = 0.f, w0 = 0.f, w32 = 0.f;
            for (int k = l; k < SS; k += 32) {
                float e = __expf(row[k] - mx);
                row[k] = e;
                sum += e;
                if (k <= qg - 16) w0 += e;
                if (k >= qg + 16) w32 += e;
            }
#pragma unroll
            for (int o = 16; o > 0; o >>= 1) {
                sum += __shfl_xor_sync(0xffffffffu, sum, o);
                w0  += __shfl_xor_sync(0xffffffffu, w0, o);
                w32 += __shfl_xor_sync(0xffffffffu, w32, o);
            }
            __syncwarp();
            if (l == 0) {
                rsum[rr] = sum;
                wsum[rr * NV + 0] = w0;
                wsum[rr * NV + 32] = w32;
            } else {   // lanes 1..31 -> interior buckets j=1..31 (single key each)
                int k = qg + l - 16;
                wsum[rr * NV + l] = (k >= 0 && k < SS) ? row[k] : 0.f;
            }
        }
    }
    __syncthreads();

    // load embed_v over eb
    for (int idx = tid; idx < NV * DK; idx += 256) {
        int r = idx >> 6, d = idx & 63;
        eb[r * 65 + d] = EV[idx];
    }
    __syncthreads();

    // ---- output: o[q][d] = (Σ_k e·v + Σ_j wsum·ev) / rsum ----
    {
        int d2 = tid & 31;   // dims d2, d2+32
        int qp = tid >> 5;   // queries 2qp, 2qp+1
        float o00 = 0.f, o01 = 0.f, o10 = 0.f, o11 = 0.f;
        for (int kt0 = 0; kt0 < SS; kt0 += 64) {
            for (int idx = tid; idx < 64 * DK; idx += 256) {
                int rr = idx >> 6, d = idx & 63;
                kt[rr * 65 + d] = Vv[bh_off + (size_t)(kt0 + rr) * HH + d];
            }
            __syncthreads();
            const float* s0 = sc + (2 * qp) * SS + kt0;
            const float* s1 = s0 + SS;
#pragma unroll 8
            for (int kk = 0; kk < 64; kk++) {
                float va = kt[kk * 65 + d2], vb = kt[kk * 65 + d2 + 32];
                float wa = s0[kk], wb = s1[kk];
                o00 = fmaf(wa, va, o00); o01 = fmaf(wa, vb, o01);
                o10 = fmaf(wb, va, o10); o11 = fmaf(wb, vb, o11);
            }
            __syncthreads();
        }
        const float* ws0 = wsum + (2 * qp) * NV;
        const float* ws1 = ws0 + NV;
#pragma unroll
        for (int j = 0; j < NV; j++) {
            float ea = eb[j * 65 + d2], e2 = eb[j * 65 + d2 + 32];
            float wa = ws0[j], wb = ws1[j];
            o00 = fmaf(wa, ea, o00); o01 = fmaf(wa, e2, o01);
            o10 = fmaf(wb, ea, o10); o11 = fmaf(wb, e2, o11);
        }
        float inv0 = 1.f / rsum[2 * qp];
        float inv1 = 1.f / rsum[2 * qp + 1];
        size_t ob = bh_off + (size_t)(q0 + 2 * qp) * HH + d2;
        O[ob]          = o00 * inv0;
        O[ob + 32]     = o01 * inv0;
        O[ob + HH]      = o10 * inv1;
        O[ob + HH + 32] = o11 * inv1;
    }
}

// ---------------- launcher ----------------
extern "C" void kernel_launch(void* const* d_in, const int* in_sizes, int n_in,
                              void* d_out, int out_size) {
    const float* x    = (const float*)d_in[0];
    const int*   mask = (const int*)d_in[1];
    const float* dw_w = (const float*)d_in[2];
    const float* dw_b = (const float*)d_in[3];
    const float* pw_w = (const float*)d_in[4];
    const float* pw_b = (const float*)d_in[5];
    const float* lcg  = (const float*)d_in[6];
    const float* lcb  = (const float*)d_in[7];
    const float* wq   = (const float*)d_in[8];
    const float* bq   = (const float*)d_in[9];
    const float* wk   = (const float*)d_in[10];
    const float* bk   = (const float*)d_in[11];
    const float* wv   = (const float*)d_in[12];
    const float* bv   = (const float*)d_in[13];
    const float* wo   = (const float*)d_in[14];
    const float* bo   = (const float*)d_in[15];
    const float* ek   = (const float*)d_in[16];
    const float* ev   = (const float*)d_in[17];
    const float* lag  = (const float*)d_in[18];
    const float* lab  = (const float*)d_in[19];
    const float* wff  = (const float*)d_in[20];
    const float* bff  = (const float*)d_in[21];
    const float* lfg  = (const float*)d_in[22];
    const float* lfb  = (const float*)d_in[23];
    float* xo = (float*)d_out;

    float *pn, *ph, *pq, *pk, *pv;
    cudaGetSymbolAddress((void**)&pn, g_n);
    cudaGetSymbolAddress((void**)&ph, g_h);
    cudaGetSymbolAddress((void**)&pq, g_q);
    cudaGetSymbolAddress((void**)&pk, g_k);
    cudaGetSymbolAddress((void**)&pv, g_v);

    const int ATTN_SMEM = (TQ * DK + TQ * SS + 64 * 65 + NV * 65 + 2 * TQ * NV + TQ) * 4;
    cudaFuncSetAttribute((const void*)attn_kernel,
                         cudaFuncAttributeMaxDynamicSharedMemorySize, ATTN_SMEM);

    dim3 gemm_grid(HH / 128, ROWS / 128);

    // 1) x = input + pos_encoding * mask
    pos_add_kernel<<<TOT / 256, 256>>>(x, mask, xo);

    // 2) conv blocks
    for (int i = 0; i < 2; i++) {
        ln_kernel<<<ROWS, 256>>>(xo, lcg + i * HH, lcb + i * HH, pn);
        dwconv_kernel<<<TOT / 256, 256>>>(pn, dw_w + i * HH * KW, dw_b + i * HH, ph);
        gemm_kernel<true, true><<<gemm_grid, 256>>>(ph, pw_w + (size_t)i * HH * HH,
                                                    pw_b + i * HH, xo, xo, ROWS, HH, HH);
    }

    // 3) attention
    ln_kernel<<<ROWS, 256>>>(xo, lag, lab, pn);
    gemm_kernel<false, false><<<gemm_grid, 256>>>(pn, wq, bq, nullptr, pq, ROWS, HH, HH);
    gemm_kernel<false, false><<<gemm_grid, 256>>>(pn, wk, bk, nullptr, pk, ROWS, HH, HH);
    gemm_kernel<false, false><<<gemm_grid, 256>>>(pn, wv, bv, nullptr, pv, ROWS, HH, HH);

    attn_kernel<<<dim3(SS / TQ, NHD, BB), 256, ATTN_SMEM>>>(pq, pk, pv, ek, ev, ph);

    gemm_kernel<false, true><<<gemm_grid, 256>>>(ph, wo, bo, xo, xo, ROWS, HH, HH);

    // 4) FFN
    ln_kernel<<<ROWS, 256>>>(xo, lfg, lfb, pn);
    gemm_kernel<true, true><<<gemm_grid, 256>>>(pn, wff, bff, xo, xo, ROWS, HH, HH);
}

// round 4
// speedup vs baseline: 1.0482x; 1.0482x over previous
#include <cuda_runtime.h>
#include <math.h>
#include <stdint.h>

// ---------------- problem constants ----------------
#define BB   32
#define SS   512
#define HH   512
#define NHD  8
#define DK   64
#define KW   7
#define NV   33      // 2*16+1 relative buckets
#define RS3  (3*HH)  // qkv fused row stride
#define ROWS (BB*SS)            // 16384
#define TOT  (BB*SS*HH)         // 8388608

// ---------------- scratch (device globals: allocation-guard safe) ----------------
__device__ float g_n[TOT];          // LN output
__device__ float g_h[TOT];          // dwconv out / attention out
__device__ float g_qkv[ROWS * RS3]; // fused QKV output
__device__ float g_wqkv[3 * HH * HH];
__device__ float g_bqkv[3 * HH];
__device__ float g_pe[SS * HH];     // positional encoding table

// ---------------- positional encoding table ----------------
__global__ void pe_kernel(float* __restrict__ pe) {
    int idx = blockIdx.x * 256 + threadIdx.x;   // SS*HH / 256 blocks
    int h = idx & (HH - 1);
    int s = idx >> 9;
    float v = 0.f;
    if (s > 0) {
        float pos = (float)(s - 1);
        int i2 = h & ~1;
        float div = expf((float)i2 * (-9.210340371976184f / (float)HH));
        float ang = pos * div;
        v = (h & 1) ? cosf(ang) : sinf(ang);
    }
    pe[idx] = v;
}

// ---------------- x + pe * mask (pure bandwidth) ----------------
__global__ void pos_add_kernel(const float* __restrict__ x,
                               const int* __restrict__ mask,
                               const float* __restrict__ pe,
                               float* __restrict__ out) {
    int idx = blockIdx.x * 256 + threadIdx.x;
    int s = (idx >> 9) & (SS - 1);
    int b = idx >> 18;
    out[idx] = x[idx] + pe[idx & (SS * HH - 1)] * (float)mask[(b << 9) + s];
}

// ---------------- layer norm (one block per row, 256 thr, 2 elems/thr) ----------------
__global__ void ln_kernel(const float* __restrict__ x,
                          const float* __restrict__ gg,
                          const float* __restrict__ bb,
                          float* __restrict__ out) {
    int row = blockIdx.x;
    const float* xr = x + (size_t)row * HH;
    int t = threadIdx.x;
    float v0 = xr[t], v1 = xr[t + 256];
    float s = v0 + v1, sq = v0 * v0 + v1 * v1;
#pragma unroll
    for (int o = 16; o > 0; o >>= 1) {
        s  += __shfl_xor_sync(0xffffffffu, s, o);
        sq += __shfl_xor_sync(0xffffffffu, sq, o);
    }
    __shared__ float ss[8], ssq[8];
    __shared__ float s_mean, s_rstd;
    int w = t >> 5, l = t & 31;
    if (l == 0) { ss[w] = s; ssq[w] = sq; }
    __syncthreads();
    if (t == 0) {
        float S1 = 0.f, S2 = 0.f;
#pragma unroll
        for (int i = 0; i < 8; i++) { S1 += ss[i]; S2 += ssq[i]; }
        float mean = S1 * (1.f / HH);
        float var = S2 * (1.f / HH) - mean * mean;
        s_mean = mean;
        s_rstd = rsqrtf(var + 1e-5f);
    }
    __syncthreads();
    float mean = s_mean, r = s_rstd;
    float* orow = out + (size_t)row * HH;
    orow[t]       = (v0 - mean) * r * gg[t] + bb[t];
    orow[t + 256] = (v1 - mean) * r * gg[t + 256] + bb[t + 256];
}

// ---------------- depthwise conv (k=7, pad=3 along S), smem tiled ----------------
// grid (8 s-tiles, 4 c-tiles, 32 b), 256 threads
__global__ void dwconv_kernel(const float* __restrict__ n,
                              const float* __restrict__ w,
                              const float* __restrict__ bias,
                              float* __restrict__ out) {
    __shared__ float sb[70][128];
    int s0 = blockIdx.x * 64, c0 = blockIdx.y * 128, b = blockIdx.z;
    int tid = threadIdx.x;
    const float* base = n + ((size_t)b * SS) * HH + c0;
    for (int i = tid; i < 70 * 128; i += 256) {
        int r = i >> 7, c = i & 127;
        int sp = s0 + r - 3;
        sb[r][c] = (sp >= 0 && sp < SS) ? base[(size_t)sp * HH + c] : 0.f;
    }
    __syncthreads();
    int c = tid & 127;
    int rr0 = (tid >> 7) * 32;
    float wr[KW];
#pragma unroll
    for (int t = 0; t < KW; t++) wr[t] = w[(c0 + c) * KW + t];
    float bz = bias[c0 + c];
    float* obase = out + ((size_t)b * SS + s0) * HH + c0 + c;
#pragma unroll 4
    for (int r = 0; r < 32; r++) {
        int sl = rr0 + r;
        float acc = bz;
#pragma unroll
        for (int t = 0; t < KW; t++) acc = fmaf(sb[sl + t][c], wr[t], acc);
        obase[(size_t)(sl) * HH] = acc;
    }
}

// ---------------- pipelined SGEMM: C[m,n] = act(A[m,:]·W[n,:] + bias[n]) (+res) ----------------
// A: MxK row-major, W: NxK row-major, 128x128x16 tile, 8x8/thread, 2-stage smem
template <bool RELU, bool RES>
__global__ void __launch_bounds__(256, 2)
gemm_kernel(const float* __restrict__ A, const float* __restrict__ W,
            const float* __restrict__ bias, const float* res,
            float* out, int Mdim, int Ndim, int Kdim) {
    __shared__ float As[2][16][132];
    __shared__ float Ws[2][16][132];
    int bm = blockIdx.y * 128, bn = blockIdx.x * 128;
    int tid = threadIdx.x;
    int tx = tid & 15, ty = tid >> 4;
    float acc[8][8];
#pragma unroll
    for (int i = 0; i < 8; i++)
#pragma unroll
        for (int j = 0; j < 8; j++) acc[i][j] = 0.f;

    int r0 = tid >> 2;            // 0..63
    int c0 = (tid & 3) << 2;      // 0,4,8,12
    const float* Aptr = A + (size_t)(bm + r0) * Kdim + c0;
    const float* Wptr = W + (size_t)(bn + r0) * Kdim + c0;
    size_t half = (size_t)64 * Kdim;

    float4 ra0 = *(const float4*)(Aptr);
    float4 ra1 = *(const float4*)(Aptr + half);
    float4 rw0 = *(const float4*)(Wptr);
    float4 rw1 = *(const float4*)(Wptr + half);

    int buf = 0;
    As[buf][c0 + 0][r0] = ra0.x; As[buf][c0 + 1][r0] = ra0.y;
    As[buf][c0 + 2][r0] = ra0.z; As[buf][c0 + 3][r0] = ra0.w;
    As[buf][c0 + 0][r0 + 64] = ra1.x; As[buf][c0 + 1][r0 + 64] = ra1.y;
    As[buf][c0 + 2][r0 + 64] = ra1.z; As[buf][c0 + 3][r0 + 64] = ra1.w;
    Ws[buf][c0 + 0][r0] = rw0.x; Ws[buf][c0 + 1][r0] = rw0.y;
    Ws[buf][c0 + 2][r0] = rw0.z; Ws[buf][c0 + 3][r0] = rw0.w;
    Ws[buf][c0 + 0][r0 + 64] = rw1.x; Ws[buf][c0 + 1][r0 + 64] = rw1.y;
    Ws[buf][c0 + 2][r0 + 64] = rw1.z; Ws[buf][c0 + 3][r0 + 64] = rw1.w;
    __syncthreads();

    for (int k0 = 16; ; k0 += 16) {
        bool more = (k0 < Kdim);
        if (more) {
            ra0 = *(const float4*)(Aptr + k0);
            ra1 = *(const float4*)(Aptr + half + k0);
            rw0 = *(const float4*)(Wptr + k0);
            rw1 = *(const float4*)(Wptr + half + k0);
        }
#pragma unroll
        for (int k = 0; k < 16; k++) {
            float a[8], bv[8];
            *(float4*)&a[0]  = *(const float4*)&As[buf][k][ty * 8];
            *(float4*)&a[4]  = *(const float4*)&As[buf][k][ty * 8 + 4];
            *(float4*)&bv[0] = *(const float4*)&Ws[buf][k][tx * 8];
            *(float4*)&bv[4] = *(const float4*)&Ws[buf][k][tx * 8 + 4];
#pragma unroll
            for (int i = 0; i < 8; i++)
#pragma unroll
                for (int j = 0; j < 8; j++)
                    acc[i][j] = fmaf(a[i], bv[j], acc[i][j]);
        }
        if (!more) break;
        buf ^= 1;
        As[buf][c0 + 0][r0] = ra0.x; As[buf][c0 + 1][r0] = ra0.y;
        As[buf][c0 + 2][r0] = ra0.z; As[buf][c0 + 3][r0] = ra0.w;
        As[buf][c0 + 0][r0 + 64] = ra1.x; As[buf][c0 + 1][r0 + 64] = ra1.y;
        As[buf][c0 + 2][r0 + 64] = ra1.z; As[buf][c0 + 3][r0 + 64] = ra1.w;
        Ws[buf][c0 + 0][r0] = rw0.x; Ws[buf][c0 + 1][r0] = rw0.y;
        Ws[buf][c0 + 2][r0] = rw0.z; Ws[buf][c0 + 3][r0] = rw0.w;
        Ws[buf][c0 + 0][r0 + 64] = rw1.x; Ws[buf][c0 + 1][r0 + 64] = rw1.y;
        Ws[buf][c0 + 2][r0 + 64] = rw1.z; Ws[buf][c0 + 3][r0 + 64] = rw1.w;
        __syncthreads();
    }

#pragma unroll
    for (int i = 0; i < 8; i++) {
        int m = bm + ty * 8 + i;
#pragma unroll
        for (int j = 0; j < 8; j += 4) {
            int n0 = bn + tx * 8 + j;
            float4 bq = *(const float4*)(bias + n0);
            float4 o4;
            o4.x = acc[i][j + 0] + bq.x;
            o4.y = acc[i][j + 1] + bq.y;
            o4.z = acc[i][j + 2] + bq.z;
            o4.w = acc[i][j + 3] + bq.w;
            if (RELU) {
                o4.x = fmaxf(o4.x, 0.f); o4.y = fmaxf(o4.y, 0.f);
                o4.z = fmaxf(o4.z, 0.f); o4.w = fmaxf(o4.w, 0.f);
            }
            if (RES) {
                float4 rr = *(const float4*)(res + (size_t)m * Ndim + n0);
                o4.x += rr.x; o4.y += rr.y; o4.z += rr.z; o4.w += rr.w;
            }
            *(float4*)(out + (size_t)m * Ndim + n0) = o4;
        }
    }
}

// ---------------- attention with relative position buckets ----------------
// grid (S/16, NH, B), 256 threads, dynamic smem ~66KB
// QKV fused buffer: row stride RS3, Q at +0, K at +HH, V at +2*HH (then + h*DK)
#define TQ 16
__global__ void __launch_bounds__(256)
attn_kernel(const float* __restrict__ QKV, const float* __restrict__ EK,
            const float* __restrict__ EV, float* __restrict__ O) {
    int qt = blockIdx.x, h = blockIdx.y, b = blockIdx.z;
    int q0 = qt * TQ;
    extern __shared__ float sm[];
    float* qs   = sm;                    // TQ*DK
    float* sc   = qs + TQ * DK;          // TQ*SS
    float* kt   = sc + TQ * SS;          // 64*65
    float* eb   = kt + 64 * 65;          // NV*65
    float* rdot = eb + NV * 65;          // TQ*NV
    float* wsum = rdot + TQ * NV;        // TQ*NV
    float* rsum = wsum + TQ * NV;        // TQ
    int tid = threadIdx.x;

    size_t bh_in  = ((size_t)b * SS) * RS3 + h * DK;   // QKV input base
    size_t bh_out = ((size_t)b * SS) * HH  + h * DK;   // output base

    // load Q tile (16x64)
#pragma unroll
    for (int r = 0; r < 4; r++) {
        int idx = tid + (r << 8);
        int qq = idx >> 6, d = idx & 63;
        qs[qq * DK + d] = QKV[bh_in + (size_t)(q0 + qq) * RS3 + d];
    }
    // load embed_k (33x64) into eb
    for (int idx = tid; idx < NV * DK; idx += 256) {
        int r = idx >> 6, d = idx & 63;
        eb[r * 65 + d] = EK[idx];
    }
    __syncthreads();

    // rdot[q][j] = qs[q]·embed_k[j]
    for (int idx = tid; idx < TQ * NV; idx += 256) {
        int qq = idx / NV, j = idx - qq * NV;
        const float* qp = qs + qq * DK;
        const float* ep = eb + j * 65;
        float a = 0.f;
#pragma unroll
        for (int d = 0; d < DK; d++) a = fmaf(qp[d], ep[d], a);
        rdot[idx] = a;
    }
    __syncthreads();

    // ---- scores: sc[q][k] = q·k + rdot[q][bucket(k-q)] ----
    {
        int kk = tid & 31;    // keys kk, kk+32
        int qp = tid >> 5;    // queries 2qp, 2qp+1
        for (int kt0 = 0; kt0 < SS; kt0 += 64) {
            for (int idx = tid; idx < 64 * DK; idx += 256) {
                int rr = idx >> 6, d = idx & 63;
                kt[rr * 65 + d] = QKV[bh_in + HH + (size_t)(kt0 + rr) * RS3 + d];
            }
            __syncthreads();
            float a00 = 0.f, a01 = 0.f, a10 = 0.f, a11 = 0.f;
            const float* q0p = qs + (2 * qp) * DK;
            const float* q1p = q0p + DK;
            const float* k0p = kt + kk * 65;
            const float* k1p = kt + (kk + 32) * 65;
#pragma unroll
            for (int d = 0; d < DK; d++) {
                float qa = q0p[d], qb = q1p[d], ka = k0p[d], kb = k1p[d];
                a00 = fmaf(qa, ka, a00); a01 = fmaf(qa, kb, a01);
                a10 = fmaf(qb, ka, a10); a11 = fmaf(qb, kb, a11);
            }
            int kg0 = kt0 + kk, kg1 = kt0 + kk + 32;
            int qg0 = q0 + 2 * qp, qg1 = qg0 + 1;
            int d00 = kg0 - qg0; d00 = d00 < -16 ? -16 : (d00 > 16 ? 16 : d00);
            int d01 = kg1 - qg0; d01 = d01 < -16 ? -16 : (d01 > 16 ? 16 : d01);
            int d10 = kg0 - qg1; d10 = d10 < -16 ? -16 : (d10 > 16 ? 16 : d10);
            int d11 = kg1 - qg1; d11 = d11 < -16 ? -16 : (d11 > 16 ? 16 : d11);
            sc[(2 * qp) * SS + kg0]     = a00 + rdot[(2 * qp) * NV + d00 + 16];
            sc[(2 * qp) * SS + kg1]     = a01 + rdot[(2 * qp) * NV + d01 + 16];
            sc[(2 * qp + 1) * SS + kg0] = a10 + rdot[(2 * qp + 1) * NV + d10 + 16];
            sc[(2 * qp + 1) * SS + kg1] = a11 + rdot[(2 * qp + 1) * NV + d11 + 16];
            __syncthreads();
        }
    }

    // ---- softmax rows + bucket weight sums ----
    {
        int w = tid >> 5, l = tid & 31;
        for (int rr = w; rr < TQ; rr += 8) {
            float* row = sc + rr * SS;
            int qg = q0 + rr;
            float mx = -1e30f;
            for (int k = l; k < SS; k += 32) mx = fmaxf(mx, row[k]);
#pragma unroll
            for (int o = 16; o > 0; o >>= 1)
                mx = fmaxf(mx, __shfl_xor_sync(0xffffffffu, mx, o));
            float sum = 0.f, w0 = 0.f, w32 = 0.f;
            for (int k = l; k < SS; k += 32) {
                float e = __expf(row[k] - mx);
                row[k] = e;
                sum += e;
                if (k <= qg - 16) w0 += e;
                if (k >= qg + 16) w32 += e;
            }
#pragma unroll
            for (int o = 16; o > 0; o >>= 1) {
                sum += __shfl_xor_sync(0xffffffffu, sum, o);
                w0  += __shfl_xor_sync(0xffffffffu, w0, o);
                w32 += __shfl_xor_sync(0xffffffffu, w32, o);
            }
            __syncwarp();
            if (l == 0) {
                rsum[rr] = sum;
                wsum[rr * NV + 0] = w0;
                wsum[rr * NV + 32] = w32;
            } else {   // lanes 1..31 -> interior buckets j=1..31 (single key each)
                int k = qg + l - 16;
                wsum[rr * NV + l] = (k >= 0 && k < SS) ? row[k] : 0.f;
            }
        }
    }
    __syncthreads();

    // load embed_v over eb
    for (int idx = tid; idx < NV * DK; idx += 256) {
        int r = idx >> 6, d = idx & 63;
        eb[r * 65 + d] = EV[idx];
    }
    __syncthreads();

    // ---- output: o[q][d] = (Σ_k e·v + Σ_j wsum·ev) / rsum ----
    {
        int d2 = tid & 31;   // dims d2, d2+32
        int qp = tid >> 5;   // queries 2qp, 2qp+1
        float o00 = 0.f, o01 = 0.f, o10 = 0.f, o11 = 0.f;
        for (int kt0 = 0; kt0 < SS; kt0 += 64) {
            for (int idx = tid; idx < 64 * DK; idx += 256) {
                int rr = idx >> 6, d = idx & 63;
                kt[rr * 65 + d] = QKV[bh_in + 2 * HH + (size_t)(kt0 + rr) * RS3 + d];
            }
            __syncthreads();
            const float* s0 = sc + (2 * qp) * SS + kt0;
            const float* s1 = s0 + SS;
#pragma unroll 8
            for (int kk = 0; kk < 64; kk++) {
                float va = kt[kk * 65 + d2], vb = kt[kk * 65 + d2 + 32];
                float wa = s0[kk], wb = s1[kk];
                o00 = fmaf(wa, va, o00); o01 = fmaf(wa, vb, o01);
                o10 = fmaf(wb, va, o10); o11 = fmaf(wb, vb, o11);
            }
            __syncthreads();
        }
        const float* ws0 = wsum + (2 * qp) * NV;
        const float* ws1 = ws0 + NV;
#pragma unroll
        for (int j = 0; j < NV; j++) {
            float ea = eb[j * 65 + d2], e2 = eb[j * 65 + d2 + 32];
            float wa = ws0[j], wb = ws1[j];
            o00 = fmaf(wa, ea, o00); o01 = fmaf(wa, e2, o01);
            o10 = fmaf(wb, ea, o10); o11 = fmaf(wb, e2, o11);
        }
        float inv0 = 1.f / rsum[2 * qp];
        float inv1 = 1.f / rsum[2 * qp + 1];
        size_t ob = bh_out + (size_t)(q0 + 2 * qp) * HH + d2;
        O[ob]           = o00 * inv0;
        O[ob + 32]      = o01 * inv0;
        O[ob + HH]      = o10 * inv1;
        O[ob + HH + 32] = o11 * inv1;
    }
}

// ---------------- launcher ----------------
extern "C" void kernel_launch(void* const* d_in, const int* in_sizes, int n_in,
                              void* d_out, int out_size) {
    const float* x    = (const float*)d_in[0];
    const int*   mask = (const int*)d_in[1];
    const float* dw_w = (const float*)d_in[2];
    const float* dw_b = (const float*)d_in[3];
    const float* pw_w = (const float*)d_in[4];
    const float* pw_b = (const float*)d_in[5];
    const float* lcg  = (const float*)d_in[6];
    const float* lcb  = (const float*)d_in[7];
    const float* wq   = (const float*)d_in[8];
    const float* bq   = (const float*)d_in[9];
    const float* wk   = (const float*)d_in[10];
    const float* bk   = (const float*)d_in[11];
    const float* wv   = (const float*)d_in[12];
    const float* bv   = (const float*)d_in[13];
    const float* wo   = (const float*)d_in[14];
    const float* bo   = (const float*)d_in[15];
    const float* ek   = (const float*)d_in[16];
    const float* ev   = (const float*)d_in[17];
    const float* lag  = (const float*)d_in[18];
    const float* lab  = (const float*)d_in[19];
    const float* wff  = (const float*)d_in[20];
    const float* bff  = (const float*)d_in[21];
    const float* lfg  = (const float*)d_in[22];
    const float* lfb  = (const float*)d_in[23];
    float* xo = (float*)d_out;

    float *pn, *ph, *pqkv, *pwqkv, *pbqkv, *ppe;
    cudaGetSymbolAddress((void**)&pn, g_n);
    cudaGetSymbolAddress((void**)&ph, g_h);
    cudaGetSymbolAddress((void**)&pqkv, g_qkv);
    cudaGetSymbolAddress((void**)&pwqkv, g_wqkv);
    cudaGetSymbolAddress((void**)&pbqkv, g_bqkv);
    cudaGetSymbolAddress((void**)&ppe, g_pe);

    // assemble fused QKV weights/bias (device-to-device, capture-legal)
    cudaMemcpyAsync(pwqkv,                 wq, (size_t)HH * HH * 4, cudaMemcpyDeviceToDevice);
    cudaMemcpyAsync(pwqkv + HH * HH,       wk, (size_t)HH * HH * 4, cudaMemcpyDeviceToDevice);
    cudaMemcpyAsync(pwqkv + 2 * HH * HH,   wv, (size_t)HH * HH * 4, cudaMemcpyDeviceToDevice);
    cudaMemcpyAsync(pbqkv,           bq, HH * 4, cudaMemcpyDeviceToDevice);
    cudaMemcpyAsync(pbqkv + HH,      bk, HH * 4, cudaMemcpyDeviceToDevice);
    cudaMemcpyAsync(pbqkv + 2 * HH,  bv, HH * 4, cudaMemcpyDeviceToDevice);

    const int ATTN_SMEM = (TQ * DK + TQ * SS + 64 * 65 + NV * 65 + 2 * TQ * NV + TQ) * 4;
    cudaFuncSetAttribute((const void*)attn_kernel,
                         cudaFuncAttributeMaxDynamicSharedMemorySize, ATTN_SMEM);

    dim3 gemm_grid(HH / 128, ROWS / 128);       // 512 blocks
    dim3 qkv_grid(RS3 / 128, ROWS / 128);       // 1536 blocks
    dim3 dw_grid(8, 4, 32);

    // 0) positional encoding table
    pe_kernel<<<(SS * HH) / 256, 256>>>(ppe);

    // 1) x = input + pe * mask
    pos_add_kernel<<<TOT / 256, 256>>>(x, mask, ppe, xo);

    // 2) conv blocks
    for (int i = 0; i < 2; i++) {
        ln_kernel<<<ROWS, 256>>>(xo, lcg + i * HH, lcb + i * HH, pn);
        dwconv_kernel<<<dw_grid, 256>>>(pn, dw_w + i * HH * KW, dw_b + i * HH, ph);
        gemm_kernel<true, true><<<gemm_grid, 256>>>(ph, pw_w + (size_t)i * HH * HH,
                                                    pw_b + i * HH, xo, xo, ROWS, HH, HH);
    }

    // 3) attention
    ln_kernel<<<ROWS, 256>>>(xo, lag, lab, pn);
    gemm_kernel<false, false><<<qkv_grid, 256>>>(pn, pwqkv, pbqkv, nullptr, pqkv,
                                                 ROWS, RS3, HH);

    attn_kernel<<<dim3(SS / TQ, NHD, BB), 256, ATTN_SMEM>>>(pqkv, ek, ev, ph);

    gemm_kernel<false, true><<<gemm_grid, 256>>>(ph, wo, bo, xo, xo, ROWS, HH, HH);

    // 4) FFN
    ln_kernel<<<ROWS, 256>>>(xo, lfg, lfb, pn);
    gemm_kernel<true, true><<<gemm_grid, 256>>>(pn, wff, bff, xo, xo, ROWS, HH, HH);
}

// round 5
// speedup vs baseline: 1.7672x; 1.6859x over previous
#include <cuda_runtime.h>
#include <math.h>
#include <stdint.h>

// ---------------- problem constants ----------------
#define BB   32
#define SS   512
#define HH   512
#define NHD  8
#define DK   64
#define KW   7
#define NV   33
#define RS3  (3*HH)
#define ROWS (BB*SS)
#define TOT  (BB*SS*HH)

// ---------------- scratch ----------------
__device__ float g_n[TOT];
__device__ float g_h[TOT];
__device__ float g_qkv[ROWS * RS3];
__device__ float g_wqkv[3 * HH * HH];
__device__ float g_bqkv[3 * HH];
__device__ float g_pe[SS * HH];

// ---------------- positional encoding table ----------------
__global__ void pe_kernel(float* __restrict__ pe) {
    int idx = blockIdx.x * 256 + threadIdx.x;
    int h = idx & (HH - 1);
    int s = idx >> 9;
    float v = 0.f;
    if (s > 0) {
        float pos = (float)(s - 1);
        int i2 = h & ~1;
        float div = expf((float)i2 * (-9.210340371976184f / (float)HH));
        float ang = pos * div;
        v = (h & 1) ? cosf(ang) : sinf(ang);
    }
    pe[idx] = v;
}

__global__ void pos_add_kernel(const float* __restrict__ x,
                               const int* __restrict__ mask,
                               const float* __restrict__ pe,
                               float* __restrict__ out) {
    int idx = blockIdx.x * 256 + threadIdx.x;
    int s = (idx >> 9) & (SS - 1);
    int b = idx >> 18;
    out[idx] = x[idx] + pe[idx & (SS * HH - 1)] * (float)mask[(b << 9) + s];
}

// ---------------- layer norm ----------------
__global__ void ln_kernel(const float* __restrict__ x,
                          const float* __restrict__ gg,
                          const float* __restrict__ bb,
                          float* __restrict__ out) {
    int row = blockIdx.x;
    const float* xr = x + (size_t)row * HH;
    int t = threadIdx.x;
    float v0 = xr[t], v1 = xr[t + 256];
    float s = v0 + v1, sq = v0 * v0 + v1 * v1;
#pragma unroll
    for (int o = 16; o > 0; o >>= 1) {
        s  += __shfl_xor_sync(0xffffffffu, s, o);
        sq += __shfl_xor_sync(0xffffffffu, sq, o);
    }
    __shared__ float ss[8], ssq[8];
    __shared__ float s_mean, s_rstd;
    int w = t >> 5, l = t & 31;
    if (l == 0) { ss[w] = s; ssq[w] = sq; }
    __syncthreads();
    if (t == 0) {
        float S1 = 0.f, S2 = 0.f;
#pragma unroll
        for (int i = 0; i < 8; i++) { S1 += ss[i]; S2 += ssq[i]; }
        float mean = S1 * (1.f / HH);
        float var = S2 * (1.f / HH) - mean * mean;
        s_mean = mean;
        s_rstd = rsqrtf(var + 1e-5f);
    }
    __syncthreads();
    float mean = s_mean, r = s_rstd;
    float* orow = out + (size_t)row * HH;
    orow[t]       = (v0 - mean) * r * gg[t] + bb[t];
    orow[t + 256] = (v1 - mean) * r * gg[t + 256] + bb[t + 256];
}

// ---------------- depthwise conv ----------------
__global__ void dwconv_kernel(const float* __restrict__ n,
                              const float* __restrict__ w,
                              const float* __restrict__ bias,
                              float* __restrict__ out) {
    __shared__ float sb[70][128];
    int s0 = blockIdx.x * 64, c0 = blockIdx.y * 128, b = blockIdx.z;
    int tid = threadIdx.x;
    const float* base = n + ((size_t)b * SS) * HH + c0;
    for (int i = tid; i < 70 * 128; i += 256) {
        int r = i >> 7, c = i & 127;
        int sp = s0 + r - 3;
        sb[r][c] = (sp >= 0 && sp < SS) ? base[(size_t)sp * HH + c] : 0.f;
    }
    __syncthreads();
    int c = tid & 127;
    int rr0 = (tid >> 7) * 32;
    float wr[KW];
#pragma unroll
    for (int t = 0; t < KW; t++) wr[t] = w[(c0 + c) * KW + t];
    float bz = bias[c0 + c];
    float* obase = out + ((size_t)b * SS + s0) * HH + c0 + c;
#pragma unroll 4
    for (int r = 0; r < 32; r++) {
        int sl = rr0 + r;
        float acc = bz;
#pragma unroll
        for (int t = 0; t < KW; t++) acc = fmaf(sb[sl + t][c], wr[t], acc);
        obase[(size_t)(sl) * HH] = acc;
    }
}

// ---------------- tf32 tensor-core GEMM ----------------
// C[m,n] = act(A[m,:]·W[n,:] + bias[n]) (+res). A: MxK rm, W: NxK rm.
// 128x128 block, 256 thr = 8 warps (4m x 2n), warp = 32x64 via m16n8k8 mma.
__device__ __forceinline__ uint32_t f2tf(float f) {
    uint32_t u;
    asm("cvt.rna.tf32.f32 %0, %1;" : "=r"(u) : "f"(f));
    return u;
}

#define MMA_TF32(d, a, b)                                                     \
    asm volatile("mma.sync.aligned.m16n8k8.row.col.f32.tf32.tf32.f32 "       \
                 "{%0,%1,%2,%3}, {%4,%5,%6,%7}, {%8,%9}, {%0,%1,%2,%3};"     \
                 : "+f"(d[0]), "+f"(d[1]), "+f"(d[2]), "+f"(d[3])            \
                 : "r"(a[0]), "r"(a[1]), "r"(a[2]), "r"(a[3]),               \
                   "r"(b[0]), "r"(b[1]))

template <bool RELU, bool RES>
__global__ void __launch_bounds__(256, 2)
tgemm(const float* __restrict__ A, const float* __restrict__ W,
      const float* __restrict__ bias, const float* res,
      float* out, int Ndim, int Kdim) {
    __shared__ uint32_t Asm[2][128 * 20];   // [m][k] pad 20
    __shared__ uint32_t Wsm[2][128 * 20];   // [n][k] pad 20
    int bm = blockIdx.y * 128, bn = blockIdx.x * 128;
    int tid = threadIdx.x;
    int wid = tid >> 5, lane = tid & 31;
    int wm = (wid & 3) * 32, wn = (wid >> 2) * 64;
    int r = lane >> 2, c = lane & 3;

    float acc[2][8][4];
#pragma unroll
    for (int i = 0; i < 2; i++)
#pragma unroll
        for (int j = 0; j < 8; j++)
#pragma unroll
            for (int q = 0; q < 4; q++) acc[i][j][q] = 0.f;

    // staging: 128x16 tile per matrix; thread handles 2 float4 per matrix
    int row0 = tid >> 2, c40 = (tid & 3) << 2;
    int row1 = row0 + 64;
    const float* Ap0 = A + (size_t)(bm + row0) * Kdim + c40;
    const float* Ap1 = A + (size_t)(bm + row1) * Kdim + c40;
    const float* Wp0 = W + (size_t)(bn + row0) * Kdim + c40;
    const float* Wp1 = W + (size_t)(bn + row1) * Kdim + c40;
    int so0 = row0 * 20 + c40, so1 = row1 * 20 + c40;

    float4 a0 = *(const float4*)Ap0;
    float4 a1 = *(const float4*)Ap1;
    float4 w0 = *(const float4*)Wp0;
    float4 w1 = *(const float4*)Wp1;

    int buf = 0;
    {
        uint4 u;
        u.x = f2tf(a0.x); u.y = f2tf(a0.y); u.z = f2tf(a0.z); u.w = f2tf(a0.w);
        *(uint4*)&Asm[buf][so0] = u;
        u.x = f2tf(a1.x); u.y = f2tf(a1.y); u.z = f2tf(a1.z); u.w = f2tf(a1.w);
        *(uint4*)&Asm[buf][so1] = u;
        u.x = f2tf(w0.x); u.y = f2tf(w0.y); u.z = f2tf(w0.z); u.w = f2tf(w0.w);
        *(uint4*)&Wsm[buf][so0] = u;
        u.x = f2tf(w1.x); u.y = f2tf(w1.y); u.z = f2tf(w1.z); u.w = f2tf(w1.w);
        *(uint4*)&Wsm[buf][so1] = u;
    }
    __syncthreads();

    int nk = Kdim >> 4;
    for (int s = 1;; s++) {
        bool more = (s < nk);
        if (more) {
            a0 = *(const float4*)(Ap0 + s * 16);
            a1 = *(const float4*)(Ap1 + s * 16);
            w0 = *(const float4*)(Wp0 + s * 16);
            w1 = *(const float4*)(Wp1 + s * 16);
        }
#pragma unroll
        for (int kk = 0; kk < 2; kk++) {
            uint32_t af[2][4], bf[8][2];
#pragma unroll
            for (int i = 0; i < 2; i++) {
                const uint32_t* p = &Asm[buf][(wm + i * 16 + r) * 20 + kk * 8 + c];
                af[i][0] = p[0];
                af[i][1] = p[160];      // +8 rows
                af[i][2] = p[4];
                af[i][3] = p[164];
            }
#pragma unroll
            for (int j = 0; j < 8; j++) {
                const uint32_t* p = &Wsm[buf][(wn + j * 8 + r) * 20 + kk * 8 + c];
                bf[j][0] = p[0];
                bf[j][1] = p[4];
            }
#pragma unroll
            for (int i = 0; i < 2; i++)
#pragma unroll
                for (int j = 0; j < 8; j++)
                    MMA_TF32(acc[i][j], af[i], bf[j]);
        }
        if (!more) break;
        buf ^= 1;
        {
            uint4 u;
            u.x = f2tf(a0.x); u.y = f2tf(a0.y); u.z = f2tf(a0.z); u.w = f2tf(a0.w);
            *(uint4*)&Asm[buf][so0] = u;
            u.x = f2tf(a1.x); u.y = f2tf(a1.y); u.z = f2tf(a1.z); u.w = f2tf(a1.w);
            *(uint4*)&Asm[buf][so1] = u;
            u.x = f2tf(w0.x); u.y = f2tf(w0.y); u.z = f2tf(w0.z); u.w = f2tf(w0.w);
            *(uint4*)&Wsm[buf][so0] = u;
            u.x = f2tf(w1.x); u.y = f2tf(w1.y); u.z = f2tf(w1.z); u.w = f2tf(w1.w);
            *(uint4*)&Wsm[buf][so1] = u;
        }
        __syncthreads();
    }

    // epilogue
#pragma unroll
    for (int i = 0; i < 2; i++) {
        int m0 = bm + wm + i * 16 + r;
#pragma unroll
        for (int j = 0; j < 8; j++) {
            int n0 = bn + wn + j * 8 + 2 * c;
            float2 b2 = *(const float2*)(bias + n0);
            float v0 = acc[i][j][0] + b2.x;
            float v1 = acc[i][j][1] + b2.y;
            float v2 = acc[i][j][2] + b2.x;
            float v3 = acc[i][j][3] + b2.y;
            if (RELU) {
                v0 = fmaxf(v0, 0.f); v1 = fmaxf(v1, 0.f);
                v2 = fmaxf(v2, 0.f); v3 = fmaxf(v3, 0.f);
            }
            if (RES) {
                float2 r0 = *(const float2*)(res + (size_t)m0 * Ndim + n0);
                float2 r1 = *(const float2*)(res + (size_t)(m0 + 8) * Ndim + n0);
                v0 += r0.x; v1 += r0.y; v2 += r1.x; v3 += r1.y;
            }
            float2 o0 = {v0, v1}, o1 = {v2, v3};
            *(float2*)(out + (size_t)m0 * Ndim + n0) = o0;
            *(float2*)(out + (size_t)(m0 + 8) * Ndim + n0) = o1;
        }
    }
}

// ---------------- attention (TQ=32, 256-key tiles, rel-pos buckets) ----------------
#define TQ  32
#define SCS 513

__global__ void __launch_bounds__(256)
attn_kernel(const float* __restrict__ QKV, const float* __restrict__ EK,
            const float* __restrict__ EV, float* __restrict__ O) {
    int qt = blockIdx.x, h = blockIdx.y, b = blockIdx.z;
    int q0 = qt * TQ;
    extern __shared__ float sm[];
    float* qs   = sm;                 // 32*65   = 2080 (reused as reduction buf)
    float* sc   = qs + 2080;          // 32*513  = 16416
    float* kt   = sc + 16416;         // 256*65  = 16640
    float* eb   = kt + 16640;         // 33*65   = 2145
    float* rdot = eb + 2145;          // 32*33   = 1056
    float* wsum = rdot + 1056;        // 1056
    float* rsum = wsum + 1056;        // 32
    int tid = threadIdx.x;

    size_t bh_in  = ((size_t)b * SS) * RS3 + h * DK;
    size_t bh_out = ((size_t)b * SS) * HH  + h * DK;

    // load Q tile (32x64) into qs (stride 65)
#pragma unroll
    for (int i = 0; i < 8; i++) {
        int idx = tid + (i << 8);
        int qq = idx >> 6, d = idx & 63;
        qs[qq * 65 + d] = QKV[bh_in + (size_t)(q0 + qq) * RS3 + d];
    }
    // load embed_k into eb (stride 65)
    for (int idx = tid; idx < NV * DK; idx += 256) {
        int r = idx >> 6, d = idx & 63;
        eb[r * 65 + d] = EK[idx];
    }
    __syncthreads();

    // rdot[q][j] = q·embed_k[j]
    for (int idx = tid; idx < TQ * NV; idx += 256) {
        int qq = idx / NV, j = idx - qq * NV;
        const float* qp = qs + qq * 65;
        const float* ep = eb + j * 65;
        float a = 0.f;
#pragma unroll
        for (int d = 0; d < DK; d++) a = fmaf(qp[d], ep[d], a);
        rdot[idx] = a;
    }
    __syncthreads();

    // ---- QK: 4q x 8k per thread over 256-key tiles ----
    {
        int qgrp = tid >> 5;     // warp -> 4 q rows
        int kl = tid & 31;
        for (int kt0 = 0; kt0 < SS; kt0 += 256) {
#pragma unroll
            for (int i = 0; i < 16; i++) {
                int f = tid + (i << 8);
                int rr = f >> 4, c4 = (f & 15) << 2;
                float4 v = *(const float4*)(QKV + bh_in + HH +
                                            (size_t)(kt0 + rr) * RS3 + c4);
                float* dst = kt + rr * 65 + c4;
                dst[0] = v.x; dst[1] = v.y; dst[2] = v.z; dst[3] = v.w;
            }
            __syncthreads();
            float acc[4][8];
#pragma unroll
            for (int i = 0; i < 4; i++)
#pragma unroll
                for (int j = 0; j < 8; j++) acc[i][j] = 0.f;
            const float* qp = qs + qgrp * 4 * 65;
#pragma unroll 8
            for (int d = 0; d < 64; d++) {
                float q0v = qp[d], q1v = qp[65 + d], q2v = qp[130 + d], q3v = qp[195 + d];
#pragma unroll
                for (int j = 0; j < 8; j++) {
                    float kv = kt[(kl + 32 * j) * 65 + d];
                    acc[0][j] = fmaf(q0v, kv, acc[0][j]);
                    acc[1][j] = fmaf(q1v, kv, acc[1][j]);
                    acc[2][j] = fmaf(q2v, kv, acc[2][j]);
                    acc[3][j] = fmaf(q3v, kv, acc[3][j]);
                }
            }
#pragma unroll
            for (int i = 0; i < 4; i++) {
                int q = qgrp * 4 + i, qg = q0 + q;
#pragma unroll
                for (int j = 0; j < 8; j++) {
                    int k = kt0 + kl + 32 * j;
                    int dd = k - qg;
                    dd = dd < -16 ? -16 : (dd > 16 ? 16 : dd);
                    sc[q * SCS + k] = acc[i][j] + rdot[q * NV + dd + 16];
                }
            }
            __syncthreads();
        }
    }

    // ---- softmax rows + bucket weight sums ----
    {
        int w = tid >> 5, l = tid & 31;
        for (int rr = w; rr < TQ; rr += 8) {
            float* row = sc + rr * SCS;
            int qg = q0 + rr;
            float mx = -1e30f;
            for (int k = l; k < SS; k += 32) mx = fmaxf(mx, row[k]);
#pragma unroll
            for (int o = 16; o > 0; o >>= 1)
                mx = fmaxf(mx, __shfl_xor_sync(0xffffffffu, mx, o));
            float sum = 0.f, w0 = 0.f, w32 = 0.f;
            for (int k = l; k < SS; k += 32) {
                float e = __expf(row[k] - mx);
                row[k] = e;
                sum += e;
                if (k <= qg - 16) w0 += e;
                if (k >= qg + 16) w32 += e;
            }
#pragma unroll
            for (int o = 16; o > 0; o >>= 1) {
                sum += __shfl_xor_sync(0xffffffffu, sum, o);
                w0  += __shfl_xor_sync(0xffffffffu, w0, o);
                w32 += __shfl_xor_sync(0xffffffffu, w32, o);
            }
            __syncwarp();
            if (l == 0) {
                rsum[rr] = sum;
                wsum[rr * NV + 0] = w0;
                wsum[rr * NV + 32] = w32;
            } else {
                int k = qg + l - 16;
                wsum[rr * NV + l] = (k >= 0 && k < SS) ? row[k] : 0.f;
            }
        }
    }
    __syncthreads();

    // reload eb with embed_v
    for (int idx = tid; idx < NV * DK; idx += 256) {
        int r = idx >> 6, d = idx & 63;
        eb[r * 65 + d] = EV[idx];
    }
    __syncthreads();

    // ---- PV: thread = (half over k, 4q x 4d); d strided by 16 ----
    {
        int half = tid >> 7, pos = tid & 127;
        int qg2 = pos >> 4, dg = pos & 15;
        float o[4][4];
#pragma unroll
        for (int i = 0; i < 4; i++)
#pragma unroll
            for (int j = 0; j < 4; j++) o[i][j] = 0.f;

        for (int kt0 = 0; kt0 < SS; kt0 += 256) {
#pragma unroll
            for (int i = 0; i < 16; i++) {
                int f = tid + (i << 8);
                int rr = f >> 4, c4 = (f & 15) << 2;
                float4 v = *(const float4*)(QKV + bh_in + 2 * HH +
                                            (size_t)(kt0 + rr) * RS3 + c4);
                float* dst = kt + rr * 65 + c4;
                dst[0] = v.x; dst[1] = v.y; dst[2] = v.z; dst[3] = v.w;
            }
            __syncthreads();
            int kb = half << 7;
            const float* s0 = sc + (qg2 * 4 + 0) * SCS + kt0 + kb;
            const float* s1 = s0 + SCS;
            const float* s2 = s1 + SCS;
            const float* s3 = s2 + SCS;
#pragma unroll 4
            for (int kk = 0; kk < 128; kk++) {
                float w0 = s0[kk], w1 = s1[kk], w2 = s2[kk], w3 = s3[kk];
                const float* vp = kt + (kb + kk) * 65 + dg;
                float v0 = vp[0], v1 = vp[16], v2 = vp[32], v3 = vp[48];
                o[0][0] = fmaf(w0, v0, o[0][0]); o[0][1] = fmaf(w0, v1, o[0][1]);
                o[0][2] = fmaf(w0, v2, o[0][2]); o[0][3] = fmaf(w0, v3, o[0][3]);
                o[1][0] = fmaf(w1, v0, o[1][0]); o[1][1] = fmaf(w1, v1, o[1][1]);
                o[1][2] = fmaf(w1, v2, o[1][2]); o[1][3] = fmaf(w1, v3, o[1][3]);
                o[2][0] = fmaf(w2, v0, o[2][0]); o[2][1] = fmaf(w2, v1, o[2][1]);
                o[2][2] = fmaf(w2, v2, o[2][2]); o[2][3] = fmaf(w2, v3, o[2][3]);
                o[3][0] = fmaf(w3, v0, o[3][0]); o[3][1] = fmaf(w3, v1, o[3][1]);
                o[3][2] = fmaf(w3, v2, o[3][2]); o[3][3] = fmaf(w3, v3, o[3][3]);
            }
            __syncthreads();
        }

        // reduce halves via qs (free now)
        if (half == 1) {
#pragma unroll
            for (int i = 0; i < 4; i++)
#pragma unroll
                for (int j = 0; j < 4; j++)
                    qs[pos * 16 + i * 4 + j] = o[i][j];
        }
        __syncthreads();
        if (half == 0) {
#pragma unroll
            for (int i = 0; i < 4; i++) {
                int q = qg2 * 4 + i;
                float a0 = o[i][0] + qs[pos * 16 + i * 4 + 0];
                float a1 = o[i][1] + qs[pos * 16 + i * 4 + 1];
                float a2 = o[i][2] + qs[pos * 16 + i * 4 + 2];
                float a3 = o[i][3] + qs[pos * 16 + i * 4 + 3];
#pragma unroll
                for (int jb = 0; jb < NV; jb++) {
                    float wv = wsum[q * NV + jb];
                    const float* ep = eb + jb * 65 + dg;
                    a0 = fmaf(wv, ep[0], a0);
                    a1 = fmaf(wv, ep[16], a1);
                    a2 = fmaf(wv, ep[32], a2);
                    a3 = fmaf(wv, ep[48], a3);
                }
                float inv = 1.f / rsum[q];
                size_t ob = bh_out + (size_t)(q0 + q) * HH + dg;
                O[ob]      = a0 * inv;
                O[ob + 16] = a1 * inv;
                O[ob + 32] = a2 * inv;
                O[ob + 48] = a3 * inv;
            }
        }
    }
}

// ---------------- launcher ----------------
extern "C" void kernel_launch(void* const* d_in, const int* in_sizes, int n_in,
                              void* d_out, int out_size) {
    const float* x    = (const float*)d_in[0];
    const int*   mask = (const int*)d_in[1];
    const float* dw_w = (const float*)d_in[2];
    const float* dw_b = (const float*)d_in[3];
    const float* pw_w = (const float*)d_in[4];
    const float* pw_b = (const float*)d_in[5];
    const float* lcg  = (const float*)d_in[6];
    const float* lcb  = (const float*)d_in[7];
    const float* wq   = (const float*)d_in[8];
    const float* bq   = (const float*)d_in[9];
    const float* wk   = (const float*)d_in[10];
    const float* bk   = (const float*)d_in[11];
    const float* wv   = (const float*)d_in[12];
    const float* bv   = (const float*)d_in[13];
    const float* wo   = (const float*)d_in[14];
    const float* bo   = (const float*)d_in[15];
    const float* ek   = (const float*)d_in[16];
    const float* ev   = (const float*)d_in[17];
    const float* lag  = (const float*)d_in[18];
    const float* lab  = (const float*)d_in[19];
    const float* wff  = (const float*)d_in[20];
    const float* bff  = (const float*)d_in[21];
    const float* lfg  = (const float*)d_in[22];
    const float* lfb  = (const float*)d_in[23];
    float* xo = (float*)d_out;

    float *pn, *ph, *pqkv, *pwqkv, *pbqkv, *ppe;
    cudaGetSymbolAddress((void**)&pn, g_n);
    cudaGetSymbolAddress((void**)&ph, g_h);
    cudaGetSymbolAddress((void**)&pqkv, g_qkv);
    cudaGetSymbolAddress((void**)&pwqkv, g_wqkv);
    cudaGetSymbolAddress((void**)&pbqkv, g_bqkv);
    cudaGetSymbolAddress((void**)&ppe, g_pe);

    cudaMemcpyAsync(pwqkv,               wq, (size_t)HH * HH * 4, cudaMemcpyDeviceToDevice);
    cudaMemcpyAsync(pwqkv + HH * HH,     wk, (size_t)HH * HH * 4, cudaMemcpyDeviceToDevice);
    cudaMemcpyAsync(pwqkv + 2 * HH * HH, wv, (size_t)HH * HH * 4, cudaMemcpyDeviceToDevice);
    cudaMemcpyAsync(pbqkv,          bq, HH * 4, cudaMemcpyDeviceToDevice);
    cudaMemcpyAsync(pbqkv + HH,     bk, HH * 4, cudaMemcpyDeviceToDevice);
    cudaMemcpyAsync(pbqkv + 2 * HH, bv, HH * 4, cudaMemcpyDeviceToDevice);

    const int ATTN_SMEM = (2080 + 16416 + 16640 + 2145 + 1056 + 1056 + 32) * 4;
    cudaFuncSetAttribute((const void*)attn_kernel,
                         cudaFuncAttributeMaxDynamicSharedMemorySize, ATTN_SMEM);

    dim3 gemm_grid(HH / 128, ROWS / 128);
    dim3 qkv_grid(RS3 / 128, ROWS / 128);
    dim3 dw_grid(8, 4, 32);

    pe_kernel<<<(SS * HH) / 256, 256>>>(ppe);
    pos_add_kernel<<<TOT / 256, 256>>>(x, mask, ppe, xo);

    for (int i = 0; i < 2; i++) {
        ln_kernel<<<ROWS, 256>>>(xo, lcg + i * HH, lcb + i * HH, pn);
        dwconv_kernel<<<dw_grid, 256>>>(pn, dw_w + i * HH * KW, dw_b + i * HH, ph);
        tgemm<true, true><<<gemm_grid, 256>>>(ph, pw_w + (size_t)i * HH * HH,
                                              pw_b + i * HH, xo, xo, HH, HH);
    }

    ln_kernel<<<ROWS, 256>>>(xo, lag, lab, pn);
    tgemm<false, false><<<qkv_grid, 256>>>(pn, pwqkv, pbqkv, nullptr, pqkv, RS3, HH);

    attn_kernel<<<dim3(SS / TQ, NHD, BB), 256, ATTN_SMEM>>>(pqkv, ek, ev, ph);

    tgemm<false, true><<<gemm_grid, 256>>>(ph, wo, bo, xo, xo, HH, HH);

    ln_kernel<<<ROWS, 256>>>(xo, lfg, lfb, pn);
    tgemm<true, true><<<gemm_grid, 256>>>(pn, wff, bff, xo, xo, HH, HH);
}

// round 7
// speedup vs baseline: 1.8479x; 1.0457x over previous
#include <cuda_runtime.h>
#include <math.h>
#include <stdint.h>

// ---------------- problem constants ----------------
#define BB   32
#define SS   512
#define HH   512
#define NHD  8
#define DK   64
#define KW   7
#define NV   33
#define RS3  (3*HH)
#define ROWS (BB*SS)
#define TOT  (BB*SS*HH)

// ---------------- scratch ----------------
__device__ float g_h[TOT];
__device__ float g_qkv[ROWS * RS3];
__device__ float g_wqkv[3 * HH * HH];
__device__ float g_bqkv[3 * HH];
__device__ float g_pe[SS * HH];
__device__ float g_stats[ROWS * 2];

// ---------------- tf32 helpers ----------------
__device__ __forceinline__ uint32_t f2tf(float f) {
    uint32_t u;
    asm("cvt.rna.tf32.f32 %0, %1;" : "=r"(u) : "f"(f));
    return u;
}
__device__ __forceinline__ float f2tff(float f) {
    return __uint_as_float(f2tf(f));
}
__device__ __forceinline__ void split2(float v, float& hi, float& lo) {
    hi = f2tff(v);
    lo = f2tff(v - hi);
}
#define U(x) __float_as_uint(x)

#define MMA_TF32(d, a, b)                                                     \
    asm volatile("mma.sync.aligned.m16n8k8.row.col.f32.tf32.tf32.f32 "       \
                 "{%0,%1,%2,%3}, {%4,%5,%6,%7}, {%8,%9}, {%0,%1,%2,%3};"     \
                 : "+f"(d[0]), "+f"(d[1]), "+f"(d[2]), "+f"(d[3])            \
                 : "r"(a[0]), "r"(a[1]), "r"(a[2]), "r"(a[3]),               \
                   "r"(b[0]), "r"(b[1]))

// ---------------- positional encoding table ----------------
__global__ void pe_kernel(float* __restrict__ pe) {
    int idx = blockIdx.x * 256 + threadIdx.x;
    int h = idx & (HH - 1);
    int s = idx >> 9;
    float v = 0.f;
    if (s > 0) {
        float pos = (float)(s - 1);
        int i2 = h & ~1;
        float div = expf((float)i2 * (-9.210340371976184f / (float)HH));
        float ang = pos * div;
        v = (h & 1) ? cosf(ang) : sinf(ang);
    }
    pe[idx] = v;
}

__global__ void pos_add_kernel(const float* __restrict__ x,
                               const int* __restrict__ mask,
                               const float* __restrict__ pe,
                               float* __restrict__ out) {
    int idx = blockIdx.x * 256 + threadIdx.x;
    int s = (idx >> 9) & (SS - 1);
    int b = idx >> 18;
    out[idx] = x[idx] + pe[idx & (SS * HH - 1)] * (float)mask[(b << 9) + s];
}

// ---------------- x += h ----------------
__global__ void add_kernel(float* __restrict__ x, const float* __restrict__ h) {
    int i = blockIdx.x * 256 + threadIdx.x;
    float4 a = ((float4*)x)[i];
    float4 b = ((const float4*)h)[i];
    a.x += b.x; a.y += b.y; a.z += b.z; a.w += b.w;
    ((float4*)x)[i] = a;
}

// ---------------- LN stats: mean/rstd per row ----------------
__global__ void ln_stats(const float* __restrict__ x, float* __restrict__ stats) {
    int row = blockIdx.x * 8 + (threadIdx.x >> 5);
    int lane = threadIdx.x & 31;
    const float4* xr = (const float4*)(x + (size_t)row * HH);
    float s = 0.f, sq = 0.f;
#pragma unroll
    for (int i = 0; i < 4; i++) {
        float4 v = xr[lane + i * 32];
        s += v.x + v.y + v.z + v.w;
        sq += v.x * v.x + v.y * v.y + v.z * v.z + v.w * v.w;
    }
#pragma unroll
    for (int o = 16; o > 0; o >>= 1) {
        s  += __shfl_xor_sync(0xffffffffu, s, o);
        sq += __shfl_xor_sync(0xffffffffu, sq, o);
    }
    if (lane == 0) {
        float mean = s * (1.f / HH);
        float var = sq * (1.f / HH) - mean * mean;
        stats[row * 2] = mean;
        stats[row * 2 + 1] = rsqrtf(var + 1e-5f);
    }
}

// ---------------- depthwise conv with fused LN ----------------
__global__ void dwconv_kernel(const float* __restrict__ x,
                              const float* __restrict__ stats,
                              const float* __restrict__ lg,
                              const float* __restrict__ lb,
                              const float* __restrict__ w,
                              const float* __restrict__ bias,
                              float* __restrict__ out) {
    __shared__ float sb[70][128];
    __shared__ float2 sstat[70];
    int s0 = blockIdx.x * 64, c0 = blockIdx.y * 128, b = blockIdx.z;
    int tid = threadIdx.x;
    if (tid < 70) {
        int sp = s0 + tid - 3;
        float2 st = {0.f, 0.f};
        if (sp >= 0 && sp < SS) st = *(const float2*)(stats + ((size_t)b * SS + sp) * 2);
        sstat[tid] = st;
    }
    __syncthreads();
    const float* base = x + ((size_t)b * SS) * HH + c0;
    for (int i = tid; i < 70 * 128; i += 256) {
        int r = i >> 7, c = i & 127;
        int sp = s0 + r - 3;
        float v = 0.f;
        if (sp >= 0 && sp < SS) {
            float raw = base[(size_t)sp * HH + c];
            float2 st = sstat[r];
            v = (raw - st.x) * st.y * lg[c0 + c] + lb[c0 + c];
        }
        sb[r][c] = v;
    }
    __syncthreads();
    int c = tid & 127;
    int rr0 = (tid >> 7) * 32;
    float wr[KW];
#pragma unroll
    for (int t = 0; t < KW; t++) wr[t] = w[(c0 + c) * KW + t];
    float bz = bias[c0 + c];
    float* obase = out + ((size_t)b * SS + s0) * HH + c0 + c;
#pragma unroll 4
    for (int r = 0; r < 32; r++) {
        int sl = rr0 + r;
        float acc = bz;
#pragma unroll
        for (int t = 0; t < KW; t++) acc = fmaf(sb[sl + t][c], wr[t], acc);
        obase[(size_t)(sl) * HH] = acc;
    }
}

// ---------------- tf32 tensor-core GEMM (optional fused LN on A) ----------------
template <bool LNA, bool RELU, bool RES>
__global__ void __launch_bounds__(256, 2)
tgemm(const float* __restrict__ A, const float* __restrict__ W,
      const float* __restrict__ bias, const float* res,
      const float* __restrict__ stats, const float* __restrict__ lng,
      const float* __restrict__ lnb,
      float* out, int Ndim, int Kdim) {
    __shared__ uint32_t Asm[2][128 * 20];
    __shared__ uint32_t Wsm[2][128 * 20];
    int bm = blockIdx.y * 128, bn = blockIdx.x * 128;
    int tid = threadIdx.x;
    int wid = tid >> 5, lane = tid & 31;
    int wm = (wid & 3) * 32, wn = (wid >> 2) * 64;
    int r = lane >> 2, c = lane & 3;

    float acc[2][8][4];
#pragma unroll
    for (int i = 0; i < 2; i++)
#pragma unroll
        for (int j = 0; j < 8; j++)
#pragma unroll
            for (int q = 0; q < 4; q++) acc[i][j][q] = 0.f;

    int row0 = tid >> 2, c40 = (tid & 3) << 2;
    int row1 = row0 + 64;
    const float* Ap0 = A + (size_t)(bm + row0) * Kdim + c40;
    const float* Ap1 = A + (size_t)(bm + row1) * Kdim + c40;
    const float* Wp0 = W + (size_t)(bn + row0) * Kdim + c40;
    const float* Wp1 = W + (size_t)(bn + row1) * Kdim + c40;
    int so0 = row0 * 20 + c40, so1 = row1 * 20 + c40;

    float m0 = 0.f, r0s = 1.f, m1 = 0.f, r1s = 1.f;
    if (LNA) {
        float2 st0 = *(const float2*)(stats + (size_t)(bm + row0) * 2);
        float2 st1 = *(const float2*)(stats + (size_t)(bm + row1) * 2);
        m0 = st0.x; r0s = st0.y; m1 = st1.x; r1s = st1.y;
    }

    float4 a0 = *(const float4*)Ap0;
    float4 a1 = *(const float4*)Ap1;
    float4 w0 = *(const float4*)Wp0;
    float4 w1 = *(const float4*)Wp1;
    float4 g4, b4;
    if (LNA) {
        g4 = *(const float4*)(lng + c40);
        b4 = *(const float4*)(lnb + c40);
    }

    int buf = 0;
    int nk = Kdim >> 4;
    for (int s = 1;; s++) {
        {
            float4 ta0 = a0, ta1 = a1;
            if (LNA) {
                ta0.x = (a0.x - m0) * r0s * g4.x + b4.x;
                ta0.y = (a0.y - m0) * r0s * g4.y + b4.y;
                ta0.z = (a0.z - m0) * r0s * g4.z + b4.z;
                ta0.w = (a0.w - m0) * r0s * g4.w + b4.w;
                ta1.x = (a1.x - m1) * r1s * g4.x + b4.x;
                ta1.y = (a1.y - m1) * r1s * g4.y + b4.y;
                ta1.z = (a1.z - m1) * r1s * g4.z + b4.z;
                ta1.w = (a1.w - m1) * r1s * g4.w + b4.w;
            }
            uint4 u;
            u.x = f2tf(ta0.x); u.y = f2tf(ta0.y); u.z = f2tf(ta0.z); u.w = f2tf(ta0.w);
            *(uint4*)&Asm[buf][so0] = u;
            u.x = f2tf(ta1.x); u.y = f2tf(ta1.y); u.z = f2tf(ta1.z); u.w = f2tf(ta1.w);
            *(uint4*)&Asm[buf][so1] = u;
            u.x = f2tf(w0.x); u.y = f2tf(w0.y); u.z = f2tf(w0.z); u.w = f2tf(w0.w);
            *(uint4*)&Wsm[buf][so0] = u;
            u.x = f2tf(w1.x); u.y = f2tf(w1.y); u.z = f2tf(w1.z); u.w = f2tf(w1.w);
            *(uint4*)&Wsm[buf][so1] = u;
        }
        __syncthreads();
        bool more = (s < nk);
        if (more) {
            a0 = *(const float4*)(Ap0 + s * 16);
            a1 = *(const float4*)(Ap1 + s * 16);
            w0 = *(const float4*)(Wp0 + s * 16);
            w1 = *(const float4*)(Wp1 + s * 16);
            if (LNA) {
                g4 = *(const float4*)(lng + s * 16 + c40);
                b4 = *(const float4*)(lnb + s * 16 + c40);
            }
        }
#pragma unroll
        for (int kk = 0; kk < 2; kk++) {
            uint32_t af[2][4], bf[8][2];
#pragma unroll
            for (int i = 0; i < 2; i++) {
                const uint32_t* p = &Asm[buf][(wm + i * 16 + r) * 20 + kk * 8 + c];
                af[i][0] = p[0];
                af[i][1] = p[160];
                af[i][2] = p[4];
                af[i][3] = p[164];
            }
#pragma unroll
            for (int j = 0; j < 8; j++) {
                const uint32_t* p = &Wsm[buf][(wn + j * 8 + r) * 20 + kk * 8 + c];
                bf[j][0] = p[0];
                bf[j][1] = p[4];
            }
#pragma unroll
            for (int i = 0; i < 2; i++)
#pragma unroll
                for (int j = 0; j < 8; j++)
                    MMA_TF32(acc[i][j], af[i], bf[j]);
        }
        if (!more) break;
        buf ^= 1;
    }

#pragma unroll
    for (int i = 0; i < 2; i++) {
        int m0i = bm + wm + i * 16 + r;
#pragma unroll
        for (int j = 0; j < 8; j++) {
            int n0 = bn + wn + j * 8 + 2 * c;
            float2 b2 = *(const float2*)(bias + n0);
            float v0 = acc[i][j][0] + b2.x;
            float v1 = acc[i][j][1] + b2.y;
            float v2 = acc[i][j][2] + b2.x;
            float v3 = acc[i][j][3] + b2.y;
            if (RELU) {
                v0 = fmaxf(v0, 0.f); v1 = fmaxf(v1, 0.f);
                v2 = fmaxf(v2, 0.f); v3 = fmaxf(v3, 0.f);
            }
            if (RES) {
                float2 r0v = *(const float2*)(res + (size_t)m0i * Ndim + n0);
                float2 r1v = *(const float2*)(res + (size_t)(m0i + 8) * Ndim + n0);
                v0 += r0v.x; v1 += r0v.y; v2 += r1v.x; v3 += r1v.y;
            }
            float2 o0 = {v0, v1}, o1 = {v2, v3};
            *(float2*)(out + (size_t)m0i * Ndim + n0) = o0;
            *(float2*)(out + (size_t)(m0i + 8) * Ndim + n0) = o1;
        }
    }
}

// ---------------- attention: error-corrected tf32 (hi/lo x2) ----------------
#define TQ    32
#define QST   68
#define KST   72
#define SCST  516
#define EBST  72
#define RDST  40

__global__ void __launch_bounds__(256)
attn_kernel(const float* __restrict__ QKV, const float* __restrict__ EK,
            const float* __restrict__ EV, float* __restrict__ O) {
    int qt = blockIdx.x, h = blockIdx.y, b = blockIdx.z;
    int q0 = qt * TQ;
    extern __shared__ float sm[];
    float* qsh  = sm;                  // 32*68  = 2176
    float* qsl  = qsh + 2176;          // 2176
    float* sc   = qsl + 2176;          // 32*516 = 16512
    float* kth  = sc + 16512;          // 128*72 = 9216
    float* ktl  = kth + 9216;          // 9216
    float* ebkh = ktl + 9216;          // 40*72  = 2880
    float* ebkl = ebkh + 2880;
    float* ebvh = ebkl + 2880;
    float* ebvl = ebvh + 2880;
    float* rdot = ebvl + 2880;         // 32*40 = 1280
    float* wsum = rdot + 1280;         // 1280
    float* rsum = wsum + 1280;         // 32

    int tid = threadIdx.x;
    int w = tid >> 5, lane = tid & 31;
    int r = lane >> 2, c = lane & 3;

    size_t bh_in  = ((size_t)b * SS) * RS3 + h * DK;
    size_t bh_out = ((size_t)b * SS) * HH  + h * DK;

    // ---- stage Q hi/lo ----
#pragma unroll
    for (int i = 0; i < 2; i++) {
        int f = tid + (i << 8);
        int row = f >> 4, c4 = (f & 15) << 2;
        float4 v = *(const float4*)(QKV + bh_in + (size_t)(q0 + row) * RS3 + c4);
        float* dh = qsh + row * QST + c4;
        float* dl = qsl + row * QST + c4;
        split2(v.x, dh[0], dl[0]); split2(v.y, dh[1], dl[1]);
        split2(v.z, dh[2], dl[2]); split2(v.w, dh[3], dl[3]);
    }
    // ---- stage embed_k / embed_v hi/lo (rows 33..39 zero-padded) ----
    for (int f = tid; f < 40 * 16; f += 256) {
        int row = f >> 4, c4 = (f & 15) << 2;
        float4 vk = {0.f, 0.f, 0.f, 0.f}, vv = {0.f, 0.f, 0.f, 0.f};
        if (row < NV) {
            vk = *(const float4*)(EK + row * DK + c4);
            vv = *(const float4*)(EV + row * DK + c4);
        }
        float* kh = ebkh + row * EBST + c4;
        float* kl = ebkl + row * EBST + c4;
        float* vh = ebvh + row * EBST + c4;
        float* vl = ebvl + row * EBST + c4;
        split2(vk.x, kh[0], kl[0]); split2(vk.y, kh[1], kl[1]);
        split2(vk.z, kh[2], kl[2]); split2(vk.w, kh[3], kl[3]);
        split2(vv.x, vh[0], vl[0]); split2(vv.y, vh[1], vl[1]);
        split2(vv.z, vh[2], vl[2]); split2(vv.w, vh[3], vl[3]);
    }
    for (int f = tid; f < 32 * RDST; f += 256) wsum[f] = 0.f;
    __syncthreads();

    // ---- rdot = Q · embed_k^T (x2, warps 0..4) ----
    if (w < 5) {
        float acc[2][4] = {{0.f, 0.f, 0.f, 0.f}, {0.f, 0.f, 0.f, 0.f}};
#pragma unroll
        for (int ks = 0; ks < 8; ks++) {
            uint32_t ah[2][4], al[2][4], bh[2], bl[2];
#pragma unroll
            for (int i = 0; i < 2; i++) {
                int base = (i * 16 + r) * QST + ks * 8 + c;
                ah[i][0] = U(qsh[base]);           al[i][0] = U(qsl[base]);
                ah[i][1] = U(qsh[base + 8 * QST]); al[i][1] = U(qsl[base + 8 * QST]);
                ah[i][2] = U(qsh[base + 4]);       al[i][2] = U(qsl[base + 4]);
                ah[i][3] = U(qsh[base + 8 * QST + 4]); al[i][3] = U(qsl[base + 8 * QST + 4]);
            }
            int pb = (w * 8 + r) * EBST + ks * 8 + c;
            bh[0] = U(ebkh[pb]); bh[1] = U(ebkh[pb + 4]);
            bl[0] = U(ebkl[pb]); bl[1] = U(ebkl[pb + 4]);
#pragma unroll
            for (int i = 0; i < 2; i++) {
                MMA_TF32(acc[i], ah[i], bh);
                MMA_TF32(acc[i], ah[i], bl);
                MMA_TF32(acc[i], al[i], bh);
            }
        }
#pragma unroll
        for (int i = 0; i < 2; i++) {
            int row = i * 16 + r;
            rdot[row * RDST + w * 8 + 2 * c]           = acc[i][0];
            rdot[row * RDST + w * 8 + 2 * c + 1]       = acc[i][1];
            rdot[(row + 8) * RDST + w * 8 + 2 * c]     = acc[i][2];
            rdot[(row + 8) * RDST + w * 8 + 2 * c + 1] = acc[i][3];
        }
    }
    __syncthreads();

    // ---- QK over 128-key tiles: warp w handles keys [w*16, w*16+16) ----
    for (int kt0 = 0; kt0 < SS; kt0 += 128) {
#pragma unroll
        for (int i = 0; i < 8; i++) {
            int f = tid + (i << 8);
            int rr = f >> 4, c4 = (f & 15) << 2;
            float4 v = *(const float4*)(QKV + bh_in + HH + (size_t)(kt0 + rr) * RS3 + c4);
            float* dh = kth + rr * KST + c4;
            float* dl = ktl + rr * KST + c4;
            split2(v.x, dh[0], dl[0]); split2(v.y, dh[1], dl[1]);
            split2(v.z, dh[2], dl[2]); split2(v.w, dh[3], dl[3]);
        }
        __syncthreads();
        float acc[2][2][4];
#pragma unroll
        for (int i = 0; i < 2; i++)
#pragma unroll
            for (int j = 0; j < 2; j++)
#pragma unroll
                for (int q = 0; q < 4; q++) acc[i][j][q] = 0.f;
#pragma unroll
        for (int ks = 0; ks < 8; ks++) {
            uint32_t ah[2][4], al[2][4];
#pragma unroll
            for (int i = 0; i < 2; i++) {
                int base = (i * 16 + r) * QST + ks * 8 + c;
                ah[i][0] = U(qsh[base]);           al[i][0] = U(qsl[base]);
                ah[i][1] = U(qsh[base + 8 * QST]); al[i][1] = U(qsl[base + 8 * QST]);
                ah[i][2] = U(qsh[base + 4]);       al[i][2] = U(qsl[base + 4]);
                ah[i][3] = U(qsh[base + 8 * QST + 4]); al[i][3] = U(qsl[base + 8 * QST + 4]);
            }
#pragma unroll
            for (int jn = 0; jn < 2; jn++) {
                uint32_t bh[2], bl[2];
                int pb = (w * 16 + jn * 8 + r) * KST + ks * 8 + c;
                bh[0] = U(kth[pb]); bh[1] = U(kth[pb + 4]);
                bl[0] = U(ktl[pb]); bl[1] = U(ktl[pb + 4]);
#pragma unroll
                for (int i = 0; i < 2; i++) {
                    MMA_TF32(acc[i][jn], ah[i], bh);
                    MMA_TF32(acc[i][jn], ah[i], bl);
                    MMA_TF32(acc[i][jn], al[i], bh);
                }
            }
        }
#pragma unroll
        for (int i = 0; i < 2; i++) {
#pragma unroll
            for (int jn = 0; jn < 2; jn++) {
                int colb = kt0 + w * 16 + jn * 8 + 2 * c;
#pragma unroll
                for (int cc = 0; cc < 4; cc++) {
                    int row = i * 16 + r + ((cc >> 1) << 3);
                    int key = colb + (cc & 1);
                    int qg = q0 + row;
                    int dd = key - qg;
                    dd = dd < -16 ? -16 : (dd > 16 ? 16 : dd);
                    sc[row * SCST + key] = acc[i][jn][cc] + rdot[row * RDST + dd + 16];
                }
            }
        }
        __syncthreads();
    }

    // ---- softmax + bucket weight sums ----
    {
        for (int rr = w; rr < TQ; rr += 8) {
            float* row = sc + rr * SCST;
            int qg = q0 + rr;
            float mx = -1e30f;
            for (int k = lane; k < SS; k += 32) mx = fmaxf(mx, row[k]);
#pragma unroll
            for (int o = 16; o > 0; o >>= 1)
                mx = fmaxf(mx, __shfl_xor_sync(0xffffffffu, mx, o));
            float sum = 0.f, w0 = 0.f, w32 = 0.f;
            for (int k = lane; k < SS; k += 32) {
                float e = __expf(row[k] - mx);
                row[k] = e;
                sum += e;
                if (k <= qg - 16) w0 += e;
                if (k >= qg + 16) w32 += e;
            }
#pragma unroll
            for (int o = 16; o > 0; o >>= 1) {
                sum += __shfl_xor_sync(0xffffffffu, sum, o);
                w0  += __shfl_xor_sync(0xffffffffu, w0, o);
                w32 += __shfl_xor_sync(0xffffffffu, w32, o);
            }
            __syncwarp();
            if (lane == 0) {
                rsum[rr] = sum;
                wsum[rr * RDST + 0] = w0;
                wsum[rr * RDST + 32] = w32;
            } else {
                int k = qg + lane - 16;
                wsum[rr * RDST + lane] = (k >= 0 && k < SS) ? row[k] : 0.f;
            }
        }
    }
    __syncthreads();

    // ---- PV + rel_v: warp w owns d-slice [w*8, w*8+8), all keys ----
    {
        float acc[2][4];
#pragma unroll
        for (int i = 0; i < 2; i++)
#pragma unroll
            for (int q = 0; q < 4; q++) acc[i][q] = 0.f;

        // rel_v: wsum[32x40] x ebv[40x64] (x2)
#pragma unroll
        for (int ks = 0; ks < 5; ks++) {
            uint32_t ah[2][4], al[2][4], bh[2], bl[2];
#pragma unroll
            for (int i = 0; i < 2; i++) {
                int base = (i * 16 + r) * RDST + ks * 8 + c;
                float h0, l0;
                split2(wsum[base], h0, l0);             ah[i][0] = U(h0); al[i][0] = U(l0);
                split2(wsum[base + 8 * RDST], h0, l0);  ah[i][1] = U(h0); al[i][1] = U(l0);
                split2(wsum[base + 4], h0, l0);         ah[i][2] = U(h0); al[i][2] = U(l0);
                split2(wsum[base + 8 * RDST + 4], h0, l0); ah[i][3] = U(h0); al[i][3] = U(l0);
            }
            int pb = (ks * 8 + c) * EBST + w * 8 + r;
            bh[0] = U(ebvh[pb]); bh[1] = U(ebvh[pb + 4 * EBST]);
            bl[0] = U(ebvl[pb]); bl[1] = U(ebvl[pb + 4 * EBST]);
#pragma unroll
            for (int i = 0; i < 2; i++) {
                MMA_TF32(acc[i], ah[i], bh);
                MMA_TF32(acc[i], ah[i], bl);
                MMA_TF32(acc[i], al[i], bh);
            }
        }

        for (int kt0 = 0; kt0 < SS; kt0 += 128) {
#pragma unroll
            for (int i = 0; i < 8; i++) {
                int f = tid + (i << 8);
                int rr = f >> 4, c4 = (f & 15) << 2;
                float4 v = *(const float4*)(QKV + bh_in + 2 * HH +
                                            (size_t)(kt0 + rr) * RS3 + c4);
                float* dh = kth + rr * KST + c4;
                float* dl = ktl + rr * KST + c4;
                split2(v.x, dh[0], dl[0]); split2(v.y, dh[1], dl[1]);
                split2(v.z, dh[2], dl[2]); split2(v.w, dh[3], dl[3]);
            }
            __syncthreads();
#pragma unroll 4
            for (int ks = 0; ks < 16; ks++) {
                int kb = ks * 8;
                uint32_t ah[2][4], al[2][4], bh[2], bl[2];
#pragma unroll
                for (int i = 0; i < 2; i++) {
                    const float* p = sc + (i * 16 + r) * SCST + kt0 + kb + c;
                    float h0, l0;
                    split2(p[0], h0, l0);             ah[i][0] = U(h0); al[i][0] = U(l0);
                    split2(p[8 * SCST], h0, l0);      ah[i][1] = U(h0); al[i][1] = U(l0);
                    split2(p[4], h0, l0);             ah[i][2] = U(h0); al[i][2] = U(l0);
                    split2(p[8 * SCST + 4], h0, l0);  ah[i][3] = U(h0); al[i][3] = U(l0);
                }
                int pb = (kb + c) * KST + w * 8 + r;
                bh[0] = U(kth[pb]); bh[1] = U(kth[pb + 4 * KST]);
                bl[0] = U(ktl[pb]); bl[1] = U(ktl[pb + 4 * KST]);
#pragma unroll
                for (int i = 0; i < 2; i++) {
                    MMA_TF32(acc[i], ah[i], bh);
                    MMA_TF32(acc[i], ah[i], bl);
                    MMA_TF32(acc[i], al[i], bh);
                }
            }
            __syncthreads();
        }

        // write output (each warp owns its d-slice; no reduction needed)
#pragma unroll
        for (int i = 0; i < 2; i++) {
            int row0 = i * 16 + r, row1 = row0 + 8;
            float inv0 = 1.f / rsum[row0];
            float inv1 = 1.f / rsum[row1];
            int col = w * 8 + 2 * c;
            float2 o0 = {acc[i][0] * inv0, acc[i][1] * inv0};
            float2 o1 = {acc[i][2] * inv1, acc[i][3] * inv1};
            *(float2*)(O + bh_out + (size_t)(q0 + row0) * HH + col) = o0;
            *(float2*)(O + bh_out + (size_t)(q0 + row1) * HH + col) = o1;
        }
    }
}

// ---------------- launcher ----------------
extern "C" void kernel_launch(void* const* d_in, const int* in_sizes, int n_in,
                              void* d_out, int out_size) {
    const float* x    = (const float*)d_in[0];
    const int*   mask = (const int*)d_in[1];
    const float* dw_w = (const float*)d_in[2];
    const float* dw_b = (const float*)d_in[3];
    const float* pw_w = (const float*)d_in[4];
    const float* pw_b = (const float*)d_in[5];
    const float* lcg  = (const float*)d_in[6];
    const float* lcb  = (const float*)d_in[7];
    const float* wq   = (const float*)d_in[8];
    const float* bq   = (const float*)d_in[9];
    const float* wk   = (const float*)d_in[10];
    const float* bk   = (const float*)d_in[11];
    const float* wv   = (const float*)d_in[12];
    const float* bv   = (const float*)d_in[13];
    const float* wo   = (const float*)d_in[14];
    const float* bo   = (const float*)d_in[15];
    const float* ek   = (const float*)d_in[16];
    const float* ev   = (const float*)d_in[17];
    const float* lag  = (const float*)d_in[18];
    const float* lab  = (const float*)d_in[19];
    const float* wff  = (const float*)d_in[20];
    const float* bff  = (const float*)d_in[21];
    const float* lfg  = (const float*)d_in[22];
    const float* lfb  = (const float*)d_in[23];
    float* xo = (float*)d_out;

    float *ph, *pqkv, *pwqkv, *pbqkv, *ppe, *pst;
    cudaGetSymbolAddress((void**)&ph, g_h);
    cudaGetSymbolAddress((void**)&pqkv, g_qkv);
    cudaGetSymbolAddress((void**)&pwqkv, g_wqkv);
    cudaGetSymbolAddress((void**)&pbqkv, g_bqkv);
    cudaGetSymbolAddress((void**)&ppe, g_pe);
    cudaGetSymbolAddress((void**)&pst, g_stats);

    cudaMemcpyAsync(pwqkv,               wq, (size_t)HH * HH * 4, cudaMemcpyDeviceToDevice);
    cudaMemcpyAsync(pwqkv + HH * HH,     wk, (size_t)HH * HH * 4, cudaMemcpyDeviceToDevice);
    cudaMemcpyAsync(pwqkv + 2 * HH * HH, wv, (size_t)HH * HH * 4, cudaMemcpyDeviceToDevice);
    cudaMemcpyAsync(pbqkv,          bq, HH * 4, cudaMemcpyDeviceToDevice);
    cudaMemcpyAsync(pbqkv + HH,     bk, HH * 4, cudaMemcpyDeviceToDevice);
    cudaMemcpyAsync(pbqkv + 2 * HH, bv, HH * 4, cudaMemcpyDeviceToDevice);

    const int ATTN_SMEM = (2 * 2176 + 16512 + 2 * 9216 + 4 * 2880 + 2 * 1280 + 32) * 4;
    cudaFuncSetAttribute((const void*)attn_kernel,
                         cudaFuncAttributeMaxDynamicSharedMemorySize, ATTN_SMEM);

    dim3 gemm_grid(HH / 128, ROWS / 128);
    dim3 qkv_grid(RS3 / 128, ROWS / 128);
    dim3 dw_grid(8, 4, 32);

    pe_kernel<<<(SS * HH) / 256, 256>>>(ppe);
    pos_add_kernel<<<TOT / 256, 256>>>(x, mask, ppe, xo);

    for (int i = 0; i < 2; i++) {
        ln_stats<<<ROWS / 8, 256>>>(xo, pst);
        dwconv_kernel<<<dw_grid, 256>>>(xo, pst, lcg + i * HH, lcb + i * HH,
                                        dw_w + i * HH * KW, dw_b + i * HH, ph);
        tgemm<false, true, true><<<gemm_grid, 256>>>(ph, pw_w + (size_t)i * HH * HH,
                                                     pw_b + i * HH, xo,
                                                     nullptr, nullptr, nullptr,
                                                     xo, HH, HH);
    }

    ln_stats<<<ROWS / 8, 256>>>(xo, pst);
    tgemm<true, false, false><<<qkv_grid, 256>>>(xo, pwqkv, pbqkv, nullptr,
                                                 pst, lag, lab, pqkv, RS3, HH);

    attn_kernel<<<dim3(SS / TQ, NHD, BB), 256, ATTN_SMEM>>>(pqkv, ek, ev, ph);

    tgemm<false, false, true><<<gemm_grid, 256>>>(ph, wo, bo, xo,
                                                  nullptr, nullptr, nullptr,
                                                  xo, HH, HH);

    // FFN: LN-fused GEMM into scratch (NO in-place A/out overlap), then residual add
    ln_stats<<<ROWS / 8, 256>>>(xo, pst);
    tgemm<true, true, false><<<gemm_grid, 256>>>(xo, wff, bff, nullptr,
                                                 pst, lfg, lfb, ph, HH, HH);
    add_kernel<<<TOT / 4 / 256, 256>>>(xo, ph);
}

// round 9
// speedup vs baseline: 2.3890x; 1.2928x over previous
#include <cuda_runtime.h>
#include <math.h>
#include <stdint.h>

// ---------------- problem constants ----------------
#define BB   32
#define SS   512
#define HH   512
#define NHD  8
#define DK   64
#define KW   7
#define NV   33
#define RS3  (3*HH)
#define ROWS (BB*SS)
#define TOT  (BB*SS*HH)

// ---------------- scratch ----------------
__device__ float g_h[TOT];
__device__ float g_qkv[ROWS * RS3];
__device__ float g_wqkv[3 * HH * HH];
__device__ float g_bqkv[3 * HH];
__device__ float g_pe[SS * HH];
__device__ float g_stats[ROWS * 2];

// ---------------- tf32 helpers ----------------
__device__ __forceinline__ uint32_t f2tf(float f) {
    uint32_t u;
    asm("cvt.rna.tf32.f32 %0, %1;" : "=r"(u) : "f"(f));
    return u;
}
__device__ __forceinline__ float f2tff(float f) {
    return __uint_as_float(f2tf(f));
}
#define U(x) __float_as_uint(x)

#define MMA_TF32(d, a, b)                                                     \
    asm volatile("mma.sync.aligned.m16n8k8.row.col.f32.tf32.tf32.f32 "       \
                 "{%0,%1,%2,%3}, {%4,%5,%6,%7}, {%8,%9}, {%0,%1,%2,%3};"     \
                 : "+f"(d[0]), "+f"(d[1]), "+f"(d[2]), "+f"(d[3])            \
                 : "r"(a[0]), "r"(a[1]), "r"(a[2]), "r"(a[3]),               \
                   "r"(b[0]), "r"(b[1]))

// ---------------- positional encoding table ----------------
__global__ void pe_kernel(float* __restrict__ pe) {
    int idx = blockIdx.x * 256 + threadIdx.x;
    int h = idx & (HH - 1);
    int s = idx >> 9;
    float v = 0.f;
    if (s > 0) {
        float pos = (float)(s - 1);
        int i2 = h & ~1;
        float div = expf((float)i2 * (-9.210340371976184f / (float)HH));
        float ang = pos * div;
        v = (h & 1) ? cosf(ang) : sinf(ang);
    }
    pe[idx] = v;
}

__global__ void pos_add_kernel(const float* __restrict__ x,
                               const int* __restrict__ mask,
                               const float* __restrict__ pe,
                               float* __restrict__ out) {
    int idx = blockIdx.x * 256 + threadIdx.x;
    int s = (idx >> 9) & (SS - 1);
    int b = idx >> 18;
    out[idx] = x[idx] + pe[idx & (SS * HH - 1)] * (float)mask[(b << 9) + s];
}

// ---------------- LN stats ----------------
__global__ void ln_stats(const float* __restrict__ x, float* __restrict__ stats) {
    int row = blockIdx.x * 8 + (threadIdx.x >> 5);
    int lane = threadIdx.x & 31;
    const float4* xr = (const float4*)(x + (size_t)row * HH);
    float s = 0.f, sq = 0.f;
#pragma unroll
    for (int i = 0; i < 4; i++) {
        float4 v = xr[lane + i * 32];
        s += v.x + v.y + v.z + v.w;
        sq += v.x * v.x + v.y * v.y + v.z * v.z + v.w * v.w;
    }
#pragma unroll
    for (int o = 16; o > 0; o >>= 1) {
        s  += __shfl_xor_sync(0xffffffffu, s, o);
        sq += __shfl_xor_sync(0xffffffffu, sq, o);
    }
    if (lane == 0) {
        float mean = s * (1.f / HH);
        float var = sq * (1.f / HH) - mean * mean;
        stats[row * 2] = mean;
        stats[row * 2 + 1] = rsqrtf(var + 1e-5f);
    }
}

// ---------------- depthwise conv with fused LN ----------------
__global__ void dwconv_kernel(const float* __restrict__ x,
                              const float* __restrict__ stats,
                              const float* __restrict__ lg,
                              const float* __restrict__ lb,
                              const float* __restrict__ w,
                              const float* __restrict__ bias,
                              float* __restrict__ out) {
    __shared__ float sb[70][128];
    __shared__ float2 sstat[70];
    __shared__ float lgs[128], lbs[128];
    int s0 = blockIdx.x * 64, c0 = blockIdx.y * 128, b = blockIdx.z;
    int tid = threadIdx.x;
    if (tid < 128) { lgs[tid] = lg[c0 + tid]; lbs[tid] = lb[c0 + tid]; }
    else if (tid < 198) {
        int sp = s0 + (tid - 128) - 3;
        float2 st = {0.f, 0.f};
        if (sp >= 0 && sp < SS) st = *(const float2*)(stats + ((size_t)b * SS + sp) * 2);
        sstat[tid - 128] = st;
    }
    __syncthreads();
    const float* base = x + ((size_t)b * SS) * HH + c0;
    for (int i = tid; i < 70 * 128; i += 256) {
        int r = i >> 7, c = i & 127;
        int sp = s0 + r - 3;
        float v = 0.f;
        if (sp >= 0 && sp < SS) {
            float raw = base[(size_t)sp * HH + c];
            float2 st = sstat[r];
            v = (raw - st.x) * st.y * lgs[c] + lbs[c];
        }
        sb[r][c] = v;
    }
    __syncthreads();
    int c = tid & 127;
    int rr0 = (tid >> 7) * 32;
    float wr[KW];
#pragma unroll
    for (int t = 0; t < KW; t++) wr[t] = w[(c0 + c) * KW + t];
    float bz = bias[c0 + c];
    float* obase = out + ((size_t)b * SS + s0) * HH + c0 + c;
#pragma unroll 4
    for (int r = 0; r < 32; r++) {
        int sl = rr0 + r;
        float acc = bz;
#pragma unroll
        for (int t = 0; t < KW; t++) acc = fmaf(sb[sl + t][c], wr[t], acc);
        obase[(size_t)(sl) * HH] = acc;
    }
}

// ---------------- tf32 tensor-core GEMM (optional fused LN on A) ----------------
template <bool LNA, bool RELU, bool RES>
__global__ void __launch_bounds__(256, 2)
tgemm(const float* __restrict__ A, const float* __restrict__ W,
      const float* __restrict__ bias, const float* res,
      const float* __restrict__ stats, const float* __restrict__ lng,
      const float* __restrict__ lnb,
      float* out, int Ndim, int Kdim) {
    __shared__ uint32_t Asm[2][128 * 20];
    __shared__ uint32_t Wsm[2][128 * 20];
    int bm = blockIdx.y * 128, bn = blockIdx.x * 128;
    int tid = threadIdx.x;
    int wid = tid >> 5, lane = tid & 31;
    int wm = (wid & 3) * 32, wn = (wid >> 2) * 64;
    int r = lane >> 2, c = lane & 3;

    float acc[2][8][4];
#pragma unroll
    for (int i = 0; i < 2; i++)
#pragma unroll
        for (int j = 0; j < 8; j++)
#pragma unroll
            for (int q = 0; q < 4; q++) acc[i][j][q] = 0.f;

    int row0 = tid >> 2, c40 = (tid & 3) << 2;
    int row1 = row0 + 64;
    const float* Ap0 = A + (size_t)(bm + row0) * Kdim + c40;
    const float* Ap1 = A + (size_t)(bm + row1) * Kdim + c40;
    const float* Wp0 = W + (size_t)(bn + row0) * Kdim + c40;
    const float* Wp1 = W + (size_t)(bn + row1) * Kdim + c40;
    int so0 = row0 * 20 + c40, so1 = row1 * 20 + c40;

    float m0 = 0.f, r0s = 1.f, m1 = 0.f, r1s = 1.f;
    if (LNA) {
        float2 st0 = *(const float2*)(stats + (size_t)(bm + row0) * 2);
        float2 st1 = *(const float2*)(stats + (size_t)(bm + row1) * 2);
        m0 = st0.x; r0s = st0.y; m1 = st1.x; r1s = st1.y;
    }

    float4 a0 = *(const float4*)Ap0;
    float4 a1 = *(const float4*)Ap1;
    float4 w0 = *(const float4*)Wp0;
    float4 w1 = *(const float4*)Wp1;
    float4 g4, b4;
    if (LNA) {
        g4 = *(const float4*)(lng + c40);
        b4 = *(const float4*)(lnb + c40);
    }

    int buf = 0;
    int nk = Kdim >> 4;
    for (int s = 1;; s++) {
        {
            float4 ta0 = a0, ta1 = a1;
            if (LNA) {
                ta0.x = (a0.x - m0) * r0s * g4.x + b4.x;
                ta0.y = (a0.y - m0) * r0s * g4.y + b4.y;
                ta0.z = (a0.z - m0) * r0s * g4.z + b4.z;
                ta0.w = (a0.w - m0) * r0s * g4.w + b4.w;
                ta1.x = (a1.x - m1) * r1s * g4.x + b4.x;
                ta1.y = (a1.y - m1) * r1s * g4.y + b4.y;
                ta1.z = (a1.z - m1) * r1s * g4.z + b4.z;
                ta1.w = (a1.w - m1) * r1s * g4.w + b4.w;
            }
            uint4 u;
            u.x = f2tf(ta0.x); u.y = f2tf(ta0.y); u.z = f2tf(ta0.z); u.w = f2tf(ta0.w);
            *(uint4*)&Asm[buf][so0] = u;
            u.x = f2tf(ta1.x); u.y = f2tf(ta1.y); u.z = f2tf(ta1.z); u.w = f2tf(ta1.w);
            *(uint4*)&Asm[buf][so1] = u;
            u.x = f2tf(w0.x); u.y = f2tf(w0.y); u.z = f2tf(w0.z); u.w = f2tf(w0.w);
            *(uint4*)&Wsm[buf][so0] = u;
            u.x = f2tf(w1.x); u.y = f2tf(w1.y); u.z = f2tf(w1.z); u.w = f2tf(w1.w);
            *(uint4*)&Wsm[buf][so1] = u;
        }
        __syncthreads();
        bool more = (s < nk);
        if (more) {
            a0 = *(const float4*)(Ap0 + s * 16);
            a1 = *(const float4*)(Ap1 + s * 16);
            w0 = *(const float4*)(Wp0 + s * 16);
            w1 = *(const float4*)(Wp1 + s * 16);
            if (LNA) {
                g4 = *(const float4*)(lng + s * 16 + c40);
                b4 = *(const float4*)(lnb + s * 16 + c40);
            }
        }
#pragma unroll
        for (int kk = 0; kk < 2; kk++) {
            uint32_t af[2][4], bf[8][2];
#pragma unroll
            for (int i = 0; i < 2; i++) {
                const uint32_t* p = &Asm[buf][(wm + i * 16 + r) * 20 + kk * 8 + c];
                af[i][0] = p[0];
                af[i][1] = p[160];
                af[i][2] = p[4];
                af[i][3] = p[164];
            }
#pragma unroll
            for (int j = 0; j < 8; j++) {
                const uint32_t* p = &Wsm[buf][(wn + j * 8 + r) * 20 + kk * 8 + c];
                bf[j][0] = p[0];
                bf[j][1] = p[4];
            }
#pragma unroll
            for (int i = 0; i < 2; i++)
#pragma unroll
                for (int j = 0; j < 8; j++)
                    MMA_TF32(acc[i][j], af[i], bf[j]);
        }
        if (!more) break;
        buf ^= 1;
    }

#pragma unroll
    for (int i = 0; i < 2; i++) {
        int m0i = bm + wm + i * 16 + r;
#pragma unroll
        for (int j = 0; j < 8; j++) {
            int n0 = bn + wn + j * 8 + 2 * c;
            float2 b2 = *(const float2*)(bias + n0);
            float v0 = acc[i][j][0] + b2.x;
            float v1 = acc[i][j][1] + b2.y;
            float v2 = acc[i][j][2] + b2.x;
            float v3 = acc[i][j][3] + b2.y;
            if (RELU) {
                v0 = fmaxf(v0, 0.f); v1 = fmaxf(v1, 0.f);
                v2 = fmaxf(v2, 0.f); v3 = fmaxf(v3, 0.f);
            }
            if (RES) {
                float2 r0v = *(const float2*)(res + (size_t)m0i * Ndim + n0);
                float2 r1v = *(const float2*)(res + (size_t)(m0i + 8) * Ndim + n0);
                v0 += r0v.x; v1 += r0v.y; v2 += r1v.x; v3 += r1v.y;
            }
            float2 o0 = {v0, v1}, o1 = {v2, v3};
            *(float2*)(out + (size_t)m0i * Ndim + n0) = o0;
            *(float2*)(out + (size_t)(m0i + 8) * Ndim + n0) = o1;
        }
    }
}

// ---------------- attention: single-tf32 mma, 256-key tiles ----------------
#define TQ    32
#define QST   68
#define KST   72
#define SCST  516
#define EBST  72
#define RDST  40

__global__ void __launch_bounds__(256)
attn_kernel(const float* __restrict__ QKV, const float* __restrict__ EK,
            const float* __restrict__ EV, float* __restrict__ O) {
    int qt = blockIdx.x, h = blockIdx.y, b = blockIdx.z;
    int q0 = qt * TQ;
    extern __shared__ float sm[];
    float* qs   = sm;                  // 32*68  = 2176
    float* sc   = qs + 2176;           // 32*516 = 16512
    float* kt   = sc + 16512;          // 256*72 = 18432
    float* ebk  = kt + 18432;          // 40*72  = 2880
    float* ebv  = ebk + 2880;          // 2880
    float* rdot = ebv + 2880;          // 32*40  = 1280
    float* wsum = rdot + 1280;         // 1280
    float* rsum = wsum + 1280;         // 32

    int tid = threadIdx.x;
    int w = tid >> 5, lane = tid & 31;
    int r = lane >> 2, c = lane & 3;

    size_t bh_in  = ((size_t)b * SS) * RS3 + h * DK;
    size_t bh_out = ((size_t)b * SS) * HH  + h * DK;

    // ---- stage Q (tf32) ----
#pragma unroll
    for (int i = 0; i < 2; i++) {
        int f = tid + (i << 8);
        int row = f >> 4, c4 = (f & 15) << 2;
        float4 v = *(const float4*)(QKV + bh_in + (size_t)(q0 + row) * RS3 + c4);
        float* d = qs + row * QST + c4;
        d[0] = f2tff(v.x); d[1] = f2tff(v.y); d[2] = f2tff(v.z); d[3] = f2tff(v.w);
    }
    // ---- stage embed_k / embed_v (rows 33..39 zero) ----
    for (int f = tid; f < 40 * 16; f += 256) {
        int row = f >> 4, c4 = (f & 15) << 2;
        float4 vk = {0.f, 0.f, 0.f, 0.f}, vv = {0.f, 0.f, 0.f, 0.f};
        if (row < NV) {
            vk = *(const float4*)(EK + row * DK + c4);
            vv = *(const float4*)(EV + row * DK + c4);
        }
        float* dk = ebk + row * EBST + c4;
        float* dv = ebv + row * EBST + c4;
        dk[0] = f2tff(vk.x); dk[1] = f2tff(vk.y); dk[2] = f2tff(vk.z); dk[3] = f2tff(vk.w);
        dv[0] = f2tff(vv.x); dv[1] = f2tff(vv.y); dv[2] = f2tff(vv.z); dv[3] = f2tff(vv.w);
    }
    for (int f = tid; f < 32 * RDST; f += 256) wsum[f] = 0.f;
    __syncthreads();

    // ---- rdot = Q · embed_k^T (warps 0..4, 8 buckets each) ----
    if (w < 5) {
        float acc[2][4] = {{0.f, 0.f, 0.f, 0.f}, {0.f, 0.f, 0.f, 0.f}};
#pragma unroll
        for (int ks = 0; ks < 8; ks++) {
            uint32_t a[2][4], bf[2];
#pragma unroll
            for (int i = 0; i < 2; i++) {
                int base = (i * 16 + r) * QST + ks * 8 + c;
                a[i][0] = U(qs[base]);
                a[i][1] = U(qs[base + 8 * QST]);
                a[i][2] = U(qs[base + 4]);
                a[i][3] = U(qs[base + 8 * QST + 4]);
            }
            int pb = (w * 8 + r) * EBST + ks * 8 + c;
            bf[0] = U(ebk[pb]); bf[1] = U(ebk[pb + 4]);
            MMA_TF32(acc[0], a[0], bf);
            MMA_TF32(acc[1], a[1], bf);
        }
#pragma unroll
        for (int i = 0; i < 2; i++) {
            int row = i * 16 + r;
            rdot[row * RDST + w * 8 + 2 * c]           = acc[i][0];
            rdot[row * RDST + w * 8 + 2 * c + 1]       = acc[i][1];
            rdot[(row + 8) * RDST + w * 8 + 2 * c]     = acc[i][2];
            rdot[(row + 8) * RDST + w * 8 + 2 * c + 1] = acc[i][3];
        }
    }
    __syncthreads();

    // ---- QK over 256-key tiles: warp w owns keys [w*32, w*32+32) ----
    for (int kt0 = 0; kt0 < SS; kt0 += 256) {
#pragma unroll
        for (int i = 0; i < 16; i++) {
            int f = tid + (i << 8);
            int rr = f >> 4, c4 = (f & 15) << 2;
            float4 v = *(const float4*)(QKV + bh_in + HH + (size_t)(kt0 + rr) * RS3 + c4);
            float* d = kt + rr * KST + c4;
            d[0] = f2tff(v.x); d[1] = f2tff(v.y); d[2] = f2tff(v.z); d[3] = f2tff(v.w);
        }
        __syncthreads();
        float acc[2][4][4];
#pragma unroll
        for (int i = 0; i < 2; i++)
#pragma unroll
            for (int j = 0; j < 4; j++)
#pragma unroll
                for (int q = 0; q < 4; q++) acc[i][j][q] = 0.f;
#pragma unroll
        for (int ks = 0; ks < 8; ks++) {
            uint32_t a[2][4];
#pragma unroll
            for (int i = 0; i < 2; i++) {
                int base = (i * 16 + r) * QST + ks * 8 + c;
                a[i][0] = U(qs[base]);
                a[i][1] = U(qs[base + 8 * QST]);
                a[i][2] = U(qs[base + 4]);
                a[i][3] = U(qs[base + 8 * QST + 4]);
            }
#pragma unroll
            for (int jn = 0; jn < 4; jn++) {
                uint32_t bf[2];
                int pb = (w * 32 + jn * 8 + r) * KST + ks * 8 + c;
                bf[0] = U(kt[pb]); bf[1] = U(kt[pb + 4]);
                MMA_TF32(acc[0][jn], a[0], bf);
                MMA_TF32(acc[1][jn], a[1], bf);
            }
        }
#pragma unroll
        for (int i = 0; i < 2; i++) {
#pragma unroll
            for (int jn = 0; jn < 4; jn++) {
                int colb = kt0 + w * 32 + jn * 8 + 2 * c;
#pragma unroll
                for (int cc = 0; cc < 4; cc++) {
                    int row = i * 16 + r + ((cc >> 1) << 3);
                    int key = colb + (cc & 1);
                    int qg = q0 + row;
                    int dd = key - qg;
                    dd = dd < -16 ? -16 : (dd > 16 ? 16 : dd);
                    sc[row * SCST + key] = acc[i][jn][cc] + rdot[row * RDST + dd + 16];
                }
            }
        }
        __syncthreads();
    }

    // ---- softmax + bucket weight sums ----
    {
        for (int rr = w; rr < TQ; rr += 8) {
            float* row = sc + rr * SCST;
            int qg = q0 + rr;
            float mx = -1e30f;
            for (int k = lane; k < SS; k += 32) mx = fmaxf(mx, row[k]);
#pragma unroll
            for (int o = 16; o > 0; o >>= 1)
                mx = fmaxf(mx, __shfl_xor_sync(0xffffffffu, mx, o));
            float sum = 0.f, w0 = 0.f, w32 = 0.f;
            for (int k = lane; k < SS; k += 32) {
                float e = __expf(row[k] - mx);
                row[k] = e;
                sum += e;
                if (k <= qg - 16) w0 += e;
                if (k >= qg + 16) w32 += e;
            }
#pragma unroll
            for (int o = 16; o > 0; o >>= 1) {
                sum += __shfl_xor_sync(0xffffffffu, sum, o);
                w0  += __shfl_xor_sync(0xffffffffu, w0, o);
                w32 += __shfl_xor_sync(0xffffffffu, w32, o);
            }
            __syncwarp();
            if (lane == 0) {
                rsum[rr] = sum;
                wsum[rr * RDST + 0] = w0;
                wsum[rr * RDST + 32] = w32;
            } else {
                int k = qg + lane - 16;
                wsum[rr * RDST + lane] = (k >= 0 && k < SS) ? row[k] : 0.f;
            }
        }
    }
    __syncthreads();

    // ---- PV + rel_v: warp w owns d-slice [w*8, w*8+8) ----
    {
        float acc[2][4];
#pragma unroll
        for (int i = 0; i < 2; i++)
#pragma unroll
            for (int q = 0; q < 4; q++) acc[i][q] = 0.f;

        // rel_v: wsum[32x40] x ebv[40x64]
#pragma unroll
        for (int ks = 0; ks < 5; ks++) {
            uint32_t a[2][4], bf[2];
#pragma unroll
            for (int i = 0; i < 2; i++) {
                int base = (i * 16 + r) * RDST + ks * 8 + c;
                a[i][0] = f2tf(wsum[base]);
                a[i][1] = f2tf(wsum[base + 8 * RDST]);
                a[i][2] = f2tf(wsum[base + 4]);
                a[i][3] = f2tf(wsum[base + 8 * RDST + 4]);
            }
            int pb = (ks * 8 + c) * EBST + w * 8 + r;
            bf[0] = U(ebv[pb]); bf[1] = U(ebv[pb + 4 * EBST]);
            MMA_TF32(acc[0], a[0], bf);
            MMA_TF32(acc[1], a[1], bf);
        }

        for (int kt0 = 0; kt0 < SS; kt0 += 256) {
#pragma unroll
            for (int i = 0; i < 16; i++) {
                int f = tid + (i << 8);
                int rr = f >> 4, c4 = (f & 15) << 2;
                float4 v = *(const float4*)(QKV + bh_in + 2 * HH +
                                            (size_t)(kt0 + rr) * RS3 + c4);
                float* d = kt + rr * KST + c4;
                d[0] = f2tff(v.x); d[1] = f2tff(v.y); d[2] = f2tff(v.z); d[3] = f2tff(v.w);
            }
            __syncthreads();
#pragma unroll 8
            for (int ks = 0; ks < 32; ks++) {
                int kb = ks * 8;
                uint32_t a[2][4], bf[2];
#pragma unroll
                for (int i = 0; i < 2; i++) {
                    const float* p = sc + (i * 16 + r) * SCST + kt0 + kb + c;
                    a[i][0] = f2tf(p[0]);
                    a[i][1] = f2tf(p[8 * SCST]);
                    a[i][2] = f2tf(p[4]);
                    a[i][3] = f2tf(p[8 * SCST + 4]);
                }
                int pb = (kb + c) * KST + w * 8 + r;
                bf[0] = U(kt[pb]); bf[1] = U(kt[pb + 4 * KST]);
                MMA_TF32(acc[0], a[0], bf);
                MMA_TF32(acc[1], a[1], bf);
            }
            __syncthreads();
        }

#pragma unroll
        for (int i = 0; i < 2; i++) {
            int row0 = i * 16 + r, row1 = row0 + 8;
            float inv0 = 1.f / rsum[row0];
            float inv1 = 1.f / rsum[row1];
            int col = w * 8 + 2 * c;
            float2 o0 = {acc[i][0] * inv0, acc[i][1] * inv0};
            float2 o1 = {acc[i][2] * inv1, acc[i][3] * inv1};
            *(float2*)(O + bh_out + (size_t)(q0 + row0) * HH + col) = o0;
            *(float2*)(O + bh_out + (size_t)(q0 + row1) * HH + col) = o1;
        }
    }
}

// ---------------- launcher ----------------
extern "C" void kernel_launch(void* const* d_in, const int* in_sizes, int n_in,
                              void* d_out, int out_size) {
    const float* x    = (const float*)d_in[0];
    const int*   mask = (const int*)d_in[1];
    const float* dw_w = (const float*)d_in[2];
    const float* dw_b = (const float*)d_in[3];
    const float* pw_w = (const float*)d_in[4];
    const float* pw_b = (const float*)d_in[5];
    const float* lcg  = (const float*)d_in[6];
    const float* lcb  = (const float*)d_in[7];
    const float* wq   = (const float*)d_in[8];
    const float* bq   = (const float*)d_in[9];
    const float* wk   = (const float*)d_in[10];
    const float* bk   = (const float*)d_in[11];
    const float* wv   = (const float*)d_in[12];
    const float* bv   = (const float*)d_in[13];
    const float* wo   = (const float*)d_in[14];
    const float* bo   = (const float*)d_in[15];
    const float* ek   = (const float*)d_in[16];
    const float* ev   = (const float*)d_in[17];
    const float* lag  = (const float*)d_in[18];
    const float* lab  = (const float*)d_in[19];
    const float* wff  = (const float*)d_in[20];
    const float* bff  = (const float*)d_in[21];
    const float* lfg  = (const float*)d_in[22];
    const float* lfb  = (const float*)d_in[23];
    float* xo = (float*)d_out;

    float *ph, *pqkv, *pwqkv, *pbqkv, *ppe, *pst;
    cudaGetSymbolAddress((void**)&ph, g_h);
    cudaGetSymbolAddress((void**)&pqkv, g_qkv);
    cudaGetSymbolAddress((void**)&pwqkv, g_wqkv);
    cudaGetSymbolAddress((void**)&pbqkv, g_bqkv);
    cudaGetSymbolAddress((void**)&ppe, g_pe);
    cudaGetSymbolAddress((void**)&pst, g_stats);

    cudaMemcpyAsync(pwqkv,               wq, (size_t)HH * HH * 4, cudaMemcpyDeviceToDevice);
    cudaMemcpyAsync(pwqkv + HH * HH,     wk, (size_t)HH * HH * 4, cudaMemcpyDeviceToDevice);
    cudaMemcpyAsync(pwqkv + 2 * HH * HH, wv, (size_t)HH * HH * 4, cudaMemcpyDeviceToDevice);
    cudaMemcpyAsync(pbqkv,          bq, HH * 4, cudaMemcpyDeviceToDevice);
    cudaMemcpyAsync(pbqkv + HH,     bk, HH * 4, cudaMemcpyDeviceToDevice);
    cudaMemcpyAsync(pbqkv + 2 * HH, bv, HH * 4, cudaMemcpyDeviceToDevice);

    const int ATTN_SMEM = (2176 + 16512 + 18432 + 2 * 2880 + 2 * 1280 + 32) * 4;
    cudaFuncSetAttribute((const void*)attn_kernel,
                         cudaFuncAttributeMaxDynamicSharedMemorySize, ATTN_SMEM);

    dim3 gemm_grid(HH / 128, ROWS / 128);
    dim3 qkv_grid(RS3 / 128, ROWS / 128);
    dim3 dw_grid(8, 4, 32);

    pe_kernel<<<(SS * HH) / 256, 256>>>(ppe);
    pos_add_kernel<<<TOT / 256, 256>>>(x, mask, ppe, xo);

    for (int i = 0; i < 2; i++) {
        ln_stats<<<ROWS / 8, 256>>>(xo, pst);
        dwconv_kernel<<<dw_grid, 256>>>(xo, pst, lcg + i * HH, lcb + i * HH,
                                        dw_w + i * HH * KW, dw_b + i * HH, ph);
        tgemm<false, true, true><<<gemm_grid, 256>>>(ph, pw_w + (size_t)i * HH * HH,
                                                     pw_b + i * HH, xo,
                                                     nullptr, nullptr, nullptr,
                                                     xo, HH, HH);
    }

    ln_stats<<<ROWS / 8, 256>>>(xo, pst);
    tgemm<true, false, false><<<qkv_grid, 256>>>(xo, pwqkv, pbqkv, nullptr,
                                                 pst, lag, lab, pqkv, RS3, HH);

    attn_kernel<<<dim3(SS / TQ, NHD, BB), 256, ATTN_SMEM>>>(pqkv, ek, ev, ph);

    // O-proj: x' = x + attn·wo + bo  -> write into g_qkv (free after attention)
    tgemm<false, false, true><<<gemm_grid, 256>>>(ph, wo, bo, xo,
                                                  nullptr, nullptr, nullptr,
                                                  pqkv, HH, HH);

    // FFN: out(d_out) = x' + relu(LN(x')·wff + bff)  -- A/res = g_qkv, out = d_out
    ln_stats<<<ROWS / 8, 256>>>(pqkv, pst);
    tgemm<true, true, true><<<gemm_grid, 256>>>(pqkv, wff, bff, pqkv,
                                                pst, lfg, lfb, xo, HH, HH);
}

// round 10
// speedup vs baseline: 2.6327x; 1.1020x over previous
#include <cuda_runtime.h>
#include <cuda_fp16.h>
#include <math.h>
#include <stdint.h>

// ---------------- problem constants ----------------
#define BB   32
#define SS   512
#define HH   512
#define NHD  8
#define DK   64
#define KW   7
#define NV   33
#define RS3  (3*HH)
#define ROWS (BB*SS)
#define TOT  (BB*SS*HH)

// ---------------- scratch ----------------
__device__ float g_h[TOT];
__device__ float g_qkv[ROWS * RS3];
__device__ float g_wqkv[3 * HH * HH];
__device__ float g_bqkv[3 * HH];
__device__ float g_pe[SS * HH];
__device__ float g_stats[ROWS * 2];

// ---------------- helpers ----------------
__device__ __forceinline__ uint32_t f2tf(float f) {
    uint32_t u;
    asm("cvt.rna.tf32.f32 %0, %1;" : "=r"(u) : "f"(f));
    return u;
}
__device__ __forceinline__ float f2tff(float f) {
    return __uint_as_float(f2tf(f));
}
__device__ __forceinline__ uint32_t h2(float x, float y) {
    __half2 h = __floats2half2_rn(x, y);
    return *reinterpret_cast<uint32_t*>(&h);
}
#define U(x) __float_as_uint(x)

#define MMA_TF32(d, a, b)                                                     \
    asm volatile("mma.sync.aligned.m16n8k8.row.col.f32.tf32.tf32.f32 "       \
                 "{%0,%1,%2,%3}, {%4,%5,%6,%7}, {%8,%9}, {%0,%1,%2,%3};"     \
                 : "+f"(d[0]), "+f"(d[1]), "+f"(d[2]), "+f"(d[3])            \
                 : "r"(a[0]), "r"(a[1]), "r"(a[2]), "r"(a[3]),               \
                   "r"(b[0]), "r"(b[1]))

#define MMA_F16(d, a, b)                                                      \
    asm volatile("mma.sync.aligned.m16n8k16.row.col.f32.f16.f16.f32 "        \
                 "{%0,%1,%2,%3}, {%4,%5,%6,%7}, {%8,%9}, {%0,%1,%2,%3};"     \
                 : "+f"(d[0]), "+f"(d[1]), "+f"(d[2]), "+f"(d[3])            \
                 : "r"(a[0]), "r"(a[1]), "r"(a[2]), "r"(a[3]),               \
                   "r"(b[0]), "r"(b[1]))

// ---------------- positional encoding table ----------------
__global__ void pe_kernel(float* __restrict__ pe) {
    int idx = blockIdx.x * 256 + threadIdx.x;
    int h = idx & (HH - 1);
    int s = idx >> 9;
    float v = 0.f;
    if (s > 0) {
        float pos = (float)(s - 1);
        int i2 = h & ~1;
        float div = expf((float)i2 * (-9.210340371976184f / (float)HH));
        float ang = pos * div;
        v = (h & 1) ? cosf(ang) : sinf(ang);
    }
    pe[idx] = v;
}

__global__ void pos_add_kernel(const float* __restrict__ x,
                               const int* __restrict__ mask,
                               const float* __restrict__ pe,
                               float* __restrict__ out) {
    int idx = blockIdx.x * 256 + threadIdx.x;
    int s = (idx >> 9) & (SS - 1);
    int b = idx >> 18;
    out[idx] = x[idx] + pe[idx & (SS * HH - 1)] * (float)mask[(b << 9) + s];
}

// ---------------- LN stats ----------------
__global__ void ln_stats(const float* __restrict__ x, float* __restrict__ stats) {
    int row = blockIdx.x * 8 + (threadIdx.x >> 5);
    int lane = threadIdx.x & 31;
    const float4* xr = (const float4*)(x + (size_t)row * HH);
    float s = 0.f, sq = 0.f;
#pragma unroll
    for (int i = 0; i < 4; i++) {
        float4 v = xr[lane + i * 32];
        s += v.x + v.y + v.z + v.w;
        sq += v.x * v.x + v.y * v.y + v.z * v.z + v.w * v.w;
    }
#pragma unroll
    for (int o = 16; o > 0; o >>= 1) {
        s  += __shfl_xor_sync(0xffffffffu, s, o);
        sq += __shfl_xor_sync(0xffffffffu, sq, o);
    }
    if (lane == 0) {
        float mean = s * (1.f / HH);
        float var = sq * (1.f / HH) - mean * mean;
        stats[row * 2] = mean;
        stats[row * 2 + 1] = rsqrtf(var + 1e-5f);
    }
}

// ---------------- depthwise conv with fused LN ----------------
__global__ void dwconv_kernel(const float* __restrict__ x,
                              const float* __restrict__ stats,
                              const float* __restrict__ lg,
                              const float* __restrict__ lb,
                              const float* __restrict__ w,
                              const float* __restrict__ bias,
                              float* __restrict__ out) {
    __shared__ float sb[70][128];
    __shared__ float2 sstat[70];
    __shared__ float lgs[128], lbs[128];
    int s0 = blockIdx.x * 64, c0 = blockIdx.y * 128, b = blockIdx.z;
    int tid = threadIdx.x;
    if (tid < 128) { lgs[tid] = lg[c0 + tid]; lbs[tid] = lb[c0 + tid]; }
    else if (tid < 198) {
        int sp = s0 + (tid - 128) - 3;
        float2 st = {0.f, 0.f};
        if (sp >= 0 && sp < SS) st = *(const float2*)(stats + ((size_t)b * SS + sp) * 2);
        sstat[tid - 128] = st;
    }
    __syncthreads();
    const float* base = x + ((size_t)b * SS) * HH + c0;
    for (int i = tid; i < 70 * 128; i += 256) {
        int r = i >> 7, c = i & 127;
        int sp = s0 + r - 3;
        float v = 0.f;
        if (sp >= 0 && sp < SS) {
            float raw = base[(size_t)sp * HH + c];
            float2 st = sstat[r];
            v = (raw - st.x) * st.y * lgs[c] + lbs[c];
        }
        sb[r][c] = v;
    }
    __syncthreads();
    int c = tid & 127;
    int rr0 = (tid >> 7) * 32;
    float wr[KW];
#pragma unroll
    for (int t = 0; t < KW; t++) wr[t] = w[(c0 + c) * KW + t];
    float bz = bias[c0 + c];
    float* obase = out + ((size_t)b * SS + s0) * HH + c0 + c;
#pragma unroll 4
    for (int r = 0; r < 32; r++) {
        int sl = rr0 + r;
        float acc = bz;
#pragma unroll
        for (int t = 0; t < KW; t++) acc = fmaf(sb[sl + t][c], wr[t], acc);
        obase[(size_t)(sl) * HH] = acc;
    }
}

// ---------------- fp16 tensor-core GEMM (optional fused LN on A) ----------------
// chunk = 16 k-floats = 8 half2 pairs per row; smem row stride 12 uint32
template <bool LNA, bool RELU, bool RES>
__global__ void __launch_bounds__(256, 2)
tgemm(const float* __restrict__ A, const float* __restrict__ W,
      const float* __restrict__ bias, const float* res,
      const float* __restrict__ stats, const float* __restrict__ lng,
      const float* __restrict__ lnb,
      float* out, int Ndim, int Kdim) {
    __shared__ uint32_t Asm[2][128 * 12];
    __shared__ uint32_t Wsm[2][128 * 12];
    int bm = blockIdx.y * 128, bn = blockIdx.x * 128;
    int tid = threadIdx.x;
    int wid = tid >> 5, lane = tid & 31;
    int wm = (wid & 3) * 32, wn = (wid >> 2) * 64;
    int r = lane >> 2, c = lane & 3;

    float acc[2][8][4];
#pragma unroll
    for (int i = 0; i < 2; i++)
#pragma unroll
        for (int j = 0; j < 8; j++)
#pragma unroll
            for (int q = 0; q < 4; q++) acc[i][j][q] = 0.f;

    int row0 = tid >> 2, c40 = (tid & 3) << 2;
    int row1 = row0 + 64;
    const float* Ap0 = A + (size_t)(bm + row0) * Kdim + c40;
    const float* Ap1 = A + (size_t)(bm + row1) * Kdim + c40;
    const float* Wp0 = W + (size_t)(bn + row0) * Kdim + c40;
    const float* Wp1 = W + (size_t)(bn + row1) * Kdim + c40;
    int so0 = row0 * 12 + (c40 >> 1), so1 = row1 * 12 + (c40 >> 1);

    float m0 = 0.f, r0s = 1.f, m1 = 0.f, r1s = 1.f;
    if (LNA) {
        float2 st0 = *(const float2*)(stats + (size_t)(bm + row0) * 2);
        float2 st1 = *(const float2*)(stats + (size_t)(bm + row1) * 2);
        m0 = st0.x; r0s = st0.y; m1 = st1.x; r1s = st1.y;
    }

    float4 a0 = *(const float4*)Ap0;
    float4 a1 = *(const float4*)Ap1;
    float4 w0 = *(const float4*)Wp0;
    float4 w1 = *(const float4*)Wp1;
    float4 g4, b4;
    if (LNA) {
        g4 = *(const float4*)(lng + c40);
        b4 = *(const float4*)(lnb + c40);
    }

    int buf = 0;
    int nk = Kdim >> 4;
    for (int s = 1;; s++) {
        {
            float4 ta0 = a0, ta1 = a1;
            if (LNA) {
                ta0.x = (a0.x - m0) * r0s * g4.x + b4.x;
                ta0.y = (a0.y - m0) * r0s * g4.y + b4.y;
                ta0.z = (a0.z - m0) * r0s * g4.z + b4.z;
                ta0.w = (a0.w - m0) * r0s * g4.w + b4.w;
                ta1.x = (a1.x - m1) * r1s * g4.x + b4.x;
                ta1.y = (a1.y - m1) * r1s * g4.y + b4.y;
                ta1.z = (a1.z - m1) * r1s * g4.z + b4.z;
                ta1.w = (a1.w - m1) * r1s * g4.w + b4.w;
            }
            uint2 u;
            u.x = h2(ta0.x, ta0.y); u.y = h2(ta0.z, ta0.w);
            *(uint2*)&Asm[buf][so0] = u;
            u.x = h2(ta1.x, ta1.y); u.y = h2(ta1.z, ta1.w);
            *(uint2*)&Asm[buf][so1] = u;
            u.x = h2(w0.x, w0.y); u.y = h2(w0.z, w0.w);
            *(uint2*)&Wsm[buf][so0] = u;
            u.x = h2(w1.x, w1.y); u.y = h2(w1.z, w1.w);
            *(uint2*)&Wsm[buf][so1] = u;
        }
        __syncthreads();
        bool more = (s < nk);
        if (more) {
            a0 = *(const float4*)(Ap0 + s * 16);
            a1 = *(const float4*)(Ap1 + s * 16);
            w0 = *(const float4*)(Wp0 + s * 16);
            w1 = *(const float4*)(Wp1 + s * 16);
            if (LNA) {
                g4 = *(const float4*)(lng + s * 16 + c40);
                b4 = *(const float4*)(lnb + s * 16 + c40);
            }
        }
        {
            uint32_t af[2][4], bf[8][2];
#pragma unroll
            for (int i = 0; i < 2; i++) {
                const uint32_t* p = &Asm[buf][(wm + i * 16 + r) * 12 + c];
                af[i][0] = p[0];
                af[i][1] = p[96];     // +8 rows
                af[i][2] = p[4];      // pair c+4
                af[i][3] = p[100];
            }
#pragma unroll
            for (int j = 0; j < 8; j++) {
                const uint32_t* p = &Wsm[buf][(wn + j * 8 + r) * 12 + c];
                bf[j][0] = p[0];
                bf[j][1] = p[4];
            }
#pragma unroll
            for (int i = 0; i < 2; i++)
#pragma unroll
                for (int j = 0; j < 8; j++)
                    MMA_F16(acc[i][j], af[i], bf[j]);
        }
        if (!more) break;
        buf ^= 1;
    }

#pragma unroll
    for (int i = 0; i < 2; i++) {
        int m0i = bm + wm + i * 16 + r;
#pragma unroll
        for (int j = 0; j < 8; j++) {
            int n0 = bn + wn + j * 8 + 2 * c;
            float2 b2 = *(const float2*)(bias + n0);
            float v0 = acc[i][j][0] + b2.x;
            float v1 = acc[i][j][1] + b2.y;
            float v2 = acc[i][j][2] + b2.x;
            float v3 = acc[i][j][3] + b2.y;
            if (RELU) {
                v0 = fmaxf(v0, 0.f); v1 = fmaxf(v1, 0.f);
                v2 = fmaxf(v2, 0.f); v3 = fmaxf(v3, 0.f);
            }
            if (RES) {
                float2 r0v = *(const float2*)(res + (size_t)m0i * Ndim + n0);
                float2 r1v = *(const float2*)(res + (size_t)(m0i + 8) * Ndim + n0);
                v0 += r0v.x; v1 += r0v.y; v2 += r1v.x; v3 += r1v.y;
            }
            float2 o0 = {v0, v1}, o1 = {v2, v3};
            *(float2*)(out + (size_t)m0i * Ndim + n0) = o0;
            *(float2*)(out + (size_t)(m0i + 8) * Ndim + n0) = o1;
        }
    }
}

// ---------------- attention: fp16 QK/rdot, tf32 PV/rel_v ----------------
#define TQ    32
#define QSTP  36      // Q pair stride (uint32)
#define KSTP  36      // K pair stride (uint32)
#define KST   72      // V float stride (PV phase)
#define SCST  516
#define EBST  72
#define RDST  40

__global__ void __launch_bounds__(256)
attn_kernel(const float* __restrict__ QKV, const float* __restrict__ EK,
            const float* __restrict__ EV, float* __restrict__ O) {
    int qt = blockIdx.x, h = blockIdx.y, b = blockIdx.z;
    int q0 = qt * TQ;
    extern __shared__ float sm[];
    uint32_t* qsu = (uint32_t*)sm;           // 32*36 = 1152 words
    float* sc   = sm + 1152;                 // 32*516 = 16512
    float* kt   = sc + 16512;                // 256*72 floats (PV) / 256*36 words (QK)
    uint32_t* ktu = (uint32_t*)kt;
    uint32_t* ebku = (uint32_t*)(kt + 18432); // 40*36 = 1440 words
    float* ebv  = kt + 18432 + 1440;         // 40*72 = 2880
    float* rdot = ebv + 2880;                // 32*40 = 1280
    float* wsum = rdot + 1280;               // 1280
    float* rsum = wsum + 1280;               // 32

    int tid = threadIdx.x;
    int w = tid >> 5, lane = tid & 31;
    int r = lane >> 2, c = lane & 3;

    size_t bh_in  = ((size_t)b * SS) * RS3 + h * DK;
    size_t bh_out = ((size_t)b * SS) * HH  + h * DK;

    // ---- stage Q as half2 pairs ----
#pragma unroll
    for (int i = 0; i < 2; i++) {
        int f = tid + (i << 8);
        int row = f >> 4, c4 = (f & 15) << 2;
        float4 v = *(const float4*)(QKV + bh_in + (size_t)(q0 + row) * RS3 + c4);
        uint32_t* d = qsu + row * QSTP + (c4 >> 1);
        d[0] = h2(v.x, v.y); d[1] = h2(v.z, v.w);
    }
    // ---- stage embed_k (pairs) / embed_v (floats); rows 33..39 zero ----
    for (int f = tid; f < 40 * 16; f += 256) {
        int row = f >> 4, c4 = (f & 15) << 2;
        float4 vk = {0.f, 0.f, 0.f, 0.f}, vv = {0.f, 0.f, 0.f, 0.f};
        if (row < NV) {
            vk = *(const float4*)(EK + row * DK + c4);
            vv = *(const float4*)(EV + row * DK + c4);
        }
        uint32_t* dk = ebku + row * QSTP + (c4 >> 1);
        dk[0] = h2(vk.x, vk.y); dk[1] = h2(vk.z, vk.w);
        float* dv = ebv + row * EBST + c4;
        dv[0] = f2tff(vv.x); dv[1] = f2tff(vv.y); dv[2] = f2tff(vv.z); dv[3] = f2tff(vv.w);
    }
    for (int f = tid; f < 32 * RDST; f += 256) wsum[f] = 0.f;
    __syncthreads();

    // ---- rdot = Q · embed_k^T (fp16 m16n8k16, warps 0..4) ----
    if (w < 5) {
        float acc[2][4] = {{0.f, 0.f, 0.f, 0.f}, {0.f, 0.f, 0.f, 0.f}};
#pragma unroll
        for (int ks = 0; ks < 4; ks++) {
            uint32_t a[2][4], bf[2];
#pragma unroll
            for (int i = 0; i < 2; i++) {
                const uint32_t* p = qsu + (i * 16 + r) * QSTP + ks * 8 + c;
                a[i][0] = p[0]; a[i][1] = p[8 * QSTP];
                a[i][2] = p[4]; a[i][3] = p[8 * QSTP + 4];
            }
            const uint32_t* pb = ebku + (w * 8 + r) * QSTP + ks * 8 + c;
            bf[0] = pb[0]; bf[1] = pb[4];
            MMA_F16(acc[0], a[0], bf);
            MMA_F16(acc[1], a[1], bf);
        }
#pragma unroll
        for (int i = 0; i < 2; i++) {
            int row = i * 16 + r;
            rdot[row * RDST + w * 8 + 2 * c]           = acc[i][0];
            rdot[row * RDST + w * 8 + 2 * c + 1]       = acc[i][1];
            rdot[(row + 8) * RDST + w * 8 + 2 * c]     = acc[i][2];
            rdot[(row + 8) * RDST + w * 8 + 2 * c + 1] = acc[i][3];
        }
    }
    __syncthreads();

    // ---- QK over 256-key tiles (fp16): warp w owns keys [w*32, w*32+32) ----
    for (int kt0 = 0; kt0 < SS; kt0 += 256) {
#pragma unroll
        for (int i = 0; i < 16; i++) {
            int f = tid + (i << 8);
            int rr = f >> 4, c4 = (f & 15) << 2;
            float4 v = *(const float4*)(QKV + bh_in + HH + (size_t)(kt0 + rr) * RS3 + c4);
            uint32_t* d = ktu + rr * KSTP + (c4 >> 1);
            d[0] = h2(v.x, v.y); d[1] = h2(v.z, v.w);
        }
        __syncthreads();
        float acc[2][4][4];
#pragma unroll
        for (int i = 0; i < 2; i++)
#pragma unroll
            for (int j = 0; j < 4; j++)
#pragma unroll
                for (int q = 0; q < 4; q++) acc[i][j][q] = 0.f;
#pragma unroll
        for (int ks = 0; ks < 4; ks++) {
            uint32_t a[2][4];
#pragma unroll
            for (int i = 0; i < 2; i++) {
                const uint32_t* p = qsu + (i * 16 + r) * QSTP + ks * 8 + c;
                a[i][0] = p[0]; a[i][1] = p[8 * QSTP];
                a[i][2] = p[4]; a[i][3] = p[8 * QSTP + 4];
            }
#pragma unroll
            for (int jn = 0; jn < 4; jn++) {
                uint32_t bf[2];
                const uint32_t* pb = ktu + (w * 32 + jn * 8 + r) * KSTP + ks * 8 + c;
                bf[0] = pb[0]; bf[1] = pb[4];
                MMA_F16(acc[0][jn], a[0], bf);
                MMA_F16(acc[1][jn], a[1], bf);
            }
        }
#pragma unroll
        for (int i = 0; i < 2; i++) {
#pragma unroll
            for (int jn = 0; jn < 4; jn++) {
                int colb = kt0 + w * 32 + jn * 8 + 2 * c;
#pragma unroll
                for (int cc = 0; cc < 4; cc++) {
                    int row = i * 16 + r + ((cc >> 1) << 3);
                    int key = colb + (cc & 1);
                    int qg = q0 + row;
                    int dd = key - qg;
                    dd = dd < -16 ? -16 : (dd > 16 ? 16 : dd);
                    sc[row * SCST + key] = acc[i][jn][cc] + rdot[row * RDST + dd + 16];
                }
            }
        }
        __syncthreads();
    }

    // ---- softmax + bucket weight sums ----
    {
        for (int rr = w; rr < TQ; rr += 8) {
            float* row = sc + rr * SCST;
            int qg = q0 + rr;
            float mx = -1e30f;
            for (int k = lane; k < SS; k += 32) mx = fmaxf(mx, row[k]);
#pragma unroll
            for (int o = 16; o > 0; o >>= 1)
                mx = fmaxf(mx, __shfl_xor_sync(0xffffffffu, mx, o));
            float sum = 0.f, w0 = 0.f, w32 = 0.f;
            for (int k = lane; k < SS; k += 32) {
                float e = __expf(row[k] - mx);
                row[k] = e;
                sum += e;
                if (k <= qg - 16) w0 += e;
                if (k >= qg + 16) w32 += e;
            }
#pragma unroll
            for (int o = 16; o > 0; o >>= 1) {
                sum += __shfl_xor_sync(0xffffffffu, sum, o);
                w0  += __shfl_xor_sync(0xffffffffu, w0, o);
                w32 += __shfl_xor_sync(0xffffffffu, w32, o);
            }
            __syncwarp();
            if (lane == 0) {
                rsum[rr] = sum;
                wsum[rr * RDST + 0] = w0;
                wsum[rr * RDST + 32] = w32;
            } else {
                int k = qg + lane - 16;
                wsum[rr * RDST + lane] = (k >= 0 && k < SS) ? row[k] : 0.f;
            }
        }
    }
    __syncthreads();

    // ---- PV + rel_v (tf32): warp w owns d-slice [w*8, w*8+8) ----
    {
        float acc[2][4];
#pragma unroll
        for (int i = 0; i < 2; i++)
#pragma unroll
            for (int q = 0; q < 4; q++) acc[i][q] = 0.f;

        // rel_v: wsum[32x40] x ebv[40x64]
#pragma unroll
        for (int ks = 0; ks < 5; ks++) {
            uint32_t a[2][4], bf[2];
#pragma unroll
            for (int i = 0; i < 2; i++) {
                int base = (i * 16 + r) * RDST + ks * 8 + c;
                a[i][0] = f2tf(wsum[base]);
                a[i][1] = f2tf(wsum[base + 8 * RDST]);
                a[i][2] = f2tf(wsum[base + 4]);
                a[i][3] = f2tf(wsum[base + 8 * RDST + 4]);
            }
            int pb = (ks * 8 + c) * EBST + w * 8 + r;
            bf[0] = U(ebv[pb]); bf[1] = U(ebv[pb + 4 * EBST]);
            MMA_TF32(acc[0], a[0], bf);
            MMA_TF32(acc[1], a[1], bf);
        }

        for (int kt0 = 0; kt0 < SS; kt0 += 256) {
#pragma unroll
            for (int i = 0; i < 16; i++) {
                int f = tid + (i << 8);
                int rr = f >> 4, c4 = (f & 15) << 2;
                float4 v = *(const float4*)(QKV + bh_in + 2 * HH +
                                            (size_t)(kt0 + rr) * RS3 + c4);
                float* d = kt + rr * KST + c4;
                d[0] = f2tff(v.x); d[1] = f2tff(v.y); d[2] = f2tff(v.z); d[3] = f2tff(v.w);
            }
            __syncthreads();
#pragma unroll 8
            for (int ks = 0; ks < 32; ks++) {
                int kb = ks * 8;
                uint32_t a[2][4], bf[2];
#pragma unroll
                for (int i = 0; i < 2; i++) {
                    const float* p = sc + (i * 16 + r) * SCST + kt0 + kb + c;
                    a[i][0] = f2tf(p[0]);
                    a[i][1] = f2tf(p[8 * SCST]);
                    a[i][2] = f2tf(p[4]);
                    a[i][3] = f2tf(p[8 * SCST + 4]);
                }
                int pb = (kb + c) * KST + w * 8 + r;
                bf[0] = U(kt[pb]); bf[1] = U(kt[pb + 4 * KST]);
                MMA_TF32(acc[0], a[0], bf);
                MMA_TF32(acc[1], a[1], bf);
            }
            __syncthreads();
        }

#pragma unroll
        for (int i = 0; i < 2; i++) {
            int row0 = i * 16 + r, row1 = row0 + 8;
            float inv0 = 1.f / rsum[row0];
            float inv1 = 1.f / rsum[row1];
            int col = w * 8 + 2 * c;
            float2 o0 = {acc[i][0] * inv0, acc[i][1] * inv0};
            float2 o1 = {acc[i][2] * inv1, acc[i][3] * inv1};
            *(float2*)(O + bh_out + (size_t)(q0 + row0) * HH + col) = o0;
            *(float2*)(O + bh_out + (size_t)(q0 + row1) * HH + col) = o1;
        }
    }
}

// ---------------- launcher ----------------
extern "C" void kernel_launch(void* const* d_in, const int* in_sizes, int n_in,
                              void* d_out, int out_size) {
    const float* x    = (const float*)d_in[0];
    const int*   mask = (const int*)d_in[1];
    const float* dw_w = (const float*)d_in[2];
    const float* dw_b = (const float*)d_in[3];
    const float* pw_w = (const float*)d_in[4];
    const float* pw_b = (const float*)d_in[5];
    const float* lcg  = (const float*)d_in[6];
    const float* lcb  = (const float*)d_in[7];
    const float* wq   = (const float*)d_in[8];
    const float* bq   = (const float*)d_in[9];
    const float* wk   = (const float*)d_in[10];
    const float* bk   = (const float*)d_in[11];
    const float* wv   = (const float*)d_in[12];
    const float* bv   = (const float*)d_in[13];
    const float* wo   = (const float*)d_in[14];
    const float* bo   = (const float*)d_in[15];
    const float* ek   = (const float*)d_in[16];
    const float* ev   = (const float*)d_in[17];
    const float* lag  = (const float*)d_in[18];
    const float* lab  = (const float*)d_in[19];
    const float* wff  = (const float*)d_in[20];
    const float* bff  = (const float*)d_in[21];
    const float* lfg  = (const float*)d_in[22];
    const float* lfb  = (const float*)d_in[23];
    float* xo = (float*)d_out;

    float *ph, *pqkv, *pwqkv, *pbqkv, *ppe, *pst;
    cudaGetSymbolAddress((void**)&ph, g_h);
    cudaGetSymbolAddress((void**)&pqkv, g_qkv);
    cudaGetSymbolAddress((void**)&pwqkv, g_wqkv);
    cudaGetSymbolAddress((void**)&pbqkv, g_bqkv);
    cudaGetSymbolAddress((void**)&ppe, g_pe);
    cudaGetSymbolAddress((void**)&pst, g_stats);

    cudaMemcpyAsync(pwqkv,               wq, (size_t)HH * HH * 4, cudaMemcpyDeviceToDevice);
    cudaMemcpyAsync(pwqkv + HH * HH,     wk, (size_t)HH * HH * 4, cudaMemcpyDeviceToDevice);
    cudaMemcpyAsync(pwqkv + 2 * HH * HH, wv, (size_t)HH * HH * 4, cudaMemcpyDeviceToDevice);
    cudaMemcpyAsync(pbqkv,          bq, HH * 4, cudaMemcpyDeviceToDevice);
    cudaMemcpyAsync(pbqkv + HH,     bk, HH * 4, cudaMemcpyDeviceToDevice);
    cudaMemcpyAsync(pbqkv + 2 * HH, bv, HH * 4, cudaMemcpyDeviceToDevice);

    const int ATTN_SMEM = (1152 + 16512 + 18432 + 1440 + 2880 + 1280 + 1280 + 32) * 4;
    cudaFuncSetAttribute((const void*)attn_kernel,
                         cudaFuncAttributeMaxDynamicSharedMemorySize, ATTN_SMEM);

    dim3 gemm_grid(HH / 128, ROWS / 128);
    dim3 qkv_grid(RS3 / 128, ROWS / 128);
    dim3 dw_grid(8, 4, 32);

    pe_kernel<<<(SS * HH) / 256, 256>>>(ppe);
    pos_add_kernel<<<TOT / 256, 256>>>(x, mask, ppe, xo);

    for (int i = 0; i < 2; i++) {
        ln_stats<<<ROWS / 8, 256>>>(xo, pst);
        dwconv_kernel<<<dw_grid, 256>>>(xo, pst, lcg + i * HH, lcb + i * HH,
                                        dw_w + i * HH * KW, dw_b + i * HH, ph);
        tgemm<false, true, true><<<gemm_grid, 256>>>(ph, pw_w + (size_t)i * HH * HH,
                                                     pw_b + i * HH, xo,
                                                     nullptr, nullptr, nullptr,
                                                     xo, HH, HH);
    }

    ln_stats<<<ROWS / 8, 256>>>(xo, pst);
    tgemm<true, false, false><<<qkv_grid, 256>>>(xo, pwqkv, pbqkv, nullptr,
                                                 pst, lag, lab, pqkv, RS3, HH);

    attn_kernel<<<dim3(SS / TQ, NHD, BB), 256, ATTN_SMEM>>>(pqkv, ek, ev, ph);

    // O-proj: x' = x + attn·wo + bo -> g_qkv (free after attention)
    tgemm<false, false, true><<<gemm_grid, 256>>>(ph, wo, bo, xo,
                                                  nullptr, nullptr, nullptr,
                                                  pqkv, HH, HH);

    // FFN: d_out = x' + relu(LN(x')·wff + bff)
    ln_stats<<<ROWS / 8, 256>>>(pqkv, pst);
    tgemm<true, true, true><<<gemm_grid, 256>>>(pqkv, wff, bff, pqkv,
                                                pst, lfg, lfb, xo, HH, HH);
}

// round 11
// speedup vs baseline: 2.9623x; 1.1252x over previous
#include <cuda_runtime.h>
#include <cuda_fp16.h>
#include <math.h>
#include <stdint.h>

// ---------------- problem constants ----------------
#define BB   32
#define SS   512
#define HH   512
#define NHD  8
#define DK   64
#define KW   7
#define NV   33
#define RS3  (3*HH)
#define ROWS (BB*SS)
#define TOT  (BB*SS*HH)

// ---------------- scratch ----------------
__device__ float  g_h[TOT];              // half-aliased activation scratch
__device__ float  g_qkv[ROWS * RS3];     // [0, ROWS*RS3/2) fp32 = QKV halves; upper = x'
__device__ __half g_wh[7 * HH * HH];     // half weights: pw0,pw1,wq,wk,wv,wo,wff
__device__ float  g_bqkv[3 * HH];
__device__ float  g_pe[SS * HH];
__device__ float  g_stats[ROWS * 2];

// ---------------- helpers ----------------
__device__ __forceinline__ uint32_t f2tf(float f) {
    uint32_t u;
    asm("cvt.rna.tf32.f32 %0, %1;" : "=r"(u) : "f"(f));
    return u;
}
__device__ __forceinline__ float f2tff(float f) {
    return __uint_as_float(f2tf(f));
}
__device__ __forceinline__ uint32_t h2(float x, float y) {
    __half2 h = __floats2half2_rn(x, y);
    return *reinterpret_cast<uint32_t*>(&h);
}
#define U(x) __float_as_uint(x)

#define MMA_TF32(d, a, b)                                                     \
    asm volatile("mma.sync.aligned.m16n8k8.row.col.f32.tf32.tf32.f32 "       \
                 "{%0,%1,%2,%3}, {%4,%5,%6,%7}, {%8,%9}, {%0,%1,%2,%3};"     \
                 : "+f"(d[0]), "+f"(d[1]), "+f"(d[2]), "+f"(d[3])            \
                 : "r"(a[0]), "r"(a[1]), "r"(a[2]), "r"(a[3]),               \
                   "r"(b[0]), "r"(b[1]))

#define MMA_F16(d, a, b)                                                      \
    asm volatile("mma.sync.aligned.m16n8k16.row.col.f32.f16.f16.f32 "        \
                 "{%0,%1,%2,%3}, {%4,%5,%6,%7}, {%8,%9}, {%0,%1,%2,%3};"     \
                 : "+f"(d[0]), "+f"(d[1]), "+f"(d[2]), "+f"(d[3])            \
                 : "r"(a[0]), "r"(a[1]), "r"(a[2]), "r"(a[3]),               \
                   "r"(b[0]), "r"(b[1]))

// ---------------- weight convert (fp32 -> half), 7 matrices ----------------
__global__ void wconv_kernel(const float* __restrict__ pw,
                             const float* __restrict__ wq,
                             const float* __restrict__ wk,
                             const float* __restrict__ wv,
                             const float* __restrict__ wo,
                             const float* __restrict__ wff,
                             __half* __restrict__ out) {
    int m = blockIdx.y;
    int idx = blockIdx.x * 256 + threadIdx.x;   // HH*HH/256 = 1024 blocks
    const float* src;
    switch (m) {
        case 0: src = pw; break;
        case 1: src = pw + HH * HH; break;
        case 2: src = wq; break;
        case 3: src = wk; break;
        case 4: src = wv; break;
        case 5: src = wo; break;
        default: src = wff; break;
    }
    out[(size_t)m * HH * HH + idx] = __float2half(src[idx]);
}

// ---------------- positional encoding table ----------------
__global__ void pe_kernel(float* __restrict__ pe) {
    int idx = blockIdx.x * 256 + threadIdx.x;
    int h = idx & (HH - 1);
    int s = idx >> 9;
    float v = 0.f;
    if (s > 0) {
        float pos = (float)(s - 1);
        int i2 = h & ~1;
        float div = expf((float)i2 * (-9.210340371976184f / (float)HH));
        float ang = pos * div;
        v = (h & 1) ? cosf(ang) : sinf(ang);
    }
    pe[idx] = v;
}

__global__ void pos_add_kernel(const float* __restrict__ x,
                               const int* __restrict__ mask,
                               const float* __restrict__ pe,
                               float* __restrict__ out) {
    int idx = blockIdx.x * 256 + threadIdx.x;
    int s = (idx >> 9) & (SS - 1);
    int b = idx >> 18;
    out[idx] = x[idx] + pe[idx & (SS * HH - 1)] * (float)mask[(b << 9) + s];
}

// ---------------- LN stats ----------------
__global__ void ln_stats(const float* __restrict__ x, float* __restrict__ stats) {
    int row = blockIdx.x * 8 + (threadIdx.x >> 5);
    int lane = threadIdx.x & 31;
    const float4* xr = (const float4*)(x + (size_t)row * HH);
    float s = 0.f, sq = 0.f;
#pragma unroll
    for (int i = 0; i < 4; i++) {
        float4 v = xr[lane + i * 32];
        s += v.x + v.y + v.z + v.w;
        sq += v.x * v.x + v.y * v.y + v.z * v.z + v.w * v.w;
    }
#pragma unroll
    for (int o = 16; o > 0; o >>= 1) {
        s  += __shfl_xor_sync(0xffffffffu, s, o);
        sq += __shfl_xor_sync(0xffffffffu, sq, o);
    }
    if (lane == 0) {
        float mean = s * (1.f / HH);
        float var = sq * (1.f / HH) - mean * mean;
        stats[row * 2] = mean;
        stats[row * 2 + 1] = rsqrtf(var + 1e-5f);
    }
}

// ---------------- depthwise conv with fused LN, half output ----------------
__global__ void dwconv_kernel(const float* __restrict__ x,
                              const float* __restrict__ stats,
                              const float* __restrict__ lg,
                              const float* __restrict__ lb,
                              const float* __restrict__ w,
                              const float* __restrict__ bias,
                              __half* __restrict__ out) {
    __shared__ float sb[70][128];
    __shared__ float2 sstat[70];
    __shared__ float lgs[128], lbs[128];
    int s0 = blockIdx.x * 64, c0 = blockIdx.y * 128, b = blockIdx.z;
    int tid = threadIdx.x;
    if (tid < 128) { lgs[tid] = lg[c0 + tid]; lbs[tid] = lb[c0 + tid]; }
    else if (tid < 198) {
        int sp = s0 + (tid - 128) - 3;
        float2 st = {0.f, 0.f};
        if (sp >= 0 && sp < SS) st = *(const float2*)(stats + ((size_t)b * SS + sp) * 2);
        sstat[tid - 128] = st;
    }
    __syncthreads();
    const float* base = x + ((size_t)b * SS) * HH + c0;
    for (int i = tid; i < 70 * 128; i += 256) {
        int r = i >> 7, c = i & 127;
        int sp = s0 + r - 3;
        float v = 0.f;
        if (sp >= 0 && sp < SS) {
            float raw = base[(size_t)sp * HH + c];
            float2 st = sstat[r];
            v = (raw - st.x) * st.y * lgs[c] + lbs[c];
        }
        sb[r][c] = v;
    }
    __syncthreads();
    int c = tid & 127;
    int rr0 = (tid >> 7) * 32;
    float wr[KW];
#pragma unroll
    for (int t = 0; t < KW; t++) wr[t] = w[(c0 + c) * KW + t];
    float bz = bias[c0 + c];
    __half* obase = out + ((size_t)b * SS + s0) * HH + c0 + c;
#pragma unroll 4
    for (int r = 0; r < 32; r++) {
        int sl = rr0 + r;
        float acc = bz;
#pragma unroll
        for (int t = 0; t < KW; t++) acc = fmaf(sb[sl + t][c], wr[t], acc);
        obase[(size_t)(sl) * HH] = __float2half(acc);
    }
}

// ---------------- fp16 GEMM: A half OR fp32+LN; out half OR fp32 ----------------
template <bool AHALF, bool LNA, bool OUTH, bool RELU, bool RES>
__global__ void __launch_bounds__(256, 2)
tgemm(const void* __restrict__ Av, const __half* __restrict__ W,
      const float* __restrict__ bias, const float* res,
      const float* __restrict__ stats, const float* __restrict__ lng,
      const float* __restrict__ lnb,
      void* __restrict__ outv, int Ndim, int Kdim) {
    __shared__ uint32_t Asm[2][128 * 12];
    __shared__ uint32_t Wsm[2][128 * 12];
    int bm = blockIdx.y * 128, bn = blockIdx.x * 128;
    int tid = threadIdx.x;
    int wid = tid >> 5, lane = tid & 31;
    int wm = (wid & 3) * 32, wn = (wid >> 2) * 64;
    int r = lane >> 2, c = lane & 3;

    float acc[2][8][4];
#pragma unroll
    for (int i = 0; i < 2; i++)
#pragma unroll
        for (int j = 0; j < 8; j++)
#pragma unroll
            for (int q = 0; q < 4; q++) acc[i][j][q] = 0.f;

    // W staging geometry: thread -> (row, 8-half group)
    int rowW = tid >> 1, grpW = tid & 1;
    const __half* Wp = W + (size_t)(bn + rowW) * Kdim + grpW * 8;
    int soW = rowW * 12 + grpW * 4;

    // A staging geometry
    const __half* Ahp = nullptr;
    const float *Ap0 = nullptr, *Ap1 = nullptr;
    int so0 = 0, so1 = 0;
    int c40 = 0;
    float m0 = 0.f, r0s = 1.f, m1 = 0.f, r1s = 1.f;
    if (AHALF) {
        Ahp = (const __half*)Av + (size_t)(bm + rowW) * Kdim + grpW * 8;
    } else {
        int row0 = tid >> 2;
        c40 = (tid & 3) << 2;
        int row1 = row0 + 64;
        Ap0 = (const float*)Av + (size_t)(bm + row0) * Kdim + c40;
        Ap1 = (const float*)Av + (size_t)(bm + row1) * Kdim + c40;
        so0 = row0 * 12 + (c40 >> 1);
        so1 = row1 * 12 + (c40 >> 1);
        if (LNA) {
            float2 st0 = *(const float2*)(stats + (size_t)(bm + row0) * 2);
            float2 st1 = *(const float2*)(stats + (size_t)(bm + row1) * 2);
            m0 = st0.x; r0s = st0.y; m1 = st1.x; r1s = st1.y;
        }
    }

    uint4 rw = *(const uint4*)Wp;
    uint4 rah;
    float4 a0, a1, g4, b4;
    if (AHALF) {
        rah = *(const uint4*)Ahp;
    } else {
        a0 = *(const float4*)Ap0;
        a1 = *(const float4*)Ap1;
        if (LNA) {
            g4 = *(const float4*)(lng + c40);
            b4 = *(const float4*)(lnb + c40);
        }
    }

    int buf = 0;
    int nk = Kdim >> 4;
    for (int s = 1;; s++) {
        // store current chunk
        *(uint4*)&Wsm[buf][soW] = rw;
        if (AHALF) {
            *(uint4*)&Asm[buf][soW] = rah;
        } else {
            float4 ta0 = a0, ta1 = a1;
            if (LNA) {
                ta0.x = (a0.x - m0) * r0s * g4.x + b4.x;
                ta0.y = (a0.y - m0) * r0s * g4.y + b4.y;
                ta0.z = (a0.z - m0) * r0s * g4.z + b4.z;
                ta0.w = (a0.w - m0) * r0s * g4.w + b4.w;
                ta1.x = (a1.x - m1) * r1s * g4.x + b4.x;
                ta1.y = (a1.y - m1) * r1s * g4.y + b4.y;
                ta1.z = (a1.z - m1) * r1s * g4.z + b4.z;
                ta1.w = (a1.w - m1) * r1s * g4.w + b4.w;
            }
            uint2 u;
            u.x = h2(ta0.x, ta0.y); u.y = h2(ta0.z, ta0.w);
            *(uint2*)&Asm[buf][so0] = u;
            u.x = h2(ta1.x, ta1.y); u.y = h2(ta1.z, ta1.w);
            *(uint2*)&Asm[buf][so1] = u;
        }
        __syncthreads();
        bool more = (s < nk);
        if (more) {
            rw = *(const uint4*)(Wp + s * 16);
            if (AHALF) {
                rah = *(const uint4*)(Ahp + s * 16);
            } else {
                a0 = *(const float4*)(Ap0 + s * 16);
                a1 = *(const float4*)(Ap1 + s * 16);
                if (LNA) {
                    g4 = *(const float4*)(lng + s * 16 + c40);
                    b4 = *(const float4*)(lnb + s * 16 + c40);
                }
            }
        }
        {
            uint32_t af[2][4], bf[8][2];
#pragma unroll
            for (int i = 0; i < 2; i++) {
                const uint32_t* p = &Asm[buf][(wm + i * 16 + r) * 12 + c];
                af[i][0] = p[0];
                af[i][1] = p[96];
                af[i][2] = p[4];
                af[i][3] = p[100];
            }
#pragma unroll
            for (int j = 0; j < 8; j++) {
                const uint32_t* p = &Wsm[buf][(wn + j * 8 + r) * 12 + c];
                bf[j][0] = p[0];
                bf[j][1] = p[4];
            }
#pragma unroll
            for (int i = 0; i < 2; i++)
#pragma unroll
                for (int j = 0; j < 8; j++)
                    MMA_F16(acc[i][j], af[i], bf[j]);
        }
        if (!more) break;
        buf ^= 1;
    }

#pragma unroll
    for (int i = 0; i < 2; i++) {
        int m0i = bm + wm + i * 16 + r;
#pragma unroll
        for (int j = 0; j < 8; j++) {
            int n0 = bn + wn + j * 8 + 2 * c;
            float2 b2 = *(const float2*)(bias + n0);
            float v0 = acc[i][j][0] + b2.x;
            float v1 = acc[i][j][1] + b2.y;
            float v2 = acc[i][j][2] + b2.x;
            float v3 = acc[i][j][3] + b2.y;
            if (RELU) {
                v0 = fmaxf(v0, 0.f); v1 = fmaxf(v1, 0.f);
                v2 = fmaxf(v2, 0.f); v3 = fmaxf(v3, 0.f);
            }
            if (RES) {
                float2 r0v = *(const float2*)(res + (size_t)m0i * Ndim + n0);
                float2 r1v = *(const float2*)(res + (size_t)(m0i + 8) * Ndim + n0);
                v0 += r0v.x; v1 += r0v.y; v2 += r1v.x; v3 += r1v.y;
            }
            if (OUTH) {
                __half* oh = (__half*)outv;
                *(uint32_t*)(oh + (size_t)m0i * Ndim + n0) = h2(v0, v1);
                *(uint32_t*)(oh + (size_t)(m0i + 8) * Ndim + n0) = h2(v2, v3);
            } else {
                float* of = (float*)outv;
                float2 o0 = {v0, v1}, o1 = {v2, v3};
                *(float2*)(of + (size_t)m0i * Ndim + n0) = o0;
                *(float2*)(of + (size_t)(m0i + 8) * Ndim + n0) = o1;
            }
        }
    }
}

// ---------------- attention: half QKV in, half out ----------------
#define TQ    32
#define QSTP  36
#define KSTP  36
#define KST   72
#define SCST  516
#define EBST  72
#define RDST  40

__global__ void __launch_bounds__(256)
attn_kernel(const __half* __restrict__ QKV, const float* __restrict__ EK,
            const float* __restrict__ EV, __half* __restrict__ O) {
    int qt = blockIdx.x, h = blockIdx.y, b = blockIdx.z;
    int q0 = qt * TQ;
    extern __shared__ float sm[];
    uint32_t* qsu = (uint32_t*)sm;            // 32*36
    float* sc   = sm + 1152;                  // 32*516
    float* kt   = sc + 16512;                 // 256*72 f32 (PV) / 256*36 words (QK)
    uint32_t* ktu = (uint32_t*)kt;
    uint32_t* ebku = (uint32_t*)(kt + 18432); // 40*36
    float* ebv  = kt + 18432 + 1440;          // 40*72
    float* rdot = ebv + 2880;
    float* wsum = rdot + 1280;
    float* rsum = wsum + 1280;

    int tid = threadIdx.x;
    int w = tid >> 5, lane = tid & 31;
    int r = lane >> 2, c = lane & 3;

    size_t bh_in  = ((size_t)b * SS) * RS3 + h * DK;
    size_t bh_out = ((size_t)b * SS) * HH  + h * DK;

    // ---- stage Q pairs (raw half copy) ----
#pragma unroll
    for (int i = 0; i < 2; i++) {
        int f = tid + (i << 8);
        int row = f >> 4, c4 = (f & 15) << 2;
        uint2 v = *(const uint2*)(QKV + bh_in + (size_t)(q0 + row) * RS3 + c4);
        uint32_t* d = qsu + row * QSTP + (c4 >> 1);
        d[0] = v.x; d[1] = v.y;
    }
    // ---- stage embed_k (half pairs) / embed_v (f32); rows 33..39 zero ----
    for (int f = tid; f < 40 * 16; f += 256) {
        int row = f >> 4, c4 = (f & 15) << 2;
        float4 vk = {0.f, 0.f, 0.f, 0.f}, vv = {0.f, 0.f, 0.f, 0.f};
        if (row < NV) {
            vk = *(const float4*)(EK + row * DK + c4);
            vv = *(const float4*)(EV + row * DK + c4);
        }
        uint32_t* dk = ebku + row * QSTP + (c4 >> 1);
        dk[0] = h2(vk.x, vk.y); dk[1] = h2(vk.z, vk.w);
        float* dv = ebv + row * EBST + c4;
        dv[0] = f2tff(vv.x); dv[1] = f2tff(vv.y); dv[2] = f2tff(vv.z); dv[3] = f2tff(vv.w);
    }
    for (int f = tid; f < 32 * RDST; f += 256) wsum[f] = 0.f;
    __syncthreads();

    // ---- rdot = Q · embed_k^T (fp16) ----
    if (w < 5) {
        float acc[2][4] = {{0.f, 0.f, 0.f, 0.f}, {0.f, 0.f, 0.f, 0.f}};
#pragma unroll
        for (int ks = 0; ks < 4; ks++) {
            uint32_t a[2][4], bf[2];
#pragma unroll
            for (int i = 0; i < 2; i++) {
                const uint32_t* p = qsu + (i * 16 + r) * QSTP + ks * 8 + c;
                a[i][0] = p[0]; a[i][1] = p[8 * QSTP];
                a[i][2] = p[4]; a[i][3] = p[8 * QSTP + 4];
            }
            const uint32_t* pb = ebku + (w * 8 + r) * QSTP + ks * 8 + c;
            bf[0] = pb[0]; bf[1] = pb[4];
            MMA_F16(acc[0], a[0], bf);
            MMA_F16(acc[1], a[1], bf);
        }
#pragma unroll
        for (int i = 0; i < 2; i++) {
            int row = i * 16 + r;
            rdot[row * RDST + w * 8 + 2 * c]           = acc[i][0];
            rdot[row * RDST + w * 8 + 2 * c + 1]       = acc[i][1];
            rdot[(row + 8) * RDST + w * 8 + 2 * c]     = acc[i][2];
            rdot[(row + 8) * RDST + w * 8 + 2 * c + 1] = acc[i][3];
        }
    }
    __syncthreads();

    // ---- QK (fp16): warp w owns keys [w*32, w*32+32) of 256-key tile ----
    for (int kt0 = 0; kt0 < SS; kt0 += 256) {
#pragma unroll
        for (int i = 0; i < 16; i++) {
            int f = tid + (i << 8);
            int rr = f >> 4, c4 = (f & 15) << 2;
            uint2 v = *(const uint2*)(QKV + bh_in + HH + (size_t)(kt0 + rr) * RS3 + c4);
            uint32_t* d = ktu + rr * KSTP + (c4 >> 1);
            d[0] = v.x; d[1] = v.y;
        }
        __syncthreads();
        float acc[2][4][4];
#pragma unroll
        for (int i = 0; i < 2; i++)
#pragma unroll
            for (int j = 0; j < 4; j++)
#pragma unroll
                for (int q = 0; q < 4; q++) acc[i][j][q] = 0.f;
#pragma unroll
        for (int ks = 0; ks < 4; ks++) {
            uint32_t a[2][4];
#pragma unroll
            for (int i = 0; i < 2; i++) {
                const uint32_t* p = qsu + (i * 16 + r) * QSTP + ks * 8 + c;
                a[i][0] = p[0]; a[i][1] = p[8 * QSTP];
                a[i][2] = p[4]; a[i][3] = p[8 * QSTP + 4];
            }
#pragma unroll
            for (int jn = 0; jn < 4; jn++) {
                uint32_t bf[2];
                const uint32_t* pb = ktu + (w * 32 + jn * 8 + r) * KSTP + ks * 8 + c;
                bf[0] = pb[0]; bf[1] = pb[4];
                MMA_F16(acc[0][jn], a[0], bf);
                MMA_F16(acc[1][jn], a[1], bf);
            }
        }
#pragma unroll
        for (int i = 0; i < 2; i++) {
#pragma unroll
            for (int jn = 0; jn < 4; jn++) {
                int colb = kt0 + w * 32 + jn * 8 + 2 * c;
#pragma unroll
                for (int cc = 0; cc < 4; cc++) {
                    int row = i * 16 + r + ((cc >> 1) << 3);
                    int key = colb + (cc & 1);
                    int qg = q0 + row;
                    int dd = key - qg;
                    dd = dd < -16 ? -16 : (dd > 16 ? 16 : dd);
                    sc[row * SCST + key] = acc[i][jn][cc] + rdot[row * RDST + dd + 16];
                }
            }
        }
        __syncthreads();
    }

    // ---- softmax + bucket weight sums ----
    {
        for (int rr = w; rr < TQ; rr += 8) {
            float* row = sc + rr * SCST;
            int qg = q0 + rr;
            float mx = -1e30f;
            for (int k = lane; k < SS; k += 32) mx = fmaxf(mx, row[k]);
#pragma unroll
            for (int o = 16; o > 0; o >>= 1)
                mx = fmaxf(mx, __shfl_xor_sync(0xffffffffu, mx, o));
            float sum = 0.f, w0 = 0.f, w32 = 0.f;
            for (int k = lane; k < SS; k += 32) {
                float e = __expf(row[k] - mx);
                row[k] = e;
                sum += e;
                if (k <= qg - 16) w0 += e;
                if (k >= qg + 16) w32 += e;
            }
#pragma unroll
            for (int o = 16; o > 0; o >>= 1) {
                sum += __shfl_xor_sync(0xffffffffu, sum, o);
                w0  += __shfl_xor_sync(0xffffffffu, w0, o);
                w32 += __shfl_xor_sync(0xffffffffu, w32, o);
            }
            __syncwarp();
            if (lane == 0) {
                rsum[rr] = sum;
                wsum[rr * RDST + 0] = w0;
                wsum[rr * RDST + 32] = w32;
            } else {
                int k = qg + lane - 16;
                wsum[rr * RDST + lane] = (k >= 0 && k < SS) ? row[k] : 0.f;
            }
        }
    }
    __syncthreads();

    // ---- PV + rel_v (tf32; half->f32 exact): warp w owns d-slice [w*8, +8) ----
    {
        float acc[2][4];
#pragma unroll
        for (int i = 0; i < 2; i++)
#pragma unroll
            for (int q = 0; q < 4; q++) acc[i][q] = 0.f;

#pragma unroll
        for (int ks = 0; ks < 5; ks++) {
            uint32_t a[2][4], bf[2];
#pragma unroll
            for (int i = 0; i < 2; i++) {
                int base = (i * 16 + r) * RDST + ks * 8 + c;
                a[i][0] = f2tf(wsum[base]);
                a[i][1] = f2tf(wsum[base + 8 * RDST]);
                a[i][2] = f2tf(wsum[base + 4]);
                a[i][3] = f2tf(wsum[base + 8 * RDST + 4]);
            }
            int pb = (ks * 8 + c) * EBST + w * 8 + r;
            bf[0] = U(ebv[pb]); bf[1] = U(ebv[pb + 4 * EBST]);
            MMA_TF32(acc[0], a[0], bf);
            MMA_TF32(acc[1], a[1], bf);
        }

        for (int kt0 = 0; kt0 < SS; kt0 += 256) {
#pragma unroll
            for (int i = 0; i < 16; i++) {
                int f = tid + (i << 8);
                int rr = f >> 4, c4 = (f & 15) << 2;
                uint2 v = *(const uint2*)(QKV + bh_in + 2 * HH +
                                          (size_t)(kt0 + rr) * RS3 + c4);
                __half2 p0 = *(__half2*)&v.x;
                __half2 p1 = *(__half2*)&v.y;
                float* d = kt + rr * KST + c4;
                d[0] = __low2float(p0); d[1] = __high2float(p0);
                d[2] = __low2float(p1); d[3] = __high2float(p1);
            }
            __syncthreads();
#pragma unroll 8
            for (int ks = 0; ks < 32; ks++) {
                int kb = ks * 8;
                uint32_t a[2][4], bf[2];
#pragma unroll
                for (int i = 0; i < 2; i++) {
                    const float* p = sc + (i * 16 + r) * SCST + kt0 + kb + c;
                    a[i][0] = f2tf(p[0]);
                    a[i][1] = f2tf(p[8 * SCST]);
                    a[i][2] = f2tf(p[4]);
                    a[i][3] = f2tf(p[8 * SCST + 4]);
                }
                int pb = (kb + c) * KST + w * 8 + r;
                bf[0] = U(kt[pb]); bf[1] = U(kt[pb + 4 * KST]);
                MMA_TF32(acc[0], a[0], bf);
                MMA_TF32(acc[1], a[1], bf);
            }
            __syncthreads();
        }

#pragma unroll
        for (int i = 0; i < 2; i++) {
            int row0 = i * 16 + r, row1 = row0 + 8;
            float inv0 = 1.f / rsum[row0];
            float inv1 = 1.f / rsum[row1];
            int col = w * 8 + 2 * c;
            *(uint32_t*)(O + bh_out + (size_t)(q0 + row0) * HH + col) =
                h2(acc[i][0] * inv0, acc[i][1] * inv0);
            *(uint32_t*)(O + bh_out + (size_t)(q0 + row1) * HH + col) =
                h2(acc[i][2] * inv1, acc[i][3] * inv1);
        }
    }
}

// ---------------- launcher ----------------
extern "C" void kernel_launch(void* const* d_in, const int* in_sizes, int n_in,
                              void* d_out, int out_size) {
    const float* x    = (const float*)d_in[0];
    const int*   mask = (const int*)d_in[1];
    const float* dw_w = (const float*)d_in[2];
    const float* dw_b = (const float*)d_in[3];
    const float* pw_w = (const float*)d_in[4];
    const float* pw_b = (const float*)d_in[5];
    const float* lcg  = (const float*)d_in[6];
    const float* lcb  = (const float*)d_in[7];
    const float* wq   = (const float*)d_in[8];
    const float* bq   = (const float*)d_in[9];
    const float* wk   = (const float*)d_in[10];
    const float* bk   = (const float*)d_in[11];
    const float* wv   = (const float*)d_in[12];
    const float* bv   = (const float*)d_in[13];
    const float* wo   = (const float*)d_in[14];
    const float* bo   = (const float*)d_in[15];
    const float* ek   = (const float*)d_in[16];
    const float* ev   = (const float*)d_in[17];
    const float* lag  = (const float*)d_in[18];
    const float* lab  = (const float*)d_in[19];
    const float* wff  = (const float*)d_in[20];
    const float* bff  = (const float*)d_in[21];
    const float* lfg  = (const float*)d_in[22];
    const float* lfb  = (const float*)d_in[23];
    float* xo = (float*)d_out;

    float *phf, *pqkv, *pbqkv, *ppe, *pst;
    __half* pwh;
    cudaGetSymbolAddress((void**)&phf, g_h);
    cudaGetSymbolAddress((void**)&pqkv, g_qkv);
    cudaGetSymbolAddress((void**)&pwh, g_wh);
    cudaGetSymbolAddress((void**)&pbqkv, g_bqkv);
    cudaGetSymbolAddress((void**)&ppe, g_pe);
    cudaGetSymbolAddress((void**)&pst, g_stats);

    __half* ph_h   = (__half*)phf;                       // half activation scratch
    __half* pqkv_h = (__half*)pqkv;                      // half QKV
    float*  px     = pqkv + (size_t)ROWS * RS3 / 2;      // fp32 x' (disjoint region)

    cudaMemcpyAsync(pbqkv,          bq, HH * 4, cudaMemcpyDeviceToDevice);
    cudaMemcpyAsync(pbqkv + HH,     bk, HH * 4, cudaMemcpyDeviceToDevice);
    cudaMemcpyAsync(pbqkv + 2 * HH, bv, HH * 4, cudaMemcpyDeviceToDevice);

    const int ATTN_SMEM = (1152 + 16512 + 18432 + 1440 + 2880 + 1280 + 1280 + 32) * 4;
    cudaFuncSetAttribute((const void*)attn_kernel,
                         cudaFuncAttributeMaxDynamicSharedMemorySize, ATTN_SMEM);

    dim3 gemm_grid(HH / 128, ROWS / 128);
    dim3 qkv_grid(RS3 / 128, ROWS / 128);
    dim3 dw_grid(8, 4, 32);

    // prep: weights->half, pe table
    wconv_kernel<<<dim3(HH * HH / 256, 7), 256>>>(pw_w, wq, wk, wv, wo, wff, pwh);
    pe_kernel<<<(SS * HH) / 256, 256>>>(ppe);
    pos_add_kernel<<<TOT / 256, 256>>>(x, mask, ppe, xo);

    // conv blocks
    for (int i = 0; i < 2; i++) {
        ln_stats<<<ROWS / 8, 256>>>(xo, pst);
        dwconv_kernel<<<dw_grid, 256>>>(xo, pst, lcg + i * HH, lcb + i * HH,
                                        dw_w + i * HH * KW, dw_b + i * HH, ph_h);
        tgemm<true, false, false, true, true><<<gemm_grid, 256>>>(
            ph_h, pwh + (size_t)i * HH * HH, pw_b + i * HH, xo,
            nullptr, nullptr, nullptr, xo, HH, HH);
    }

    // QKV (LN fused, half output)
    ln_stats<<<ROWS / 8, 256>>>(xo, pst);
    tgemm<false, true, true, false, false><<<qkv_grid, 256>>>(
        xo, pwh + (size_t)2 * HH * HH, pbqkv, nullptr,
        pst, lag, lab, pqkv_h, RS3, HH);

    attn_kernel<<<dim3(SS / TQ, NHD, BB), 256, ATTN_SMEM>>>(pqkv_h, ek, ev, ph_h);

    // O-proj: x' = x + attn·wo + bo -> px (fp32)
    tgemm<true, false, false, false, true><<<gemm_grid, 256>>>(
        ph_h, pwh + (size_t)5 * HH * HH, bo, xo,
        nullptr, nullptr, nullptr, px, HH, HH);

    // FFN: d_out = x' + relu(LN(x')·wff + bff)
    ln_stats<<<ROWS / 8, 256>>>(px, pst);
    tgemm<false, true, false, true, true><<<gemm_grid, 256>>>(
        px, pwh + (size_t)6 * HH * HH, bff, px,
        pst, lfg, lfb, xo, HH, HH);
}

// round 12
// speedup vs baseline: 3.2049x; 1.0819x over previous
#include <cuda_runtime.h>
#include <cuda_fp16.h>
#include <math.h>
#include <stdint.h>

// ---------------- problem constants ----------------
#define BB   32
#define SS   512
#define HH   512
#define NHD  8
#define DK   64
#define KW   7
#define NV   33
#define RS3  (3*HH)
#define ROWS (BB*SS)
#define TOT  (BB*SS*HH)

// ---------------- scratch ----------------
__device__ float  g_h[TOT];
__device__ float  g_qkv[ROWS * RS3];     // lower half: half QKV; upper: fp32 x'
__device__ __half g_wh[7 * HH * HH];
__device__ float  g_bqkv[3 * HH];
__device__ float  g_pe[SS * HH];
__device__ float  g_stats[ROWS * 2];

// ---------------- helpers ----------------
__device__ __forceinline__ uint32_t h2(float x, float y) {
    __half2 h = __floats2half2_rn(x, y);
    return *reinterpret_cast<uint32_t*>(&h);
}
__device__ __forceinline__ uint32_t sptr(const void* p) {
    return (uint32_t)__cvta_generic_to_shared(p);
}
#define U(x) __float_as_uint(x)

#define MMA_TF32(d, a, b)                                                     \
    asm volatile("mma.sync.aligned.m16n8k8.row.col.f32.tf32.tf32.f32 "       \
                 "{%0,%1,%2,%3}, {%4,%5,%6,%7}, {%8,%9}, {%0,%1,%2,%3};"     \
                 : "+f"(d[0]), "+f"(d[1]), "+f"(d[2]), "+f"(d[3])            \
                 : "r"(a[0]), "r"(a[1]), "r"(a[2]), "r"(a[3]),               \
                   "r"(b[0]), "r"(b[1]))

#define MMA_F16(d, a, b)                                                      \
    asm volatile("mma.sync.aligned.m16n8k16.row.col.f32.f16.f16.f32 "        \
                 "{%0,%1,%2,%3}, {%4,%5,%6,%7}, {%8,%9}, {%0,%1,%2,%3};"     \
                 : "+f"(d[0]), "+f"(d[1]), "+f"(d[2]), "+f"(d[3])            \
                 : "r"(a[0]), "r"(a[1]), "r"(a[2]), "r"(a[3]),               \
                   "r"(b[0]), "r"(b[1]))

#define LDSMX4(r0, r1, r2, r3, addr)                                          \
    asm volatile("ldmatrix.sync.aligned.m8n8.x4.shared.b16 {%0,%1,%2,%3}, [%4];" \
                 : "=r"(r0), "=r"(r1), "=r"(r2), "=r"(r3) : "r"(addr))

// ---------------- weight convert ----------------
__global__ void wconv_kernel(const float* __restrict__ pw,
                             const float* __restrict__ wq,
                             const float* __restrict__ wk,
                             const float* __restrict__ wv,
                             const float* __restrict__ wo,
                             const float* __restrict__ wff,
                             __half* __restrict__ out) {
    int m = blockIdx.y;
    int idx = blockIdx.x * 256 + threadIdx.x;
    const float* src;
    switch (m) {
        case 0: src = pw; break;
        case 1: src = pw + HH * HH; break;
        case 2: src = wq; break;
        case 3: src = wk; break;
        case 4: src = wv; break;
        case 5: src = wo; break;
        default: src = wff; break;
    }
    out[(size_t)m * HH * HH + idx] = __float2half(src[idx]);
}

// ---------------- positional encoding ----------------
__global__ void pe_kernel(float* __restrict__ pe) {
    int idx = blockIdx.x * 256 + threadIdx.x;
    int h = idx & (HH - 1);
    int s = idx >> 9;
    float v = 0.f;
    if (s > 0) {
        float pos = (float)(s - 1);
        int i2 = h & ~1;
        float div = expf((float)i2 * (-9.210340371976184f / (float)HH));
        float ang = pos * div;
        v = (h & 1) ? cosf(ang) : sinf(ang);
    }
    pe[idx] = v;
}

__global__ void pos_add_kernel(const float* __restrict__ x,
                               const int* __restrict__ mask,
                               const float* __restrict__ pe,
                               float* __restrict__ out) {
    int idx = blockIdx.x * 256 + threadIdx.x;
    int s = (idx >> 9) & (SS - 1);
    int b = idx >> 18;
    out[idx] = x[idx] + pe[idx & (SS * HH - 1)] * (float)mask[(b << 9) + s];
}

// ---------------- LN stats ----------------
__global__ void ln_stats(const float* __restrict__ x, float* __restrict__ stats) {
    int row = blockIdx.x * 8 + (threadIdx.x >> 5);
    int lane = threadIdx.x & 31;
    const float4* xr = (const float4*)(x + (size_t)row * HH);
    float s = 0.f, sq = 0.f;
#pragma unroll
    for (int i = 0; i < 4; i++) {
        float4 v = xr[lane + i * 32];
        s += v.x + v.y + v.z + v.w;
        sq += v.x * v.x + v.y * v.y + v.z * v.z + v.w * v.w;
    }
#pragma unroll
    for (int o = 16; o > 0; o >>= 1) {
        s  += __shfl_xor_sync(0xffffffffu, s, o);
        sq += __shfl_xor_sync(0xffffffffu, sq, o);
    }
    if (lane == 0) {
        float mean = s * (1.f / HH);
        float var = sq * (1.f / HH) - mean * mean;
        stats[row * 2] = mean;
        stats[row * 2 + 1] = rsqrtf(var + 1e-5f);
    }
}

// ---------------- depthwise conv (fused LN, float4 staging, half out) ----------------
__global__ void dwconv_kernel(const float* __restrict__ x,
                              const float* __restrict__ stats,
                              const float* __restrict__ lg,
                              const float* __restrict__ lb,
                              const float* __restrict__ w,
                              const float* __restrict__ bias,
                              __half* __restrict__ out) {
    __shared__ float sb[70][128];
    __shared__ float2 sstat[70];
    __shared__ float lgs[128], lbs[128];
    int s0 = blockIdx.x * 64, c0 = blockIdx.y * 128, b = blockIdx.z;
    int tid = threadIdx.x;
    if (tid < 128) { lgs[tid] = lg[c0 + tid]; lbs[tid] = lb[c0 + tid]; }
    else if (tid < 198) {
        int sp = s0 + (tid - 128) - 3;
        float2 st = {0.f, 0.f};
        if (sp >= 0 && sp < SS) st = *(const float2*)(stats + ((size_t)b * SS + sp) * 2);
        sstat[tid - 128] = st;
    }
    __syncthreads();
    const float* base = x + ((size_t)b * SS) * HH + c0;
#pragma unroll 3
    for (int i = tid; i < 70 * 32; i += 256) {
        int r = i >> 5, c4 = (i & 31) << 2;
        int sp = s0 + r - 3;
        float4 v = {0.f, 0.f, 0.f, 0.f};
        if (sp >= 0 && sp < SS) {
            v = *(const float4*)(base + (size_t)sp * HH + c4);
            float2 st = sstat[r];
            v.x = (v.x - st.x) * st.y * lgs[c4]     + lbs[c4];
            v.y = (v.y - st.x) * st.y * lgs[c4 + 1] + lbs[c4 + 1];
            v.z = (v.z - st.x) * st.y * lgs[c4 + 2] + lbs[c4 + 2];
            v.w = (v.w - st.x) * st.y * lgs[c4 + 3] + lbs[c4 + 3];
        }
        *(float4*)(&sb[r][c4]) = v;
    }
    __syncthreads();
    int c = tid & 127;
    int rr0 = (tid >> 7) * 32;
    float wr[KW];
#pragma unroll
    for (int t = 0; t < KW; t++) wr[t] = w[(c0 + c) * KW + t];
    float bz = bias[c0 + c];
    __half* obase = out + ((size_t)b * SS + s0) * HH + c0 + c;
#pragma unroll 4
    for (int r = 0; r < 32; r++) {
        int sl = rr0 + r;
        float acc = bz;
#pragma unroll
        for (int t = 0; t < KW; t++) acc = fmaf(sb[sl + t][c], wr[t], acc);
        obase[(size_t)(sl) * HH] = __float2half(acc);
    }
}

// ---------------- fp16 GEMM with ldmatrix fragments ----------------
template <bool AHALF, bool LNA, bool OUTH, bool RELU, bool RES>
__global__ void __launch_bounds__(256, 2)
tgemm(const void* __restrict__ Av, const __half* __restrict__ W,
      const float* __restrict__ bias, const float* res,
      const float* __restrict__ stats, const float* __restrict__ lng,
      const float* __restrict__ lnb,
      void* __restrict__ outv, int Ndim, int Kdim) {
    __shared__ uint32_t Asm[2][128 * 12];
    __shared__ uint32_t Wsm[2][128 * 12];
    int bm = blockIdx.y * 128, bn = blockIdx.x * 128;
    int tid = threadIdx.x;
    int wid = tid >> 5, lane = tid & 31;
    int wm = (wid & 3) * 32, wn = (wid >> 2) * 64;

    float acc[2][8][4];
#pragma unroll
    for (int i = 0; i < 2; i++)
#pragma unroll
        for (int j = 0; j < 8; j++)
#pragma unroll
            for (int q = 0; q < 4; q++) acc[i][j][q] = 0.f;

    // ldmatrix addresses (buffer 0)
    int tr = lane & 7, ts = lane >> 3;
    uint32_t aAddr = sptr(&Asm[0][0]) +
        (((wm + ((ts & 1) << 3) + tr) * 12 + ((ts >> 1) << 2)) << 2);
    uint32_t bAddr[4];
#pragma unroll
    for (int j4 = 0; j4 < 4; j4++)
        bAddr[j4] = sptr(&Wsm[0][0]) +
            (((wn + 8 * (2 * j4 + (ts >> 1)) + tr) * 12 + ((ts & 1) << 2)) << 2);

    // W staging
    int rowW = tid >> 1, grpW = tid & 1;
    const __half* Wp = W + (size_t)(bn + rowW) * Kdim + grpW * 8;
    int soW = rowW * 12 + grpW * 4;

    // A staging
    const __half* Ahp = nullptr;
    const float *Ap0 = nullptr, *Ap1 = nullptr;
    int so0 = 0, so1 = 0, c40 = 0;
    float m0 = 0.f, r0s = 1.f, m1 = 0.f, r1s = 1.f;
    if (AHALF) {
        Ahp = (const __half*)Av + (size_t)(bm + rowW) * Kdim + grpW * 8;
    } else {
        int row0 = tid >> 2;
        c40 = (tid & 3) << 2;
        int row1 = row0 + 64;
        Ap0 = (const float*)Av + (size_t)(bm + row0) * Kdim + c40;
        Ap1 = (const float*)Av + (size_t)(bm + row1) * Kdim + c40;
        so0 = row0 * 12 + (c40 >> 1);
        so1 = row1 * 12 + (c40 >> 1);
        if (LNA) {
            float2 st0 = *(const float2*)(stats + (size_t)(bm + row0) * 2);
            float2 st1 = *(const float2*)(stats + (size_t)(bm + row1) * 2);
            m0 = st0.x; r0s = st0.y; m1 = st1.x; r1s = st1.y;
        }
    }

    uint4 rw = *(const uint4*)Wp;
    uint4 rah;
    float4 a0, a1, g4, b4;
    if (AHALF) {
        rah = *(const uint4*)Ahp;
    } else {
        a0 = *(const float4*)Ap0;
        a1 = *(const float4*)Ap1;
        if (LNA) {
            g4 = *(const float4*)(lng + c40);
            b4 = *(const float4*)(lnb + c40);
        }
    }

    int buf = 0;
    int nk = Kdim >> 4;
    for (int s = 1;; s++) {
        *(uint4*)&Wsm[buf][soW] = rw;
        if (AHALF) {
            *(uint4*)&Asm[buf][soW] = rah;
        } else {
            float4 ta0 = a0, ta1 = a1;
            if (LNA) {
                ta0.x = (a0.x - m0) * r0s * g4.x + b4.x;
                ta0.y = (a0.y - m0) * r0s * g4.y + b4.y;
                ta0.z = (a0.z - m0) * r0s * g4.z + b4.z;
                ta0.w = (a0.w - m0) * r0s * g4.w + b4.w;
                ta1.x = (a1.x - m1) * r1s * g4.x + b4.x;
                ta1.y = (a1.y - m1) * r1s * g4.y + b4.y;
                ta1.z = (a1.z - m1) * r1s * g4.z + b4.z;
                ta1.w = (a1.w - m1) * r1s * g4.w + b4.w;
            }
            uint2 u;
            u.x = h2(ta0.x, ta0.y); u.y = h2(ta0.z, ta0.w);
            *(uint2*)&Asm[buf][so0] = u;
            u.x = h2(ta1.x, ta1.y); u.y = h2(ta1.z, ta1.w);
            *(uint2*)&Asm[buf][so1] = u;
        }
        __syncthreads();
        bool more = (s < nk);
        if (more) {
            rw = *(const uint4*)(Wp + s * 16);
            if (AHALF) {
                rah = *(const uint4*)(Ahp + s * 16);
            } else {
                a0 = *(const float4*)(Ap0 + s * 16);
                a1 = *(const float4*)(Ap1 + s * 16);
                if (LNA) {
                    g4 = *(const float4*)(lng + s * 16 + c40);
                    b4 = *(const float4*)(lnb + s * 16 + c40);
                }
            }
        }
        {
            uint32_t bo = buf ? 6144u : 0u;
            uint32_t af[2][4], bf[8][2];
            LDSMX4(af[0][0], af[0][1], af[0][2], af[0][3], aAddr + bo);
            LDSMX4(af[1][0], af[1][1], af[1][2], af[1][3], aAddr + bo + 768u);
#pragma unroll
            for (int j4 = 0; j4 < 4; j4++) {
                LDSMX4(bf[2 * j4][0], bf[2 * j4][1],
                       bf[2 * j4 + 1][0], bf[2 * j4 + 1][1], bAddr[j4] + bo);
            }
#pragma unroll
            for (int i = 0; i < 2; i++)
#pragma unroll
                for (int j = 0; j < 8; j++)
                    MMA_F16(acc[i][j], af[i], bf[j]);
        }
        if (!more) break;
        buf ^= 1;
    }

    int r = lane >> 2, c = lane & 3;
#pragma unroll
    for (int i = 0; i < 2; i++) {
        int m0i = bm + wm + i * 16 + r;
#pragma unroll
        for (int j = 0; j < 8; j++) {
            int n0 = bn + wn + j * 8 + 2 * c;
            float2 b2 = *(const float2*)(bias + n0);
            float v0 = acc[i][j][0] + b2.x;
            float v1 = acc[i][j][1] + b2.y;
            float v2 = acc[i][j][2] + b2.x;
            float v3 = acc[i][j][3] + b2.y;
            if (RELU) {
                v0 = fmaxf(v0, 0.f); v1 = fmaxf(v1, 0.f);
                v2 = fmaxf(v2, 0.f); v3 = fmaxf(v3, 0.f);
            }
            if (RES) {
                float2 r0v = *(const float2*)(res + (size_t)m0i * Ndim + n0);
                float2 r1v = *(const float2*)(res + (size_t)(m0i + 8) * Ndim + n0);
                v0 += r0v.x; v1 += r0v.y; v2 += r1v.x; v3 += r1v.y;
            }
            if (OUTH) {
                __half* oh = (__half*)outv;
                *(uint32_t*)(oh + (size_t)m0i * Ndim + n0) = h2(v0, v1);
                *(uint32_t*)(oh + (size_t)(m0i + 8) * Ndim + n0) = h2(v2, v3);
            } else {
                float* of = (float*)outv;
                float2 o0 = {v0, v1}, o1 = {v2, v3};
                *(float2*)(of + (size_t)m0i * Ndim + n0) = o0;
                *(float2*)(of + (size_t)(m0i + 8) * Ndim + n0) = o1;
            }
        }
    }
}

// ---------------- attention ----------------
#define TQ    32
#define QSTP  36
#define KSTP  36
#define KST   72
#define SCST  516
#define EBST  72
#define RDST  40

__global__ void __launch_bounds__(256)
attn_kernel(const __half* __restrict__ QKV, const float* __restrict__ EK,
            const float* __restrict__ EV, __half* __restrict__ O) {
    int qt = blockIdx.x, h = blockIdx.y, b = blockIdx.z;
    int q0 = qt * TQ;
    extern __shared__ float sm[];
    uint32_t* qsu = (uint32_t*)sm;            // 32*36
    float* sc   = sm + 1152;                  // 32*516
    float* kt   = sc + 16512;                 // 256*72 f32 (PV) / 256*36 words (QK)
    uint32_t* ktu = (uint32_t*)kt;
    uint32_t* ebku = (uint32_t*)(kt + 18432); // 40*36
    float* ebv  = kt + 18432 + 1440;          // 40*72
    float* rdot = ebv + 2880;
    float* wsum = rdot + 1280;
    float* rsum = wsum + 1280;

    int tid = threadIdx.x;
    int w = tid >> 5, lane = tid & 31;
    int r = lane >> 2, c = lane & 3;
    int tr = lane & 7, ts = lane >> 3;

    size_t bh_in  = ((size_t)b * SS) * RS3 + h * DK;
    size_t bh_out = ((size_t)b * SS) * HH  + h * DK;

    // ---- stage Q pairs ----
#pragma unroll
    for (int i = 0; i < 2; i++) {
        int f = tid + (i << 8);
        int row = f >> 4, c4 = (f & 15) << 2;
        uint2 v = *(const uint2*)(QKV + bh_in + (size_t)(q0 + row) * RS3 + c4);
        uint32_t* d = qsu + row * QSTP + (c4 >> 1);
        d[0] = v.x; d[1] = v.y;
    }
    // ---- stage embed_k (half pairs) / embed_v (raw f32) ----
    for (int f = tid; f < 40 * 16; f += 256) {
        int row = f >> 4, c4 = (f & 15) << 2;
        float4 vk = {0.f, 0.f, 0.f, 0.f}, vv = {0.f, 0.f, 0.f, 0.f};
        if (row < NV) {
            vk = *(const float4*)(EK + row * DK + c4);
            vv = *(const float4*)(EV + row * DK + c4);
        }
        uint32_t* dk = ebku + row * QSTP + (c4 >> 1);
        dk[0] = h2(vk.x, vk.y); dk[1] = h2(vk.z, vk.w);
        *(float4*)(ebv + row * EBST + c4) = vv;
    }
    for (int f = tid; f < 32 * RDST; f += 256) wsum[f] = 0.f;
    __syncthreads();

    // ---- rdot = Q · embed_k^T (fp16, warps 0..4) ----
    if (w < 5) {
        float acc[2][4] = {{0.f, 0.f, 0.f, 0.f}, {0.f, 0.f, 0.f, 0.f}};
#pragma unroll
        for (int ks = 0; ks < 4; ks++) {
            uint32_t a[2][4], bf[2];
#pragma unroll
            for (int i = 0; i < 2; i++) {
                const uint32_t* p = qsu + (i * 16 + r) * QSTP + ks * 8 + c;
                a[i][0] = p[0]; a[i][1] = p[8 * QSTP];
                a[i][2] = p[4]; a[i][3] = p[8 * QSTP + 4];
            }
            const uint32_t* pb = ebku + (w * 8 + r) * QSTP + ks * 8 + c;
            bf[0] = pb[0]; bf[1] = pb[4];
            MMA_F16(acc[0], a[0], bf);
            MMA_F16(acc[1], a[1], bf);
        }
#pragma unroll
        for (int i = 0; i < 2; i++) {
            int row = i * 16 + r;
            rdot[row * RDST + w * 8 + 2 * c]           = acc[i][0];
            rdot[row * RDST + w * 8 + 2 * c + 1]       = acc[i][1];
            rdot[(row + 8) * RDST + w * 8 + 2 * c]     = acc[i][2];
            rdot[(row + 8) * RDST + w * 8 + 2 * c + 1] = acc[i][3];
        }
    }
    __syncthreads();

    // ldmatrix address bases for QK
    uint32_t qAddr = sptr(qsu) +
        (((((ts & 1) << 3) + tr) * QSTP + ((ts >> 1) << 2)) << 2);
    uint32_t kAddr0 = sptr(ktu) +
        (((w * 32 + 8 * (ts >> 1) + tr) * KSTP + ((ts & 1) << 2)) << 2);
    uint32_t kAddr1 = kAddr0 + ((16 * KSTP) << 2);

    // ---- QK (fp16 + ldmatrix): warp w owns keys [w*32, +32) of 256-tile ----
    for (int kt0 = 0; kt0 < SS; kt0 += 256) {
#pragma unroll
        for (int i = 0; i < 16; i++) {
            int f = tid + (i << 8);
            int rr = f >> 4, c4 = (f & 15) << 2;
            uint2 v = *(const uint2*)(QKV + bh_in + HH + (size_t)(kt0 + rr) * RS3 + c4);
            uint32_t* d = ktu + rr * KSTP + (c4 >> 1);
            d[0] = v.x; d[1] = v.y;
        }
        __syncthreads();
        float acc[2][4][4];
#pragma unroll
        for (int i = 0; i < 2; i++)
#pragma unroll
            for (int j = 0; j < 4; j++)
#pragma unroll
                for (int q = 0; q < 4; q++) acc[i][j][q] = 0.f;
#pragma unroll
        for (int ks = 0; ks < 4; ks++) {
            uint32_t kso = ks * 32;
            uint32_t a[2][4], bf[4][2];
            LDSMX4(a[0][0], a[0][1], a[0][2], a[0][3], qAddr + kso);
            LDSMX4(a[1][0], a[1][1], a[1][2], a[1][3],
                   qAddr + ((16 * QSTP) << 2) + kso);
            LDSMX4(bf[0][0], bf[0][1], bf[1][0], bf[1][1], kAddr0 + kso);
            LDSMX4(bf[2][0], bf[2][1], bf[3][0], bf[3][1], kAddr1 + kso);
#pragma unroll
            for (int jn = 0; jn < 4; jn++) {
                MMA_F16(acc[0][jn], a[0], bf[jn]);
                MMA_F16(acc[1][jn], a[1], bf[jn]);
            }
        }
#pragma unroll
        for (int i = 0; i < 2; i++) {
#pragma unroll
            for (int jn = 0; jn < 4; jn++) {
                int colb = kt0 + w * 32 + jn * 8 + 2 * c;
#pragma unroll
                for (int cc = 0; cc < 4; cc++) {
                    int row = i * 16 + r + ((cc >> 1) << 3);
                    int key = colb + (cc & 1);
                    int qg = q0 + row;
                    int dd = key - qg;
                    dd = dd < -16 ? -16 : (dd > 16 ? 16 : dd);
                    sc[row * SCST + key] = acc[i][jn][cc] + rdot[row * RDST + dd + 16];
                }
            }
        }
        __syncthreads();
    }

    // ---- softmax + bucket weight sums ----
    {
        for (int rr = w; rr < TQ; rr += 8) {
            float* row = sc + rr * SCST;
            int qg = q0 + rr;
            float mx = -1e30f;
            for (int k = lane; k < SS; k += 32) mx = fmaxf(mx, row[k]);
#pragma unroll
            for (int o = 16; o > 0; o >>= 1)
                mx = fmaxf(mx, __shfl_xor_sync(0xffffffffu, mx, o));
            float sum = 0.f, w0 = 0.f, w32 = 0.f;
            for (int k = lane; k < SS; k += 32) {
                float e = __expf(row[k] - mx);
                row[k] = e;
                sum += e;
                if (k <= qg - 16) w0 += e;
                if (k >= qg + 16) w32 += e;
            }
#pragma unroll
            for (int o = 16; o > 0; o >>= 1) {
                sum += __shfl_xor_sync(0xffffffffu, sum, o);
                w0  += __shfl_xor_sync(0xffffffffu, w0, o);
                w32 += __shfl_xor_sync(0xffffffffu, w32, o);
            }
            __syncwarp();
            if (lane == 0) {
                rsum[rr] = sum;
                wsum[rr * RDST + 0] = w0;
                wsum[rr * RDST + 32] = w32;
            } else {
                int k = qg + lane - 16;
                wsum[rr * RDST + lane] = (k >= 0 && k < SS) ? row[k] : 0.f;
            }
        }
    }
    __syncthreads();

    // ---- PV + rel_v (tf32, raw fp32 bits): warp w owns d-slice [w*8, +8) ----
    {
        float acc[2][4];
#pragma unroll
        for (int i = 0; i < 2; i++)
#pragma unroll
            for (int q = 0; q < 4; q++) acc[i][q] = 0.f;

#pragma unroll
        for (int ks = 0; ks < 5; ks++) {
            uint32_t a[2][4], bf[2];
#pragma unroll
            for (int i = 0; i < 2; i++) {
                int base = (i * 16 + r) * RDST + ks * 8 + c;
                a[i][0] = U(wsum[base]);
                a[i][1] = U(wsum[base + 8 * RDST]);
                a[i][2] = U(wsum[base + 4]);
                a[i][3] = U(wsum[base + 8 * RDST + 4]);
            }
            int pb = (ks * 8 + c) * EBST + w * 8 + r;
            bf[0] = U(ebv[pb]); bf[1] = U(ebv[pb + 4 * EBST]);
            MMA_TF32(acc[0], a[0], bf);
            MMA_TF32(acc[1], a[1], bf);
        }

        for (int kt0 = 0; kt0 < SS; kt0 += 256) {
#pragma unroll
            for (int i = 0; i < 16; i++) {
                int f = tid + (i << 8);
                int rr = f >> 4, c4 = (f & 15) << 2;
                uint2 v = *(const uint2*)(QKV + bh_in + 2 * HH +
                                          (size_t)(kt0 + rr) * RS3 + c4);
                __half2 p0 = *(__half2*)&v.x;
                __half2 p1 = *(__half2*)&v.y;
                float* d = kt + rr * KST + c4;
                d[0] = __low2float(p0); d[1] = __high2float(p0);
                d[2] = __low2float(p1); d[3] = __high2float(p1);
            }
            __syncthreads();
#pragma unroll 8
            for (int ks = 0; ks < 32; ks++) {
                int kb = ks * 8;
                uint32_t a[2][4], bf[2];
#pragma unroll
                for (int i = 0; i < 2; i++) {
                    const float* p = sc + (i * 16 + r) * SCST + kt0 + kb + c;
                    a[i][0] = U(p[0]);
                    a[i][1] = U(p[8 * SCST]);
                    a[i][2] = U(p[4]);
                    a[i][3] = U(p[8 * SCST + 4]);
                }
                int pb = (kb + c) * KST + w * 8 + r;
                bf[0] = U(kt[pb]); bf[1] = U(kt[pb + 4 * KST]);
                MMA_TF32(acc[0], a[0], bf);
                MMA_TF32(acc[1], a[1], bf);
            }
            __syncthreads();
        }

#pragma unroll
        for (int i = 0; i < 2; i++) {
            int row0 = i * 16 + r, row1 = row0 + 8;
            float inv0 = 1.f / rsum[row0];
            float inv1 = 1.f / rsum[row1];
            int col = w * 8 + 2 * c;
            *(uint32_t*)(O + bh_out + (size_t)(q0 + row0) * HH + col) =
                h2(acc[i][0] * inv0, acc[i][1] * inv0);
            *(uint32_t*)(O + bh_out + (size_t)(q0 + row1) * HH + col) =
                h2(acc[i][2] * inv1, acc[i][3] * inv1);
        }
    }
}

// ---------------- launcher ----------------
extern "C" void kernel_launch(void* const* d_in, const int* in_sizes, int n_in,
                              void* d_out, int out_size) {
    const float* x    = (const float*)d_in[0];
    const int*   mask = (const int*)d_in[1];
    const float* dw_w = (const float*)d_in[2];
    const float* dw_b = (const float*)d_in[3];
    const float* pw_w = (const float*)d_in[4];
    const float* pw_b = (const float*)d_in[5];
    const float* lcg  = (const float*)d_in[6];
    const float* lcb  = (const float*)d_in[7];
    const float* wq   = (const float*)d_in[8];
    const float* bq   = (const float*)d_in[9];
    const float* wk   = (const float*)d_in[10];
    const float* bk   = (const float*)d_in[11];
    const float* wv   = (const float*)d_in[12];
    const float* bv   = (const float*)d_in[13];
    const float* wo   = (const float*)d_in[14];
    const float* bo   = (const float*)d_in[15];
    const float* ek   = (const float*)d_in[16];
    const float* ev   = (const float*)d_in[17];
    const float* lag  = (const float*)d_in[18];
    const float* lab  = (const float*)d_in[19];
    const float* wff  = (const float*)d_in[20];
    const float* bff  = (const float*)d_in[21];
    const float* lfg  = (const float*)d_in[22];
    const float* lfb  = (const float*)d_in[23];
    float* xo = (float*)d_out;

    float *phf, *pqkv, *pbqkv, *ppe, *pst;
    __half* pwh;
    cudaGetSymbolAddress((void**)&phf, g_h);
    cudaGetSymbolAddress((void**)&pqkv, g_qkv);
    cudaGetSymbolAddress((void**)&pwh, g_wh);
    cudaGetSymbolAddress((void**)&pbqkv, g_bqkv);
    cudaGetSymbolAddress((void**)&ppe, g_pe);
    cudaGetSymbolAddress((void**)&pst, g_stats);

    __half* ph_h   = (__half*)phf;
    __half* pqkv_h = (__half*)pqkv;
    float*  px     = pqkv + (size_t)ROWS * RS3 / 2;

    cudaMemcpyAsync(pbqkv,          bq, HH * 4, cudaMemcpyDeviceToDevice);
    cudaMemcpyAsync(pbqkv + HH,     bk, HH * 4, cudaMemcpyDeviceToDevice);
    cudaMemcpyAsync(pbqkv + 2 * HH, bv, HH * 4, cudaMemcpyDeviceToDevice);

    const int ATTN_SMEM = (1152 + 16512 + 18432 + 1440 + 2880 + 1280 + 1280 + 32) * 4;
    cudaFuncSetAttribute((const void*)attn_kernel,
                         cudaFuncAttributeMaxDynamicSharedMemorySize, ATTN_SMEM);

    dim3 gemm_grid(HH / 128, ROWS / 128);
    dim3 qkv_grid(RS3 / 128, ROWS / 128);
    dim3 dw_grid(8, 4, 32);

    wconv_kernel<<<dim3(HH * HH / 256, 7), 256>>>(pw_w, wq, wk, wv, wo, wff, pwh);
    pe_kernel<<<(SS * HH) / 256, 256>>>(ppe);
    pos_add_kernel<<<TOT / 256, 256>>>(x, mask, ppe, xo);

    for (int i = 0; i < 2; i++) {
        ln_stats<<<ROWS / 8, 256>>>(xo, pst);
        dwconv_kernel<<<dw_grid, 256>>>(xo, pst, lcg + i * HH, lcb + i * HH,
                                        dw_w + i * HH * KW, dw_b + i * HH, ph_h);
        tgemm<true, false, false, true, true><<<gemm_grid, 256>>>(
            ph_h, pwh + (size_t)i * HH * HH, pw_b + i * HH, xo,
            nullptr, nullptr, nullptr, xo, HH, HH);
    }

    ln_stats<<<ROWS / 8, 256>>>(xo, pst);
    tgemm<false, true, true, false, false><<<qkv_grid, 256>>>(
        xo, pwh + (size_t)2 * HH * HH, pbqkv, nullptr,
        pst, lag, lab, pqkv_h, RS3, HH);

    attn_kernel<<<dim3(SS / TQ, NHD, BB), 256, ATTN_SMEM>>>(pqkv_h, ek, ev, ph_h);

    tgemm<true, false, false, false, true><<<gemm_grid, 256>>>(
        ph_h, pwh + (size_t)5 * HH * HH, bo, xo,
        nullptr, nullptr, nullptr, px, HH, HH);

    ln_stats<<<ROWS / 8, 256>>>(px, pst);
    tgemm<false, true, false, true, true><<<gemm_grid, 256>>>(
        px, pwh + (size_t)6 * HH * HH, bff, px,
        pst, lfg, lfb, xo, HH, HH);
}

// round 13
// speedup vs baseline: 3.2779x; 1.0228x over previous
#include <cuda_runtime.h>
#include <cuda_fp16.h>
#include <math.h>
#include <stdint.h>

// ---------------- problem constants ----------------
#define BB   32
#define SS   512
#define HH   512
#define NHD  8
#define DK   64
#define KW   7
#define NV   33
#define RS3  (3*HH)
#define ROWS (BB*SS)
#define TOT  (BB*SS*HH)

// ---------------- scratch ----------------
__device__ float  g_h[TOT];
__device__ float  g_qkv[ROWS * RS3];     // lower half: half QKV; upper: fp32 x'
__device__ __half g_wh[7 * HH * HH];
__device__ float  g_bqkv[3 * HH];
__device__ float  g_pe[SS * HH];
__device__ float  g_stats[ROWS * 2];

// ---------------- helpers ----------------
__device__ __forceinline__ uint32_t h2(float x, float y) {
    __half2 h = __floats2half2_rn(x, y);
    return *reinterpret_cast<uint32_t*>(&h);
}
__device__ __forceinline__ uint32_t sptr(const void* p) {
    return (uint32_t)__cvta_generic_to_shared(p);
}
#define U(x) __float_as_uint(x)

#define MMA_TF32(d, a, b)                                                     \
    asm volatile("mma.sync.aligned.m16n8k8.row.col.f32.tf32.tf32.f32 "       \
                 "{%0,%1,%2,%3}, {%4,%5,%6,%7}, {%8,%9}, {%0,%1,%2,%3};"     \
                 : "+f"(d[0]), "+f"(d[1]), "+f"(d[2]), "+f"(d[3])            \
                 : "r"(a[0]), "r"(a[1]), "r"(a[2]), "r"(a[3]),               \
                   "r"(b[0]), "r"(b[1]))

#define MMA_F16(d, a, b)                                                      \
    asm volatile("mma.sync.aligned.m16n8k16.row.col.f32.f16.f16.f32 "        \
                 "{%0,%1,%2,%3}, {%4,%5,%6,%7}, {%8,%9}, {%0,%1,%2,%3};"     \
                 : "+f"(d[0]), "+f"(d[1]), "+f"(d[2]), "+f"(d[3])            \
                 : "r"(a[0]), "r"(a[1]), "r"(a[2]), "r"(a[3]),               \
                   "r"(b[0]), "r"(b[1]))

#define LDSMX4(r0, r1, r2, r3, addr)                                          \
    asm volatile("ldmatrix.sync.aligned.m8n8.x4.shared.b16 {%0,%1,%2,%3}, [%4];" \
                 : "=r"(r0), "=r"(r1), "=r"(r2), "=r"(r3) : "r"(addr))

#define LDSMX2T(r0, r1, addr)                                                 \
    asm volatile("ldmatrix.sync.aligned.m8n8.x2.trans.shared.b16 {%0,%1}, [%2];" \
                 : "=r"(r0), "=r"(r1) : "r"(addr))

// ---------------- weight convert ----------------
__global__ void wconv_kernel(const float* __restrict__ pw,
                             const float* __restrict__ wq,
                             const float* __restrict__ wk,
                             const float* __restrict__ wv,
                             const float* __restrict__ wo,
                             const float* __restrict__ wff,
                             __half* __restrict__ out) {
    int m = blockIdx.y;
    int idx = blockIdx.x * 256 + threadIdx.x;
    const float* src;
    switch (m) {
        case 0: src = pw; break;
        case 1: src = pw + HH * HH; break;
        case 2: src = wq; break;
        case 3: src = wk; break;
        case 4: src = wv; break;
        case 5: src = wo; break;
        default: src = wff; break;
    }
    out[(size_t)m * HH * HH + idx] = __float2half(src[idx]);
}

// ---------------- positional encoding ----------------
__global__ void pe_kernel(float* __restrict__ pe) {
    int idx = blockIdx.x * 256 + threadIdx.x;
    int h = idx & (HH - 1);
    int s = idx >> 9;
    float v = 0.f;
    if (s > 0) {
        float pos = (float)(s - 1);
        int i2 = h & ~1;
        float div = expf((float)i2 * (-9.210340371976184f / (float)HH));
        float ang = pos * div;
        v = (h & 1) ? cosf(ang) : sinf(ang);
    }
    pe[idx] = v;
}

__global__ void pos_add_kernel(const float* __restrict__ x,
                               const int* __restrict__ mask,
                               const float* __restrict__ pe,
                               float* __restrict__ out) {
    int idx = blockIdx.x * 256 + threadIdx.x;
    int s = (idx >> 9) & (SS - 1);
    int b = idx >> 18;
    out[idx] = x[idx] + pe[idx & (SS * HH - 1)] * (float)mask[(b << 9) + s];
}

// ---------------- LN stats ----------------
__global__ void ln_stats(const float* __restrict__ x, float* __restrict__ stats) {
    int row = blockIdx.x * 8 + (threadIdx.x >> 5);
    int lane = threadIdx.x & 31;
    const float4* xr = (const float4*)(x + (size_t)row * HH);
    float s = 0.f, sq = 0.f;
#pragma unroll
    for (int i = 0; i < 4; i++) {
        float4 v = xr[lane + i * 32];
        s += v.x + v.y + v.z + v.w;
        sq += v.x * v.x + v.y * v.y + v.z * v.z + v.w * v.w;
    }
#pragma unroll
    for (int o = 16; o > 0; o >>= 1) {
        s  += __shfl_xor_sync(0xffffffffu, s, o);
        sq += __shfl_xor_sync(0xffffffffu, sq, o);
    }
    if (lane == 0) {
        float mean = s * (1.f / HH);
        float var = sq * (1.f / HH) - mean * mean;
        stats[row * 2] = mean;
        stats[row * 2 + 1] = rsqrtf(var + 1e-5f);
    }
}

// ---------------- depthwise conv (fused LN, sliding-window regs, half out) ----------------
__global__ void dwconv_kernel(const float* __restrict__ x,
                              const float* __restrict__ stats,
                              const float* __restrict__ lg,
                              const float* __restrict__ lb,
                              const float* __restrict__ w,
                              const float* __restrict__ bias,
                              __half* __restrict__ out) {
    __shared__ float sb[70][128];
    __shared__ float2 sstat[70];
    __shared__ float lgs[128], lbs[128];
    int s0 = blockIdx.x * 64, c0 = blockIdx.y * 128, b = blockIdx.z;
    int tid = threadIdx.x;
    if (tid < 128) { lgs[tid] = lg[c0 + tid]; lbs[tid] = lb[c0 + tid]; }
    else if (tid < 198) {
        int sp = s0 + (tid - 128) - 3;
        float2 st = {0.f, 0.f};
        if (sp >= 0 && sp < SS) st = *(const float2*)(stats + ((size_t)b * SS + sp) * 2);
        sstat[tid - 128] = st;
    }
    __syncthreads();
    const float* base = x + ((size_t)b * SS) * HH + c0;
#pragma unroll 3
    for (int i = tid; i < 70 * 32; i += 256) {
        int r = i >> 5, c4 = (i & 31) << 2;
        int sp = s0 + r - 3;
        float4 v = {0.f, 0.f, 0.f, 0.f};
        if (sp >= 0 && sp < SS) {
            v = *(const float4*)(base + (size_t)sp * HH + c4);
            float2 st = sstat[r];
            v.x = (v.x - st.x) * st.y * lgs[c4]     + lbs[c4];
            v.y = (v.y - st.x) * st.y * lgs[c4 + 1] + lbs[c4 + 1];
            v.z = (v.z - st.x) * st.y * lgs[c4 + 2] + lbs[c4 + 2];
            v.w = (v.w - st.x) * st.y * lgs[c4 + 3] + lbs[c4 + 3];
        }
        *(float4*)(&sb[r][c4]) = v;
    }
    __syncthreads();
    int c = tid & 127;
    int rr0 = (tid >> 7) * 32;
    float wr[KW];
#pragma unroll
    for (int t = 0; t < KW; t++) wr[t] = w[(c0 + c) * KW + t];
    float bz = bias[c0 + c];
    __half* obase = out + ((size_t)b * SS + s0) * HH + c0 + c;
    // sliding window of 7 rows in registers: 1 new LDS per output row
    float win[KW];
#pragma unroll
    for (int t = 0; t < KW; t++) win[t] = sb[rr0 + t][c];
#pragma unroll
    for (int r = 0; r < 32; r++) {
        float acc = bz;
#pragma unroll
        for (int t = 0; t < KW; t++) acc = fmaf(win[t], wr[t], acc);
        obase[(size_t)(rr0 + r) * HH] = __float2half(acc);
#pragma unroll
        for (int t = 0; t < KW - 1; t++) win[t] = win[t + 1];
        if (r < 31) win[KW - 1] = sb[rr0 + r + KW][c];
    }
}

// ---------------- fp16 GEMM with ldmatrix fragments (unchanged R12) ----------------
template <bool AHALF, bool LNA, bool OUTH, bool RELU, bool RES>
__global__ void __launch_bounds__(256, 2)
tgemm(const void* __restrict__ Av, const __half* __restrict__ W,
      const float* __restrict__ bias, const float* res,
      const float* __restrict__ stats, const float* __restrict__ lng,
      const float* __restrict__ lnb,
      void* __restrict__ outv, int Ndim, int Kdim) {
    __shared__ uint32_t Asm[2][128 * 12];
    __shared__ uint32_t Wsm[2][128 * 12];
    int bm = blockIdx.y * 128, bn = blockIdx.x * 128;
    int tid = threadIdx.x;
    int wid = tid >> 5, lane = tid & 31;
    int wm = (wid & 3) * 32, wn = (wid >> 2) * 64;

    float acc[2][8][4];
#pragma unroll
    for (int i = 0; i < 2; i++)
#pragma unroll
        for (int j = 0; j < 8; j++)
#pragma unroll
            for (int q = 0; q < 4; q++) acc[i][j][q] = 0.f;

    int tr = lane & 7, ts = lane >> 3;
    uint32_t aAddr = sptr(&Asm[0][0]) +
        (((wm + ((ts & 1) << 3) + tr) * 12 + ((ts >> 1) << 2)) << 2);
    uint32_t bAddr[4];
#pragma unroll
    for (int j4 = 0; j4 < 4; j4++)
        bAddr[j4] = sptr(&Wsm[0][0]) +
            (((wn + 8 * (2 * j4 + (ts >> 1)) + tr) * 12 + ((ts & 1) << 2)) << 2);

    int rowW = tid >> 1, grpW = tid & 1;
    const __half* Wp = W + (size_t)(bn + rowW) * Kdim + grpW * 8;
    int soW = rowW * 12 + grpW * 4;

    const __half* Ahp = nullptr;
    const float *Ap0 = nullptr, *Ap1 = nullptr;
    int so0 = 0, so1 = 0, c40 = 0;
    float m0 = 0.f, r0s = 1.f, m1 = 0.f, r1s = 1.f;
    if (AHALF) {
        Ahp = (const __half*)Av + (size_t)(bm + rowW) * Kdim + grpW * 8;
    } else {
        int row0 = tid >> 2;
        c40 = (tid & 3) << 2;
        int row1 = row0 + 64;
        Ap0 = (const float*)Av + (size_t)(bm + row0) * Kdim + c40;
        Ap1 = (const float*)Av + (size_t)(bm + row1) * Kdim + c40;
        so0 = row0 * 12 + (c40 >> 1);
        so1 = row1 * 12 + (c40 >> 1);
        if (LNA) {
            float2 st0 = *(const float2*)(stats + (size_t)(bm + row0) * 2);
            float2 st1 = *(const float2*)(stats + (size_t)(bm + row1) * 2);
            m0 = st0.x; r0s = st0.y; m1 = st1.x; r1s = st1.y;
        }
    }

    uint4 rw = *(const uint4*)Wp;
    uint4 rah;
    float4 a0, a1, g4, b4;
    if (AHALF) {
        rah = *(const uint4*)Ahp;
    } else {
        a0 = *(const float4*)Ap0;
        a1 = *(const float4*)Ap1;
        if (LNA) {
            g4 = *(const float4*)(lng + c40);
            b4 = *(const float4*)(lnb + c40);
        }
    }

    int buf = 0;
    int nk = Kdim >> 4;
    for (int s = 1;; s++) {
        *(uint4*)&Wsm[buf][soW] = rw;
        if (AHALF) {
            *(uint4*)&Asm[buf][soW] = rah;
        } else {
            float4 ta0 = a0, ta1 = a1;
            if (LNA) {
                ta0.x = (a0.x - m0) * r0s * g4.x + b4.x;
                ta0.y = (a0.y - m0) * r0s * g4.y + b4.y;
                ta0.z = (a0.z - m0) * r0s * g4.z + b4.z;
                ta0.w = (a0.w - m0) * r0s * g4.w + b4.w;
                ta1.x = (a1.x - m1) * r1s * g4.x + b4.x;
                ta1.y = (a1.y - m1) * r1s * g4.y + b4.y;
                ta1.z = (a1.z - m1) * r1s * g4.z + b4.z;
                ta1.w = (a1.w - m1) * r1s * g4.w + b4.w;
            }
            uint2 u;
            u.x = h2(ta0.x, ta0.y); u.y = h2(ta0.z, ta0.w);
            *(uint2*)&Asm[buf][so0] = u;
            u.x = h2(ta1.x, ta1.y); u.y = h2(ta1.z, ta1.w);
            *(uint2*)&Asm[buf][so1] = u;
        }
        __syncthreads();
        bool more = (s < nk);
        if (more) {
            rw = *(const uint4*)(Wp + s * 16);
            if (AHALF) {
                rah = *(const uint4*)(Ahp + s * 16);
            } else {
                a0 = *(const float4*)(Ap0 + s * 16);
                a1 = *(const float4*)(Ap1 + s * 16);
                if (LNA) {
                    g4 = *(const float4*)(lng + s * 16 + c40);
                    b4 = *(const float4*)(lnb + s * 16 + c40);
                }
            }
        }
        {
            uint32_t bo = buf ? 6144u : 0u;
            uint32_t af[2][4], bf[8][2];
            LDSMX4(af[0][0], af[0][1], af[0][2], af[0][3], aAddr + bo);
            LDSMX4(af[1][0], af[1][1], af[1][2], af[1][3], aAddr + bo + 768u);
#pragma unroll
            for (int j4 = 0; j4 < 4; j4++) {
                LDSMX4(bf[2 * j4][0], bf[2 * j4][1],
                       bf[2 * j4 + 1][0], bf[2 * j4 + 1][1], bAddr[j4] + bo);
            }
#pragma unroll
            for (int i = 0; i < 2; i++)
#pragma unroll
                for (int j = 0; j < 8; j++)
                    MMA_F16(acc[i][j], af[i], bf[j]);
        }
        if (!more) break;
        buf ^= 1;
    }

    int r = lane >> 2, c = lane & 3;
#pragma unroll
    for (int i = 0; i < 2; i++) {
        int m0i = bm + wm + i * 16 + r;
#pragma unroll
        for (int j = 0; j < 8; j++) {
            int n0 = bn + wn + j * 8 + 2 * c;
            float2 b2 = *(const float2*)(bias + n0);
            float v0 = acc[i][j][0] + b2.x;
            float v1 = acc[i][j][1] + b2.y;
            float v2 = acc[i][j][2] + b2.x;
            float v3 = acc[i][j][3] + b2.y;
            if (RELU) {
                v0 = fmaxf(v0, 0.f); v1 = fmaxf(v1, 0.f);
                v2 = fmaxf(v2, 0.f); v3 = fmaxf(v3, 0.f);
            }
            if (RES) {
                float2 r0v = *(const float2*)(res + (size_t)m0i * Ndim + n0);
                float2 r1v = *(const float2*)(res + (size_t)(m0i + 8) * Ndim + n0);
                v0 += r0v.x; v1 += r0v.y; v2 += r1v.x; v3 += r1v.y;
            }
            if (OUTH) {
                __half* oh = (__half*)outv;
                *(uint32_t*)(oh + (size_t)m0i * Ndim + n0) = h2(v0, v1);
                *(uint32_t*)(oh + (size_t)(m0i + 8) * Ndim + n0) = h2(v2, v3);
            } else {
                float* of = (float*)outv;
                float2 o0 = {v0, v1}, o1 = {v2, v3};
                *(float2*)(of + (size_t)m0i * Ndim + n0) = o0;
                *(float2*)(of + (size_t)(m0i + 8) * Ndim + n0) = o1;
            }
        }
    }
}

// ---------------- attention: fp16 QK + fp16 PV (half prob buffer) ----------------
#define TQ    32
#define QSTP  36
#define KSTP  36
#define SCST  516
#define SCHP  520     // half stride of prob buffer
#define EBST  72
#define RDST  40

__global__ void __launch_bounds__(256)
attn_kernel(const __half* __restrict__ QKV, const float* __restrict__ EK,
            const float* __restrict__ EV, __half* __restrict__ O) {
    int qt = blockIdx.x, h = blockIdx.y, b = blockIdx.z;
    int q0 = qt * TQ;
    extern __shared__ float sm[];
    uint32_t* qsu  = (uint32_t*)sm;             // 1152 words
    float*    sc   = sm + 1152;                 // 16512 (fp32 scores)
    uint32_t* ktu  = (uint32_t*)(sm + 17664);   // 9216 (K/V half pairs)
    __half*   sch  = (__half*)(sm + 26880);     // 8320 words (half probs)
    uint32_t* ebku = (uint32_t*)(sm + 35200);   // 1440
    float*    ebv  = sm + 36640;                // 2880 (f32, rel_v)
    float*    rdot = sm + 39520;                // 1280
    float*    wsum = sm + 40800;                // 1280
    float*    rsum = sm + 42080;                // 32

    int tid = threadIdx.x;
    int w = tid >> 5, lane = tid & 31;
    int r = lane >> 2, c = lane & 3;
    int tr = lane & 7, ts = lane >> 3;

    size_t bh_in  = ((size_t)b * SS) * RS3 + h * DK;
    size_t bh_out = ((size_t)b * SS) * HH  + h * DK;

    // ---- stage Q pairs ----
#pragma unroll
    for (int i = 0; i < 2; i++) {
        int f = tid + (i << 8);
        int row = f >> 4, c4 = (f & 15) << 2;
        uint2 v = *(const uint2*)(QKV + bh_in + (size_t)(q0 + row) * RS3 + c4);
        uint32_t* d = qsu + row * QSTP + (c4 >> 1);
        d[0] = v.x; d[1] = v.y;
    }
    // ---- stage embed_k (half pairs) / embed_v (raw f32) ----
    for (int f = tid; f < 40 * 16; f += 256) {
        int row = f >> 4, c4 = (f & 15) << 2;
        float4 vk = {0.f, 0.f, 0.f, 0.f}, vv = {0.f, 0.f, 0.f, 0.f};
        if (row < NV) {
            vk = *(const float4*)(EK + row * DK + c4);
            vv = *(const float4*)(EV + row * DK + c4);
        }
        uint32_t* dk = ebku + row * QSTP + (c4 >> 1);
        dk[0] = h2(vk.x, vk.y); dk[1] = h2(vk.z, vk.w);
        *(float4*)(ebv + row * EBST + c4) = vv;
    }
    for (int f = tid; f < 32 * RDST; f += 256) wsum[f] = 0.f;
    __syncthreads();

    // ---- rdot = Q · embed_k^T (fp16, warps 0..4) ----
    if (w < 5) {
        float acc[2][4] = {{0.f, 0.f, 0.f, 0.f}, {0.f, 0.f, 0.f, 0.f}};
#pragma unroll
        for (int ks = 0; ks < 4; ks++) {
            uint32_t a[2][4], bf[2];
#pragma unroll
            for (int i = 0; i < 2; i++) {
                const uint32_t* p = qsu + (i * 16 + r) * QSTP + ks * 8 + c;
                a[i][0] = p[0]; a[i][1] = p[8 * QSTP];
                a[i][2] = p[4]; a[i][3] = p[8 * QSTP + 4];
            }
            const uint32_t* pb = ebku + (w * 8 + r) * QSTP + ks * 8 + c;
            bf[0] = pb[0]; bf[1] = pb[4];
            MMA_F16(acc[0], a[0], bf);
            MMA_F16(acc[1], a[1], bf);
        }
#pragma unroll
        for (int i = 0; i < 2; i++) {
            int row = i * 16 + r;
            rdot[row * RDST + w * 8 + 2 * c]           = acc[i][0];
            rdot[row * RDST + w * 8 + 2 * c + 1]       = acc[i][1];
            rdot[(row + 8) * RDST + w * 8 + 2 * c]     = acc[i][2];
            rdot[(row + 8) * RDST + w * 8 + 2 * c + 1] = acc[i][3];
        }
    }
    __syncthreads();

    // ldmatrix bases
    uint32_t qAddr = sptr(qsu) +
        (((((ts & 1) << 3) + tr) * QSTP + ((ts >> 1) << 2)) << 2);
    uint32_t kAddr0 = sptr(ktu) +
        (((w * 32 + 8 * (ts >> 1) + tr) * KSTP + ((ts & 1) << 2)) << 2);
    uint32_t kAddr1 = kAddr0 + ((16 * KSTP) << 2);
    // PV bases: A from sch (probs), B from ktu (V) via trans
    uint32_t pAddr = sptr(sch) +
        ((((ts & 1) << 3) + tr) * SCHP + ((ts >> 1) << 3)) * 2;
    uint32_t vAddr = sptr(ktu) + (((lane & 15) * KSTP + w * 4) << 2);

    // ---- QK (fp16 + ldmatrix): warp w owns keys [w*32, +32) of 256-tile ----
    for (int kt0 = 0; kt0 < SS; kt0 += 256) {
#pragma unroll
        for (int i = 0; i < 16; i++) {
            int f = tid + (i << 8);
            int rr = f >> 4, c4 = (f & 15) << 2;
            uint2 v = *(const uint2*)(QKV + bh_in + HH + (size_t)(kt0 + rr) * RS3 + c4);
            uint32_t* d = ktu + rr * KSTP + (c4 >> 1);
            d[0] = v.x; d[1] = v.y;
        }
        __syncthreads();
        float acc[2][4][4];
#pragma unroll
        for (int i = 0; i < 2; i++)
#pragma unroll
            for (int j = 0; j < 4; j++)
#pragma unroll
                for (int q = 0; q < 4; q++) acc[i][j][q] = 0.f;
#pragma unroll
        for (int ks = 0; ks < 4; ks++) {
            uint32_t kso = ks * 32;
            uint32_t a[2][4], bf[4][2];
            LDSMX4(a[0][0], a[0][1], a[0][2], a[0][3], qAddr + kso);
            LDSMX4(a[1][0], a[1][1], a[1][2], a[1][3],
                   qAddr + ((16 * QSTP) << 2) + kso);
            LDSMX4(bf[0][0], bf[0][1], bf[1][0], bf[1][1], kAddr0 + kso);
            LDSMX4(bf[2][0], bf[2][1], bf[3][0], bf[3][1], kAddr1 + kso);
#pragma unroll
            for (int jn = 0; jn < 4; jn++) {
                MMA_F16(acc[0][jn], a[0], bf[jn]);
                MMA_F16(acc[1][jn], a[1], bf[jn]);
            }
        }
#pragma unroll
        for (int i = 0; i < 2; i++) {
#pragma unroll
            for (int jn = 0; jn < 4; jn++) {
                int colb = kt0 + w * 32 + jn * 8 + 2 * c;
#pragma unroll
                for (int cc = 0; cc < 4; cc++) {
                    int row = i * 16 + r + ((cc >> 1) << 3);
                    int key = colb + (cc & 1);
                    int qg = q0 + row;
                    int dd = key - qg;
                    dd = dd < -16 ? -16 : (dd > 16 ? 16 : dd);
                    sc[row * SCST + key] = acc[i][jn][cc] + rdot[row * RDST + dd + 16];
                }
            }
        }
        __syncthreads();
    }

    // ---- softmax: fp32 sums, half probs into sch ----
    {
        for (int rr = w; rr < TQ; rr += 8) {
            float* row = sc + rr * SCST;
            __half* hrow = sch + rr * SCHP;
            int qg = q0 + rr;
            float mx = -1e30f;
            for (int k = lane; k < SS; k += 32) mx = fmaxf(mx, row[k]);
#pragma unroll
            for (int o = 16; o > 0; o >>= 1)
                mx = fmaxf(mx, __shfl_xor_sync(0xffffffffu, mx, o));
            float sum = 0.f, w0 = 0.f, w32 = 0.f;
            for (int k = lane; k < SS; k += 32) {
                float e = __expf(row[k] - mx);
                hrow[k] = __float2half(e);
                sum += e;
                if (k <= qg - 16) w0 += e;
                if (k >= qg + 16) w32 += e;
            }
#pragma unroll
            for (int o = 16; o > 0; o >>= 1) {
                sum += __shfl_xor_sync(0xffffffffu, sum, o);
                w0  += __shfl_xor_sync(0xffffffffu, w0, o);
                w32 += __shfl_xor_sync(0xffffffffu, w32, o);
            }
            __syncwarp();
            if (lane == 0) {
                rsum[rr] = sum;
                wsum[rr * RDST + 0] = w0;
                wsum[rr * RDST + 32] = w32;
            } else {
                int k = qg + lane - 16;
                wsum[rr * RDST + lane] =
                    (k >= 0 && k < SS) ? __half2float(hrow[k]) : 0.f;
            }
        }
    }
    __syncthreads();

    // ---- PV (fp16) + rel_v (tf32): warp w owns d-slice [w*8, +8) ----
    {
        float acc[2][4];
#pragma unroll
        for (int i = 0; i < 2; i++)
#pragma unroll
            for (int q = 0; q < 4; q++) acc[i][q] = 0.f;

        // rel_v: wsum[32x40] x ebv[40x64] (tf32, raw fp32 bits)
#pragma unroll
        for (int ks = 0; ks < 5; ks++) {
            uint32_t a[2][4], bf[2];
#pragma unroll
            for (int i = 0; i < 2; i++) {
                int base = (i * 16 + r) * RDST + ks * 8 + c;
                a[i][0] = U(wsum[base]);
                a[i][1] = U(wsum[base + 8 * RDST]);
                a[i][2] = U(wsum[base + 4]);
                a[i][3] = U(wsum[base + 8 * RDST + 4]);
            }
            int pb = (ks * 8 + c) * EBST + w * 8 + r;
            bf[0] = U(ebv[pb]); bf[1] = U(ebv[pb + 4 * EBST]);
            MMA_TF32(acc[0], a[0], bf);
            MMA_TF32(acc[1], a[1], bf);
        }

        for (int kt0 = 0; kt0 < SS; kt0 += 256) {
            // stage V raw half pairs
#pragma unroll
            for (int i = 0; i < 16; i++) {
                int f = tid + (i << 8);
                int rr = f >> 4, c4 = (f & 15) << 2;
                uint2 v = *(const uint2*)(QKV + bh_in + 2 * HH +
                                          (size_t)(kt0 + rr) * RS3 + c4);
                uint32_t* d = ktu + rr * KSTP + (c4 >> 1);
                d[0] = v.x; d[1] = v.y;
            }
            __syncthreads();
#pragma unroll 4
            for (int ks = 0; ks < 16; ks++) {
                uint32_t a[2][4], bf[2];
                uint32_t po = (uint32_t)(kt0 + ks * 16) * 2;   // half offset -> bytes
                LDSMX4(a[0][0], a[0][1], a[0][2], a[0][3], pAddr + po);
                LDSMX4(a[1][0], a[1][1], a[1][2], a[1][3],
                       pAddr + (16 * SCHP) * 2 + po);
                LDSMX2T(bf[0], bf[1], vAddr + ((ks * 16 * KSTP) << 2));
                MMA_F16(acc[0], a[0], bf);
                MMA_F16(acc[1], a[1], bf);
            }
            __syncthreads();
        }

#pragma unroll
        for (int i = 0; i < 2; i++) {
            int row0 = i * 16 + r, row1 = row0 + 8;
            float inv0 = 1.f / rsum[row0];
            float inv1 = 1.f / rsum[row1];
            int col = w * 8 + 2 * c;
            *(uint32_t*)(O + bh_out + (size_t)(q0 + row0) * HH + col) =
                h2(acc[i][0] * inv0, acc[i][1] * inv0);
            *(uint32_t*)(O + bh_out + (size_t)(q0 + row1) * HH + col) =
                h2(acc[i][2] * inv1, acc[i][3] * inv1);
        }
    }
}

// ---------------- launcher ----------------
extern "C" void kernel_launch(void* const* d_in, const int* in_sizes, int n_in,
                              void* d_out, int out_size) {
    const float* x    = (const float*)d_in[0];
    const int*   mask = (const int*)d_in[1];
    const float* dw_w = (const float*)d_in[2];
    const float* dw_b = (const float*)d_in[3];
    const float* pw_w = (const float*)d_in[4];
    const float* pw_b = (const float*)d_in[5];
    const float* lcg  = (const float*)d_in[6];
    const float* lcb  = (const float*)d_in[7];
    const float* wq   = (const float*)d_in[8];
    const float* bq   = (const float*)d_in[9];
    const float* wk   = (const float*)d_in[10];
    const float* bk   = (const float*)d_in[11];
    const float* wv   = (const float*)d_in[12];
    const float* bv   = (const float*)d_in[13];
    const float* wo   = (const float*)d_in[14];
    const float* bo   = (const float*)d_in[15];
    const float* ek   = (const float*)d_in[16];
    const float* ev   = (const float*)d_in[17];
    const float* lag  = (const float*)d_in[18];
    const float* lab  = (const float*)d_in[19];
    const float* wff  = (const float*)d_in[20];
    const float* bff  = (const float*)d_in[21];
    const float* lfg  = (const float*)d_in[22];
    const float* lfb  = (const float*)d_in[23];
    float* xo = (float*)d_out;

    float *phf, *pqkv, *pbqkv, *ppe, *pst;
    __half* pwh;
    cudaGetSymbolAddress((void**)&phf, g_h);
    cudaGetSymbolAddress((void**)&pqkv, g_qkv);
    cudaGetSymbolAddress((void**)&pwh, g_wh);
    cudaGetSymbolAddress((void**)&pbqkv, g_bqkv);
    cudaGetSymbolAddress((void**)&ppe, g_pe);
    cudaGetSymbolAddress((void**)&pst, g_stats);

    __half* ph_h   = (__half*)phf;
    __half* pqkv_h = (__half*)pqkv;
    float*  px     = pqkv + (size_t)ROWS * RS3 / 2;

    cudaMemcpyAsync(pbqkv,          bq, HH * 4, cudaMemcpyDeviceToDevice);
    cudaMemcpyAsync(pbqkv + HH,     bk, HH * 4, cudaMemcpyDeviceToDevice);
    cudaMemcpyAsync(pbqkv + 2 * HH, bv, HH * 4, cudaMemcpyDeviceToDevice);

    const int ATTN_SMEM = 42112 * 4;
    cudaFuncSetAttribute((const void*)attn_kernel,
                         cudaFuncAttributeMaxDynamicSharedMemorySize, ATTN_SMEM);

    dim3 gemm_grid(HH / 128, ROWS / 128);
    dim3 qkv_grid(RS3 / 128, ROWS / 128);
    dim3 dw_grid(8, 4, 32);

    wconv_kernel<<<dim3(HH * HH / 256, 7), 256>>>(pw_w, wq, wk, wv, wo, wff, pwh);
    pe_kernel<<<(SS * HH) / 256, 256>>>(ppe);
    pos_add_kernel<<<TOT / 256, 256>>>(x, mask, ppe, xo);

    for (int i = 0; i < 2; i++) {
        ln_stats<<<ROWS / 8, 256>>>(xo, pst);
        dwconv_kernel<<<dw_grid, 256>>>(xo, pst, lcg + i * HH, lcb + i * HH,
                                        dw_w + i * HH * KW, dw_b + i * HH, ph_h);
        tgemm<true, false, false, true, true><<<gemm_grid, 256>>>(
            ph_h, pwh + (size_t)i * HH * HH, pw_b + i * HH, xo,
            nullptr, nullptr, nullptr, xo, HH, HH);
    }

    ln_stats<<<ROWS / 8, 256>>>(xo, pst);
    tgemm<false, true, true, false, false><<<qkv_grid, 256>>>(
        xo, pwh + (size_t)2 * HH * HH, pbqkv, nullptr,
        pst, lag, lab, pqkv_h, RS3, HH);

    attn_kernel<<<dim3(SS / TQ, NHD, BB), 256, ATTN_SMEM>>>(pqkv_h, ek, ev, ph_h);

    tgemm<true, false, false, false, true><<<gemm_grid, 256>>>(
        ph_h, pwh + (size_t)5 * HH * HH, bo, xo,
        nullptr, nullptr, nullptr, px, HH, HH);

    ln_stats<<<ROWS / 8, 256>>>(px, pst);
    tgemm<false, true, false, true, true><<<gemm_grid, 256>>>(
        px, pwh + (size_t)6 * HH * HH, bff, px,
        pst, lfg, lfb, xo, HH, HH);
}

// round 16
// speedup vs baseline: 4.0824x; 1.2454x over previous
#include <cuda_runtime.h>
#include <cuda_fp16.h>
#include <math.h>
#include <stdint.h>

// ---------------- problem constants ----------------
#define BB   32
#define SS   512
#define HH   512
#define NHD  8
#define DK   64
#define KW   7
#define NV   33
#define RS3  (3*HH)
#define ROWS (BB*SS)
#define TOT  (BB*SS*HH)

// ---------------- scratch ----------------
__device__ float  g_h[TOT];
__device__ float  g_qkv[ROWS * RS3];     // lower half: half QKV; upper: fp32 x'
__device__ __half g_wh[7 * HH * HH];
__device__ float  g_bqkv[3 * HH];
__device__ float  g_pe[SS * HH];
__device__ float  g_stats[ROWS * 2];

// ---------------- helpers ----------------
__device__ __forceinline__ uint32_t h2(float x, float y) {
    __half2 h = __floats2half2_rn(x, y);
    return *reinterpret_cast<uint32_t*>(&h);
}
__device__ __forceinline__ uint32_t sptr(const void* p) {
    return (uint32_t)__cvta_generic_to_shared(p);
}
#define U(x) __float_as_uint(x)

#define MMA_TF32(d, a, b)                                                     \
    asm volatile("mma.sync.aligned.m16n8k8.row.col.f32.tf32.tf32.f32 "       \
                 "{%0,%1,%2,%3}, {%4,%5,%6,%7}, {%8,%9}, {%0,%1,%2,%3};"     \
                 : "+f"(d[0]), "+f"(d[1]), "+f"(d[2]), "+f"(d[3])            \
                 : "r"(a[0]), "r"(a[1]), "r"(a[2]), "r"(a[3]),               \
                   "r"(b[0]), "r"(b[1]))

#define MMA_F16(d, a, b)                                                      \
    asm volatile("mma.sync.aligned.m16n8k16.row.col.f32.f16.f16.f32 "        \
                 "{%0,%1,%2,%3}, {%4,%5,%6,%7}, {%8,%9}, {%0,%1,%2,%3};"     \
                 : "+f"(d[0]), "+f"(d[1]), "+f"(d[2]), "+f"(d[3])            \
                 : "r"(a[0]), "r"(a[1]), "r"(a[2]), "r"(a[3]),               \
                   "r"(b[0]), "r"(b[1]))

#define LDSMX4(r0, r1, r2, r3, addr)                                          \
    asm volatile("ldmatrix.sync.aligned.m8n8.x4.shared.b16 {%0,%1,%2,%3}, [%4];" \
                 : "=r"(r0), "=r"(r1), "=r"(r2), "=r"(r3) : "r"(addr))

#define LDSMX2T(r0, r1, addr)                                                 \
    asm volatile("ldmatrix.sync.aligned.m8n8.x2.trans.shared.b16 {%0,%1}, [%2];" \
                 : "=r"(r0), "=r"(r1) : "r"(addr))

// ---------------- weight convert ----------------
__global__ void wconv_kernel(const float* __restrict__ pw,
                             const float* __restrict__ wq,
                             const float* __restrict__ wk,
                             const float* __restrict__ wv,
                             const float* __restrict__ wo,
                             const float* __restrict__ wff,
                             __half* __restrict__ out) {
    int m = blockIdx.y;
    int idx = blockIdx.x * 256 + threadIdx.x;
    const float* src;
    switch (m) {
        case 0: src = pw; break;
        case 1: src = pw + HH * HH; break;
        case 2: src = wq; break;
        case 3: src = wk; break;
        case 4: src = wv; break;
        case 5: src = wo; break;
        default: src = wff; break;
    }
    out[(size_t)m * HH * HH + idx] = __float2half(src[idx]);
}

// ---------------- positional encoding ----------------
__global__ void pe_kernel(float* __restrict__ pe) {
    int idx = blockIdx.x * 256 + threadIdx.x;
    int h = idx & (HH - 1);
    int s = idx >> 9;
    float v = 0.f;
    if (s > 0) {
        float pos = (float)(s - 1);
        int i2 = h & ~1;
        float div = expf((float)i2 * (-9.210340371976184f / (float)HH));
        float ang = pos * div;
        v = (h & 1) ? cosf(ang) : sinf(ang);
    }
    pe[idx] = v;
}

__global__ void pos_add_kernel(const float* __restrict__ x,
                               const int* __restrict__ mask,
                               const float* __restrict__ pe,
                               float* __restrict__ out) {
    int idx = blockIdx.x * 256 + threadIdx.x;
    int s = (idx >> 9) & (SS - 1);
    int b = idx >> 18;
    out[idx] = x[idx] + pe[idx & (SS * HH - 1)] * (float)mask[(b << 9) + s];
}

// ---------------- LN stats ----------------
__global__ void ln_stats(const float* __restrict__ x, float* __restrict__ stats) {
    int row = blockIdx.x * 8 + (threadIdx.x >> 5);
    int lane = threadIdx.x & 31;
    const float4* xr = (const float4*)(x + (size_t)row * HH);
    float s = 0.f, sq = 0.f;
#pragma unroll
    for (int i = 0; i < 4; i++) {
        float4 v = xr[lane + i * 32];
        s += v.x + v.y + v.z + v.w;
        sq += v.x * v.x + v.y * v.y + v.z * v.z + v.w * v.w;
    }
#pragma unroll
    for (int o = 16; o > 0; o >>= 1) {
        s  += __shfl_xor_sync(0xffffffffu, s, o);
        sq += __shfl_xor_sync(0xffffffffu, sq, o);
    }
    if (lane == 0) {
        float mean = s * (1.f / HH);
        float var = sq * (1.f / HH) - mean * mean;
        stats[row * 2] = mean;
        stats[row * 2 + 1] = rsqrtf(var + 1e-5f);
    }
}

// ---------------- depthwise conv (fused LN, sliding window, half out) ----------------
__global__ void dwconv_kernel(const float* __restrict__ x,
                              const float* __restrict__ stats,
                              const float* __restrict__ lg,
                              const float* __restrict__ lb,
                              const float* __restrict__ w,
                              const float* __restrict__ bias,
                              __half* __restrict__ out) {
    __shared__ float sb[70][128];
    __shared__ float2 sstat[70];
    __shared__ float lgs[128], lbs[128];
    int s0 = blockIdx.x * 64, c0 = blockIdx.y * 128, b = blockIdx.z;
    int tid = threadIdx.x;
    if (tid < 128) { lgs[tid] = lg[c0 + tid]; lbs[tid] = lb[c0 + tid]; }
    else if (tid < 198) {
        int sp = s0 + (tid - 128) - 3;
        float2 st = {0.f, 0.f};
        if (sp >= 0 && sp < SS) st = *(const float2*)(stats + ((size_t)b * SS + sp) * 2);
        sstat[tid - 128] = st;
    }
    __syncthreads();
    const float* base = x + ((size_t)b * SS) * HH + c0;
#pragma unroll 3
    for (int i = tid; i < 70 * 32; i += 256) {
        int r = i >> 5, c4 = (i & 31) << 2;
        int sp = s0 + r - 3;
        float4 v = {0.f, 0.f, 0.f, 0.f};
        if (sp >= 0 && sp < SS) {
            v = *(const float4*)(base + (size_t)sp * HH + c4);
            float2 st = sstat[r];
            v.x = (v.x - st.x) * st.y * lgs[c4]     + lbs[c4];
            v.y = (v.y - st.x) * st.y * lgs[c4 + 1] + lbs[c4 + 1];
            v.z = (v.z - st.x) * st.y * lgs[c4 + 2] + lbs[c4 + 2];
            v.w = (v.w - st.x) * st.y * lgs[c4 + 3] + lbs[c4 + 3];
        }
        *(float4*)(&sb[r][c4]) = v;
    }
    __syncthreads();
    int c = tid & 127;
    int rr0 = (tid >> 7) * 32;
    float wr[KW];
#pragma unroll
    for (int t = 0; t < KW; t++) wr[t] = w[(c0 + c) * KW + t];
    float bz = bias[c0 + c];
    __half* obase = out + ((size_t)b * SS + s0) * HH + c0 + c;
    float win[KW];
#pragma unroll
    for (int t = 0; t < KW; t++) win[t] = sb[rr0 + t][c];
#pragma unroll
    for (int r = 0; r < 32; r++) {
        float acc = bz;
#pragma unroll
        for (int t = 0; t < KW; t++) acc = fmaf(win[t], wr[t], acc);
        obase[(size_t)(rr0 + r) * HH] = __float2half(acc);
#pragma unroll
        for (int t = 0; t < KW - 1; t++) win[t] = win[t + 1];
        if (r < 31) win[KW - 1] = sb[rr0 + r + KW][c];
    }
}

// ---------------- fp16 GEMM with ldmatrix fragments (unchanged) ----------------
template <bool AHALF, bool LNA, bool OUTH, bool RELU, bool RES>
__global__ void __launch_bounds__(256, 2)
tgemm(const void* __restrict__ Av, const __half* __restrict__ W,
      const float* __restrict__ bias, const float* res,
      const float* __restrict__ stats, const float* __restrict__ lng,
      const float* __restrict__ lnb,
      void* __restrict__ outv, int Ndim, int Kdim) {
    __shared__ uint32_t Asm[2][128 * 12];
    __shared__ uint32_t Wsm[2][128 * 12];
    int bm = blockIdx.y * 128, bn = blockIdx.x * 128;
    int tid = threadIdx.x;
    int wid = tid >> 5, lane = tid & 31;
    int wm = (wid & 3) * 32, wn = (wid >> 2) * 64;

    float acc[2][8][4];
#pragma unroll
    for (int i = 0; i < 2; i++)
#pragma unroll
        for (int j = 0; j < 8; j++)
#pragma unroll
            for (int q = 0; q < 4; q++) acc[i][j][q] = 0.f;

    int tr = lane & 7, ts = lane >> 3;
    uint32_t aAddr = sptr(&Asm[0][0]) +
        (((wm + ((ts & 1) << 3) + tr) * 12 + ((ts >> 1) << 2)) << 2);
    uint32_t bAddr[4];
#pragma unroll
    for (int j4 = 0; j4 < 4; j4++)
        bAddr[j4] = sptr(&Wsm[0][0]) +
            (((wn + 8 * (2 * j4 + (ts >> 1)) + tr) * 12 + ((ts & 1) << 2)) << 2);

    int rowW = tid >> 1, grpW = tid & 1;
    const __half* Wp = W + (size_t)(bn + rowW) * Kdim + grpW * 8;
    int soW = rowW * 12 + grpW * 4;

    const __half* Ahp = nullptr;
    const float *Ap0 = nullptr, *Ap1 = nullptr;
    int so0 = 0, so1 = 0, c40 = 0;
    float m0 = 0.f, r0s = 1.f, m1 = 0.f, r1s = 1.f;
    if (AHALF) {
        Ahp = (const __half*)Av + (size_t)(bm + rowW) * Kdim + grpW * 8;
    } else {
        int row0 = tid >> 2;
        c40 = (tid & 3) << 2;
        int row1 = row0 + 64;
        Ap0 = (const float*)Av + (size_t)(bm + row0) * Kdim + c40;
        Ap1 = (const float*)Av + (size_t)(bm + row1) * Kdim + c40;
        so0 = row0 * 12 + (c40 >> 1);
        so1 = row1 * 12 + (c40 >> 1);
        if (LNA) {
            float2 st0 = *(const float2*)(stats + (size_t)(bm + row0) * 2);
            float2 st1 = *(const float2*)(stats + (size_t)(bm + row1) * 2);
            m0 = st0.x; r0s = st0.y; m1 = st1.x; r1s = st1.y;
        }
    }

    uint4 rw = *(const uint4*)Wp;
    uint4 rah;
    float4 a0, a1, g4, b4;
    if (AHALF) {
        rah = *(const uint4*)Ahp;
    } else {
        a0 = *(const float4*)Ap0;
        a1 = *(const float4*)Ap1;
        if (LNA) {
            g4 = *(const float4*)(lng + c40);
            b4 = *(const float4*)(lnb + c40);
        }
    }

    int buf = 0;
    int nk = Kdim >> 4;
    for (int s = 1;; s++) {
        *(uint4*)&Wsm[buf][soW] = rw;
        if (AHALF) {
            *(uint4*)&Asm[buf][soW] = rah;
        } else {
            float4 ta0 = a0, ta1 = a1;
            if (LNA) {
                ta0.x = (a0.x - m0) * r0s * g4.x + b4.x;
                ta0.y = (a0.y - m0) * r0s * g4.y + b4.y;
                ta0.z = (a0.z - m0) * r0s * g4.z + b4.z;
                ta0.w = (a0.w - m0) * r0s * g4.w + b4.w;
                ta1.x = (a1.x - m1) * r1s * g4.x + b4.x;
                ta1.y = (a1.y - m1) * r1s * g4.y + b4.y;
                ta1.z = (a1.z - m1) * r1s * g4.z + b4.z;
                ta1.w = (a1.w - m1) * r1s * g4.w + b4.w;
            }
            uint2 u;
            u.x = h2(ta0.x, ta0.y); u.y = h2(ta0.z, ta0.w);
            *(uint2*)&Asm[buf][so0] = u;
            u.x = h2(ta1.x, ta1.y); u.y = h2(ta1.z, ta1.w);
            *(uint2*)&Asm[buf][so1] = u;
        }
        __syncthreads();
        bool more = (s < nk);
        if (more) {
            rw = *(const uint4*)(Wp + s * 16);
            if (AHALF) {
                rah = *(const uint4*)(Ahp + s * 16);
            } else {
                a0 = *(const float4*)(Ap0 + s * 16);
                a1 = *(const float4*)(Ap1 + s * 16);
                if (LNA) {
                    g4 = *(const float4*)(lng + s * 16 + c40);
                    b4 = *(const float4*)(lnb + s * 16 + c40);
                }
            }
        }
        {
            uint32_t bo = buf ? 6144u : 0u;
            uint32_t af[2][4], bf[8][2];
            LDSMX4(af[0][0], af[0][1], af[0][2], af[0][3], aAddr + bo);
            LDSMX4(af[1][0], af[1][1], af[1][2], af[1][3], aAddr + bo + 768u);
#pragma unroll
            for (int j4 = 0; j4 < 4; j4++) {
                LDSMX4(bf[2 * j4][0], bf[2 * j4][1],
                       bf[2 * j4 + 1][0], bf[2 * j4 + 1][1], bAddr[j4] + bo);
            }
#pragma unroll
            for (int i = 0; i < 2; i++)
#pragma unroll
                for (int j = 0; j < 8; j++)
                    MMA_F16(acc[i][j], af[i], bf[j]);
        }
        if (!more) break;
        buf ^= 1;
    }

    int r = lane >> 2, c = lane & 3;
#pragma unroll
    for (int i = 0; i < 2; i++) {
        int m0i = bm + wm + i * 16 + r;
#pragma unroll
        for (int j = 0; j < 8; j++) {
            int n0 = bn + wn + j * 8 + 2 * c;
            float2 b2 = *(const float2*)(bias + n0);
            float v0 = acc[i][j][0] + b2.x;
            float v1 = acc[i][j][1] + b2.y;
            float v2 = acc[i][j][2] + b2.x;
            float v3 = acc[i][j][3] + b2.y;
            if (RELU) {
                v0 = fmaxf(v0, 0.f); v1 = fmaxf(v1, 0.f);
                v2 = fmaxf(v2, 0.f); v3 = fmaxf(v3, 0.f);
            }
            if (RES) {
                float2 r0v = *(const float2*)(res + (size_t)m0i * Ndim + n0);
                float2 r1v = *(const float2*)(res + (size_t)(m0i + 8) * Ndim + n0);
                v0 += r0v.x; v1 += r0v.y; v2 += r1v.x; v3 += r1v.y;
            }
            if (OUTH) {
                __half* oh = (__half*)outv;
                *(uint32_t*)(oh + (size_t)m0i * Ndim + n0) = h2(v0, v1);
                *(uint32_t*)(oh + (size_t)(m0i + 8) * Ndim + n0) = h2(v2, v3);
            } else {
                float* of = (float*)outv;
                float2 o0 = {v0, v1}, o1 = {v2, v3};
                *(float2*)(of + (size_t)m0i * Ndim + n0) = o0;
                *(float2*)(of + (size_t)(m0i + 8) * Ndim + n0) = o1;
            }
        }
    }
}

// ---------------- attention: half scores, f16x2 exp, corrected layout ----------------
#define TQ    32
#define QSTP  36
#define KSTP  36
#define SCHP  520     // half stride of score/prob buffer
#define EBST  72
#define RDST  40

__global__ void __launch_bounds__(256)
attn_kernel(const __half* __restrict__ QKV, const float* __restrict__ EK,
            const float* __restrict__ EV, __half* __restrict__ O) {
    int qt = blockIdx.x, h = blockIdx.y, b = blockIdx.z;
    int q0 = qt * TQ;
    extern __shared__ float sm[];
    // layout (32-bit word offsets); sch needs 32*520 halves = 16640 halves = 8320 WORDS
    uint32_t* qsu  = (uint32_t*)sm;             // [0, 1152)
    __half*   sch  = (__half*)(sm + 1152);      // [1152, 9472)  8320 w
    uint32_t* ktu  = (uint32_t*)(sm + 9472);    // [9472, 18688) 9216 w
    uint32_t* ebku = (uint32_t*)(sm + 18688);   // [18688, 20128) 1440 w
    float*    ebv  = sm + 20128;                // [20128, 23008) 2880 w
    float*    rdot = sm + 23008;                // [23008, 24288) 1280 w
    float*    wsum = sm + 24288;                // [24288, 25568) 1280 w
    float*    rsum = sm + 25568;                // [25568, 25600) 32 w

    int tid = threadIdx.x;
    int w = tid >> 5, lane = tid & 31;
    int r = lane >> 2, c = lane & 3;
    int tr = lane & 7, ts = lane >> 3;

    size_t bh_in  = ((size_t)b * SS) * RS3 + h * DK;
    size_t bh_out = ((size_t)b * SS) * HH  + h * DK;

    // ---- stage Q pairs ----
#pragma unroll
    for (int i = 0; i < 2; i++) {
        int f = tid + (i << 8);
        int row = f >> 4, c4 = (f & 15) << 2;
        uint2 v = *(const uint2*)(QKV + bh_in + (size_t)(q0 + row) * RS3 + c4);
        uint32_t* d = qsu + row * QSTP + (c4 >> 1);
        d[0] = v.x; d[1] = v.y;
    }
    // ---- stage embed_k (half pairs) / embed_v (raw f32) ----
    for (int f = tid; f < 40 * 16; f += 256) {
        int row = f >> 4, c4 = (f & 15) << 2;
        float4 vk = {0.f, 0.f, 0.f, 0.f}, vv = {0.f, 0.f, 0.f, 0.f};
        if (row < NV) {
            vk = *(const float4*)(EK + row * DK + c4);
            vv = *(const float4*)(EV + row * DK + c4);
        }
        uint32_t* dk = ebku + row * QSTP + (c4 >> 1);
        dk[0] = h2(vk.x, vk.y); dk[1] = h2(vk.z, vk.w);
        *(float4*)(ebv + row * EBST + c4) = vv;
    }
    for (int f = tid; f < 32 * RDST; f += 256) wsum[f] = 0.f;
    __syncthreads();

    // ---- rdot = Q · embed_k^T (fp16, warps 0..4) ----
    if (w < 5) {
        float acc[2][4] = {{0.f, 0.f, 0.f, 0.f}, {0.f, 0.f, 0.f, 0.f}};
#pragma unroll
        for (int ks = 0; ks < 4; ks++) {
            uint32_t a[2][4], bf[2];
#pragma unroll
            for (int i = 0; i < 2; i++) {
                const uint32_t* p = qsu + (i * 16 + r) * QSTP + ks * 8 + c;
                a[i][0] = p[0]; a[i][1] = p[8 * QSTP];
                a[i][2] = p[4]; a[i][3] = p[8 * QSTP + 4];
            }
            const uint32_t* pb = ebku + (w * 8 + r) * QSTP + ks * 8 + c;
            bf[0] = pb[0]; bf[1] = pb[4];
            MMA_F16(acc[0], a[0], bf);
            MMA_F16(acc[1], a[1], bf);
        }
#pragma unroll
        for (int i = 0; i < 2; i++) {
            int row = i * 16 + r;
            rdot[row * RDST + w * 8 + 2 * c]           = acc[i][0];
            rdot[row * RDST + w * 8 + 2 * c + 1]       = acc[i][1];
            rdot[(row + 8) * RDST + w * 8 + 2 * c]     = acc[i][2];
            rdot[(row + 8) * RDST + w * 8 + 2 * c + 1] = acc[i][3];
        }
    }
    __syncthreads();

    // ldmatrix bases
    uint32_t qAddr = sptr(qsu) +
        (((((ts & 1) << 3) + tr) * QSTP + ((ts >> 1) << 2)) << 2);
    uint32_t kAddr0 = sptr(ktu) +
        (((w * 32 + 8 * (ts >> 1) + tr) * KSTP + ((ts & 1) << 2)) << 2);
    uint32_t kAddr1 = kAddr0 + ((16 * KSTP) << 2);
    uint32_t pAddr = sptr(sch) +
        ((((ts & 1) << 3) + tr) * SCHP + ((ts >> 1) << 3)) * 2;
    uint32_t vAddr = sptr(ktu) + (((lane & 15) * KSTP + w * 4) << 2);

    // ---- QK (fp16 + ldmatrix): scores written as half ----
    for (int kt0 = 0; kt0 < SS; kt0 += 256) {
#pragma unroll
        for (int i = 0; i < 16; i++) {
            int f = tid + (i << 8);
            int rr = f >> 4, c4 = (f & 15) << 2;
            uint2 v = *(const uint2*)(QKV + bh_in + HH + (size_t)(kt0 + rr) * RS3 + c4);
            uint32_t* d = ktu + rr * KSTP + (c4 >> 1);
            d[0] = v.x; d[1] = v.y;
        }
        __syncthreads();
        float acc[2][4][4];
#pragma unroll
        for (int i = 0; i < 2; i++)
#pragma unroll
            for (int j = 0; j < 4; j++)
#pragma unroll
                for (int q = 0; q < 4; q++) acc[i][j][q] = 0.f;
#pragma unroll
        for (int ks = 0; ks < 4; ks++) {
            uint32_t kso = ks * 32;
            uint32_t a[2][4], bf[4][2];
            LDSMX4(a[0][0], a[0][1], a[0][2], a[0][3], qAddr + kso);
            LDSMX4(a[1][0], a[1][1], a[1][2], a[1][3],
                   qAddr + ((16 * QSTP) << 2) + kso);
            LDSMX4(bf[0][0], bf[0][1], bf[1][0], bf[1][1], kAddr0 + kso);
            LDSMX4(bf[2][0], bf[2][1], bf[3][0], bf[3][1], kAddr1 + kso);
#pragma unroll
            for (int jn = 0; jn < 4; jn++) {
                MMA_F16(acc[0][jn], a[0], bf[jn]);
                MMA_F16(acc[1][jn], a[1], bf[jn]);
            }
        }
#pragma unroll
        for (int i = 0; i < 2; i++) {
#pragma unroll
            for (int jn = 0; jn < 4; jn++) {
                int colb = kt0 + w * 32 + jn * 8 + 2 * c;
                int row0 = i * 16 + r, row1 = row0 + 8;
                int qg0 = q0 + row0, qg1 = q0 + row1;
                int d00 = colb - qg0;     d00 = d00 < -16 ? -16 : (d00 > 16 ? 16 : d00);
                int d01 = colb + 1 - qg0; d01 = d01 < -16 ? -16 : (d01 > 16 ? 16 : d01);
                int d10 = colb - qg1;     d10 = d10 < -16 ? -16 : (d10 > 16 ? 16 : d10);
                int d11 = colb + 1 - qg1; d11 = d11 < -16 ? -16 : (d11 > 16 ? 16 : d11);
                float v0 = acc[i][jn][0] + rdot[row0 * RDST + d00 + 16];
                float v1 = acc[i][jn][1] + rdot[row0 * RDST + d01 + 16];
                float v2 = acc[i][jn][2] + rdot[row1 * RDST + d10 + 16];
                float v3 = acc[i][jn][3] + rdot[row1 * RDST + d11 + 16];
                *(uint32_t*)(sch + row0 * SCHP + colb) = h2(v0, v1);
                *(uint32_t*)(sch + row1 * SCHP + colb) = h2(v2, v3);
            }
        }
        __syncthreads();
    }

    // ---- softmax on half scores with ex2.approx.f16x2; fp32 sums ----
    {
        const float L2E = 1.4426950408889634f;
        for (int rr = w; rr < TQ; rr += 8) {
            __half2* hrow = (__half2*)(sch + rr * SCHP);
            int qg = q0 + rr;
            float mx = -1e30f;
#pragma unroll
            for (int i = 0; i < 8; i++) {
                float2 f = __half22float2(hrow[lane + 32 * i]);
                mx = fmaxf(mx, fmaxf(f.x, f.y));
            }
#pragma unroll
            for (int o = 16; o > 0; o >>= 1)
                mx = fmaxf(mx, __shfl_xor_sync(0xffffffffu, mx, o));
            float sum = 0.f, w0 = 0.f, w32 = 0.f;
#pragma unroll
            for (int i = 0; i < 8; i++) {
                int kp = lane + 32 * i;
                float2 f = __half22float2(hrow[kp]);
                uint32_t packed = h2((f.x - mx) * L2E, (f.y - mx) * L2E);
                uint32_t er;
                asm("ex2.approx.f16x2 %0, %1;" : "=r"(er) : "r"(packed));
                hrow[kp] = *reinterpret_cast<__half2*>(&er);
                float2 e = __half22float2(*reinterpret_cast<__half2*>(&er));
                sum += e.x + e.y;
                int k0 = 2 * kp, k1 = k0 + 1;
                if (k0 <= qg - 16) w0 += e.x;
                if (k1 <= qg - 16) w0 += e.y;
                if (k0 >= qg + 16) w32 += e.x;
                if (k1 >= qg + 16) w32 += e.y;
            }
#pragma unroll
            for (int o = 16; o > 0; o >>= 1) {
                sum += __shfl_xor_sync(0xffffffffu, sum, o);
                w0  += __shfl_xor_sync(0xffffffffu, w0, o);
                w32 += __shfl_xor_sync(0xffffffffu, w32, o);
            }
            __syncwarp();
            if (lane == 0) {
                rsum[rr] = sum;
                wsum[rr * RDST + 0] = w0;
                wsum[rr * RDST + 32] = w32;
            } else {
                int k = qg + lane - 16;
                wsum[rr * RDST + lane] =
                    (k >= 0 && k < SS) ? __half2float(((__half*)hrow)[k]) : 0.f;
            }
        }
    }
    __syncthreads();

    // ---- PV (fp16) + rel_v (tf32): warp w owns d-slice [w*8, +8) ----
    {
        float acc[2][4];
#pragma unroll
        for (int i = 0; i < 2; i++)
#pragma unroll
            for (int q = 0; q < 4; q++) acc[i][q] = 0.f;

#pragma unroll
        for (int ks = 0; ks < 5; ks++) {
            uint32_t a[2][4], bf[2];
#pragma unroll
            for (int i = 0; i < 2; i++) {
                int base = (i * 16 + r) * RDST + ks * 8 + c;
                a[i][0] = U(wsum[base]);
                a[i][1] = U(wsum[base + 8 * RDST]);
                a[i][2] = U(wsum[base + 4]);
                a[i][3] = U(wsum[base + 8 * RDST + 4]);
            }
            int pb = (ks * 8 + c) * EBST + w * 8 + r;
            bf[0] = U(ebv[pb]); bf[1] = U(ebv[pb + 4 * EBST]);
            MMA_TF32(acc[0], a[0], bf);
            MMA_TF32(acc[1], a[1], bf);
        }

        for (int kt0 = 0; kt0 < SS; kt0 += 256) {
#pragma unroll
            for (int i = 0; i < 16; i++) {
                int f = tid + (i << 8);
                int rr = f >> 4, c4 = (f & 15) << 2;
                uint2 v = *(const uint2*)(QKV + bh_in + 2 * HH +
                                          (size_t)(kt0 + rr) * RS3 + c4);
                uint32_t* d = ktu + rr * KSTP + (c4 >> 1);
                d[0] = v.x; d[1] = v.y;
            }
            __syncthreads();
#pragma unroll 4
            for (int ks = 0; ks < 16; ks++) {
                uint32_t a[2][4], bf[2];
                uint32_t po = (uint32_t)(kt0 + ks * 16) * 2;
                LDSMX4(a[0][0], a[0][1], a[0][2], a[0][3], pAddr + po);
                LDSMX4(a[1][0], a[1][1], a[1][2], a[1][3],
                       pAddr + (16 * SCHP) * 2 + po);
                LDSMX2T(bf[0], bf[1], vAddr + ((ks * 16 * KSTP) << 2));
                MMA_F16(acc[0], a[0], bf);
                MMA_F16(acc[1], a[1], bf);
            }
            __syncthreads();
        }

#pragma unroll
        for (int i = 0; i < 2; i++) {
            int row0 = i * 16 + r, row1 = row0 + 8;
            float inv0 = 1.f / rsum[row0];
            float inv1 = 1.f / rsum[row1];
            int col = w * 8 + 2 * c;
            *(uint32_t*)(O + bh_out + (size_t)(q0 + row0) * HH + col) =
                h2(acc[i][0] * inv0, acc[i][1] * inv0);
            *(uint32_t*)(O + bh_out + (size_t)(q0 + row1) * HH + col) =
                h2(acc[i][2] * inv1, acc[i][3] * inv1);
        }
    }
}

// ---------------- launcher ----------------
extern "C" void kernel_launch(void* const* d_in, const int* in_sizes, int n_in,
                              void* d_out, int out_size) {
    const float* x    = (const float*)d_in[0];
    const int*   mask = (const int*)d_in[1];
    const float* dw_w = (const float*)d_in[2];
    const float* dw_b = (const float*)d_in[3];
    const float* pw_w = (const float*)d_in[4];
    const float* pw_b = (const float*)d_in[5];
    const float* lcg  = (const float*)d_in[6];
    const float* lcb  = (const float*)d_in[7];
    const float* wq   = (const float*)d_in[8];
    const float* bq   = (const float*)d_in[9];
    const float* wk   = (const float*)d_in[10];
    const float* bk   = (const float*)d_in[11];
    const float* wv   = (const float*)d_in[12];
    const float* bv   = (const float*)d_in[13];
    const float* wo   = (const float*)d_in[14];
    const float* bo   = (const float*)d_in[15];
    const float* ek   = (const float*)d_in[16];
    const float* ev   = (const float*)d_in[17];
    const float* lag  = (const float*)d_in[18];
    const float* lab  = (const float*)d_in[19];
    const float* wff  = (const float*)d_in[20];
    const float* bff  = (const float*)d_in[21];
    const float* lfg  = (const float*)d_in[22];
    const float* lfb  = (const float*)d_in[23];
    float* xo = (float*)d_out;

    float *phf, *pqkv, *pbqkv, *ppe, *pst;
    __half* pwh;
    cudaGetSymbolAddress((void**)&phf, g_h);
    cudaGetSymbolAddress((void**)&pqkv, g_qkv);
    cudaGetSymbolAddress((void**)&pwh, g_wh);
    cudaGetSymbolAddress((void**)&pbqkv, g_bqkv);
    cudaGetSymbolAddress((void**)&ppe, g_pe);
    cudaGetSymbolAddress((void**)&pst, g_stats);

    __half* ph_h   = (__half*)phf;
    __half* pqkv_h = (__half*)pqkv;
    float*  px     = pqkv + (size_t)ROWS * RS3 / 2;

    cudaMemcpyAsync(pbqkv,          bq, HH * 4, cudaMemcpyDeviceToDevice);
    cudaMemcpyAsync(pbqkv + HH,     bk, HH * 4, cudaMemcpyDeviceToDevice);
    cudaMemcpyAsync(pbqkv + 2 * HH, bv, HH * 4, cudaMemcpyDeviceToDevice);

    const int ATTN_SMEM = 25600 * 4;   // 100KB -> still 2 blocks/SM
    cudaFuncSetAttribute((const void*)attn_kernel,
                         cudaFuncAttributeMaxDynamicSharedMemorySize, ATTN_SMEM);

    dim3 gemm_grid(HH / 128, ROWS / 128);
    dim3 qkv_grid(RS3 / 128, ROWS / 128);
    dim3 dw_grid(8, 4, 32);

    wconv_kernel<<<dim3(HH * HH / 256, 7), 256>>>(pw_w, wq, wk, wv, wo, wff, pwh);
    pe_kernel<<<(SS * HH) / 256, 256>>>(ppe);
    pos_add_kernel<<<TOT / 256, 256>>>(x, mask, ppe, xo);

    for (int i = 0; i < 2; i++) {
        ln_stats<<<ROWS / 8, 256>>>(xo, pst);
        dwconv_kernel<<<dw_grid, 256>>>(xo, pst, lcg + i * HH, lcb + i * HH,
                                        dw_w + i * HH * KW, dw_b + i * HH, ph_h);
        tgemm<true, false, false, true, true><<<gemm_grid, 256>>>(
            ph_h, pwh + (size_t)i * HH * HH, pw_b + i * HH, xo,
            nullptr, nullptr, nullptr, xo, HH, HH);
    }

    ln_stats<<<ROWS / 8, 256>>>(xo, pst);
    tgemm<false, true, true, false, false><<<qkv_grid, 256>>>(
        xo, pwh + (size_t)2 * HH * HH, pbqkv, nullptr,
        pst, lag, lab, pqkv_h, RS3, HH);

    attn_kernel<<<dim3(SS / TQ, NHD, BB), 256, ATTN_SMEM>>>(pqkv_h, ek, ev, ph_h);

    tgemm<true, false, false, false, true><<<gemm_grid, 256>>>(
        ph_h, pwh + (size_t)5 * HH * HH, bo, xo,
        nullptr, nullptr, nullptr, px, HH, HH);

    ln_stats<<<ROWS / 8, 256>>>(px, pst);
    tgemm<false, true, false, true, true><<<gemm_grid, 256>>>(
        px, pwh + (size_t)6 * HH * HH, bff, px,
        pst, lfg, lfb, xo, HH, HH);
}

// round 17
// speedup vs baseline: 4.3309x; 1.0609x over previous
#include <cuda_runtime.h>
#include <cuda_fp16.h>
#include <math.h>
#include <stdint.h>

// ---------------- problem constants ----------------
#define BB   32
#define SS   512
#define HH   512
#define NHD  8
#define DK   64
#define KW   7
#define NV   33
#define RS3  (3*HH)
#define ROWS (BB*SS)
#define TOT  (BB*SS*HH)

// ---------------- scratch ----------------
__device__ float  g_h[TOT];
__device__ float  g_qkv[ROWS * RS3];     // lower half: half QKV; upper: fp32 x'
__device__ __half g_wh[7 * HH * HH];
__device__ float  g_bqkv[3 * HH];
__device__ float  g_pe[SS * HH];
__device__ float  g_stats[ROWS * 2];

// ---------------- helpers ----------------
__device__ __forceinline__ uint32_t h2(float x, float y) {
    __half2 h = __floats2half2_rn(x, y);
    return *reinterpret_cast<uint32_t*>(&h);
}
__device__ __forceinline__ uint32_t sptr(const void* p) {
    return (uint32_t)__cvta_generic_to_shared(p);
}
#define U(x) __float_as_uint(x)

#define MMA_TF32(d, a, b)                                                     \
    asm volatile("mma.sync.aligned.m16n8k8.row.col.f32.tf32.tf32.f32 "       \
                 "{%0,%1,%2,%3}, {%4,%5,%6,%7}, {%8,%9}, {%0,%1,%2,%3};"     \
                 : "+f"(d[0]), "+f"(d[1]), "+f"(d[2]), "+f"(d[3])            \
                 : "r"(a[0]), "r"(a[1]), "r"(a[2]), "r"(a[3]),               \
                   "r"(b[0]), "r"(b[1]))

#define MMA_F16(d, a, b)                                                      \
    asm volatile("mma.sync.aligned.m16n8k16.row.col.f32.f16.f16.f32 "        \
                 "{%0,%1,%2,%3}, {%4,%5,%6,%7}, {%8,%9}, {%0,%1,%2,%3};"     \
                 : "+f"(d[0]), "+f"(d[1]), "+f"(d[2]), "+f"(d[3])            \
                 : "r"(a[0]), "r"(a[1]), "r"(a[2]), "r"(a[3]),               \
                   "r"(b[0]), "r"(b[1]))

#define LDSMX4(r0, r1, r2, r3, addr)                                          \
    asm volatile("ldmatrix.sync.aligned.m8n8.x4.shared.b16 {%0,%1,%2,%3}, [%4];" \
                 : "=r"(r0), "=r"(r1), "=r"(r2), "=r"(r3) : "r"(addr))

#define LDSMX2T(r0, r1, addr)                                                 \
    asm volatile("ldmatrix.sync.aligned.m8n8.x2.trans.shared.b16 {%0,%1}, [%2];" \
                 : "=r"(r0), "=r"(r1) : "r"(addr))

#define CPA16(dst, src)                                                       \
    asm volatile("cp.async.ca.shared.global [%0], [%1], 16;"                 \
                 :: "r"(dst), "l"(src))
#define CPAC() asm volatile("cp.async.commit_group;")
#define CPAW() asm volatile("cp.async.wait_group 0;")

// ---------------- weight convert ----------------
__global__ void wconv_kernel(const float* __restrict__ pw,
                             const float* __restrict__ wq,
                             const float* __restrict__ wk,
                             const float* __restrict__ wv,
                             const float* __restrict__ wo,
                             const float* __restrict__ wff,
                             __half* __restrict__ out) {
    int m = blockIdx.y;
    int idx = blockIdx.x * 256 + threadIdx.x;
    const float* src;
    switch (m) {
        case 0: src = pw; break;
        case 1: src = pw + HH * HH; break;
        case 2: src = wq; break;
        case 3: src = wk; break;
        case 4: src = wv; break;
        case 5: src = wo; break;
        default: src = wff; break;
    }
    out[(size_t)m * HH * HH + idx] = __float2half(src[idx]);
}

// ---------------- positional encoding ----------------
__global__ void pe_kernel(float* __restrict__ pe) {
    int idx = blockIdx.x * 256 + threadIdx.x;
    int h = idx & (HH - 1);
    int s = idx >> 9;
    float v = 0.f;
    if (s > 0) {
        float pos = (float)(s - 1);
        int i2 = h & ~1;
        float div = expf((float)i2 * (-9.210340371976184f / (float)HH));
        float ang = pos * div;
        v = (h & 1) ? cosf(ang) : sinf(ang);
    }
    pe[idx] = v;
}

// ---------------- fused pos_add + LN stats (warp per row) ----------------
__global__ void pos_add_ln(const float* __restrict__ x,
                           const int* __restrict__ mask,
                           const float* __restrict__ pe,
                           float* __restrict__ out,
                           float* __restrict__ stats) {
    int row = blockIdx.x * 8 + (threadIdx.x >> 5);
    int lane = threadIdx.x & 31;
    int s = row & (SS - 1);
    float m = (float)mask[row];
    const float4* xr = (const float4*)(x + (size_t)row * HH);
    const float4* pr = (const float4*)(pe + (size_t)s * HH);
    float4* orow = (float4*)(out + (size_t)row * HH);
    float sum = 0.f, sq = 0.f;
#pragma unroll
    for (int i = 0; i < 4; i++) {
        float4 v = xr[lane + i * 32];
        float4 p = pr[lane + i * 32];
        v.x += p.x * m; v.y += p.y * m; v.z += p.z * m; v.w += p.w * m;
        orow[lane + i * 32] = v;
        sum += v.x + v.y + v.z + v.w;
        sq  += v.x * v.x + v.y * v.y + v.z * v.z + v.w * v.w;
    }
#pragma unroll
    for (int o = 16; o > 0; o >>= 1) {
        sum += __shfl_xor_sync(0xffffffffu, sum, o);
        sq  += __shfl_xor_sync(0xffffffffu, sq, o);
    }
    if (lane == 0) {
        float mean = sum * (1.f / HH);
        float var = sq * (1.f / HH) - mean * mean;
        stats[row * 2] = mean;
        stats[row * 2 + 1] = rsqrtf(var + 1e-5f);
    }
}

// ---------------- LN stats ----------------
__global__ void ln_stats(const float* __restrict__ x, float* __restrict__ stats) {
    int row = blockIdx.x * 8 + (threadIdx.x >> 5);
    int lane = threadIdx.x & 31;
    const float4* xr = (const float4*)(x + (size_t)row * HH);
    float s = 0.f, sq = 0.f;
#pragma unroll
    for (int i = 0; i < 4; i++) {
        float4 v = xr[lane + i * 32];
        s += v.x + v.y + v.z + v.w;
        sq += v.x * v.x + v.y * v.y + v.z * v.z + v.w * v.w;
    }
#pragma unroll
    for (int o = 16; o > 0; o >>= 1) {
        s  += __shfl_xor_sync(0xffffffffu, s, o);
        sq += __shfl_xor_sync(0xffffffffu, sq, o);
    }
    if (lane == 0) {
        float mean = s * (1.f / HH);
        float var = sq * (1.f / HH) - mean * mean;
        stats[row * 2] = mean;
        stats[row * 2 + 1] = rsqrtf(var + 1e-5f);
    }
}

// ---------------- depthwise conv (fused LN, sliding window, half out) ----------------
__global__ void dwconv_kernel(const float* __restrict__ x,
                              const float* __restrict__ stats,
                              const float* __restrict__ lg,
                              const float* __restrict__ lb,
                              const float* __restrict__ w,
                              const float* __restrict__ bias,
                              __half* __restrict__ out) {
    __shared__ float sb[70][128];
    __shared__ float2 sstat[70];
    __shared__ float lgs[128], lbs[128];
    int s0 = blockIdx.x * 64, c0 = blockIdx.y * 128, b = blockIdx.z;
    int tid = threadIdx.x;
    if (tid < 128) { lgs[tid] = lg[c0 + tid]; lbs[tid] = lb[c0 + tid]; }
    else if (tid < 198) {
        int sp = s0 + (tid - 128) - 3;
        float2 st = {0.f, 0.f};
        if (sp >= 0 && sp < SS) st = *(const float2*)(stats + ((size_t)b * SS + sp) * 2);
        sstat[tid - 128] = st;
    }
    __syncthreads();
    const float* base = x + ((size_t)b * SS) * HH + c0;
#pragma unroll 3
    for (int i = tid; i < 70 * 32; i += 256) {
        int r = i >> 5, c4 = (i & 31) << 2;
        int sp = s0 + r - 3;
        float4 v = {0.f, 0.f, 0.f, 0.f};
        if (sp >= 0 && sp < SS) {
            v = *(const float4*)(base + (size_t)sp * HH + c4);
            float2 st = sstat[r];
            v.x = (v.x - st.x) * st.y * lgs[c4]     + lbs[c4];
            v.y = (v.y - st.x) * st.y * lgs[c4 + 1] + lbs[c4 + 1];
            v.z = (v.z - st.x) * st.y * lgs[c4 + 2] + lbs[c4 + 2];
            v.w = (v.w - st.x) * st.y * lgs[c4 + 3] + lbs[c4 + 3];
        }
        *(float4*)(&sb[r][c4]) = v;
    }
    __syncthreads();
    int c = tid & 127;
    int rr0 = (tid >> 7) * 32;
    float wr[KW];
#pragma unroll
    for (int t = 0; t < KW; t++) wr[t] = w[(c0 + c) * KW + t];
    float bz = bias[c0 + c];
    __half* obase = out + ((size_t)b * SS + s0) * HH + c0 + c;
    float win[KW];
#pragma unroll
    for (int t = 0; t < KW; t++) win[t] = sb[rr0 + t][c];
#pragma unroll
    for (int r = 0; r < 32; r++) {
        float acc = bz;
#pragma unroll
        for (int t = 0; t < KW; t++) acc = fmaf(win[t], wr[t], acc);
        obase[(size_t)(rr0 + r) * HH] = __float2half(acc);
#pragma unroll
        for (int t = 0; t < KW - 1; t++) win[t] = win[t + 1];
        if (r < 31) win[KW - 1] = sb[rr0 + r + KW][c];
    }
}

// ---------------- fp16 GEMM: ldmatrix + cp.async staging ----------------
template <bool AHALF, bool LNA, bool OUTH, bool RELU, bool RES>
__global__ void __launch_bounds__(256, 2)
tgemm(const void* __restrict__ Av, const __half* __restrict__ W,
      const float* __restrict__ bias, const float* res,
      const float* __restrict__ stats, const float* __restrict__ lng,
      const float* __restrict__ lnb,
      void* __restrict__ outv, int Ndim, int Kdim) {
    __shared__ uint32_t Asm[2][128 * 12];
    __shared__ uint32_t Wsm[2][128 * 12];
    int bm = blockIdx.y * 128, bn = blockIdx.x * 128;
    int tid = threadIdx.x;
    int wid = tid >> 5, lane = tid & 31;
    int wm = (wid & 3) * 32, wn = (wid >> 2) * 64;

    float acc[2][8][4];
#pragma unroll
    for (int i = 0; i < 2; i++)
#pragma unroll
        for (int j = 0; j < 8; j++)
#pragma unroll
            for (int q = 0; q < 4; q++) acc[i][j][q] = 0.f;

    int tr = lane & 7, ts = lane >> 3;
    uint32_t aAddr = sptr(&Asm[0][0]) +
        (((wm + ((ts & 1) << 3) + tr) * 12 + ((ts >> 1) << 2)) << 2);
    uint32_t bAddr[4];
#pragma unroll
    for (int j4 = 0; j4 < 4; j4++)
        bAddr[j4] = sptr(&Wsm[0][0]) +
            (((wn + 8 * (2 * j4 + (ts >> 1)) + tr) * 12 + ((ts & 1) << 2)) << 2);

    int rowW = tid >> 1, grpW = tid & 1;
    const __half* Wp = W + (size_t)(bn + rowW) * Kdim + grpW * 8;
    int soW = rowW * 12 + grpW * 4;
    uint32_t wDst[2] = { sptr(&Wsm[0][soW]), sptr(&Wsm[1][soW]) };

    const __half* Ahp = nullptr;
    uint32_t aDst[2] = {0, 0};
    const float *Ap0 = nullptr, *Ap1 = nullptr;
    int so0 = 0, so1 = 0, c40 = 0;
    float m0 = 0.f, r0s = 1.f, m1 = 0.f, r1s = 1.f;
    if (AHALF) {
        Ahp = (const __half*)Av + (size_t)(bm + rowW) * Kdim + grpW * 8;
        aDst[0] = sptr(&Asm[0][soW]);
        aDst[1] = sptr(&Asm[1][soW]);
    } else {
        int row0 = tid >> 2;
        c40 = (tid & 3) << 2;
        int row1 = row0 + 64;
        Ap0 = (const float*)Av + (size_t)(bm + row0) * Kdim + c40;
        Ap1 = (const float*)Av + (size_t)(bm + row1) * Kdim + c40;
        so0 = row0 * 12 + (c40 >> 1);
        so1 = row1 * 12 + (c40 >> 1);
        if (LNA) {
            float2 st0 = *(const float2*)(stats + (size_t)(bm + row0) * 2);
            float2 st1 = *(const float2*)(stats + (size_t)(bm + row1) * 2);
            m0 = st0.x; r0s = st0.y; m1 = st1.x; r1s = st1.y;
        }
    }

    // ---- prologue: stage chunk 0 ----
    CPA16(wDst[0], Wp);
    if (AHALF) CPA16(aDst[0], Ahp);
    CPAC();
    float4 a0, a1, g4, b4;
    if (!AHALF) {
        a0 = *(const float4*)Ap0;
        a1 = *(const float4*)Ap1;
        if (LNA) {
            g4 = *(const float4*)(lng + c40);
            b4 = *(const float4*)(lnb + c40);
        }
        float4 ta0 = a0, ta1 = a1;
        if (LNA) {
            ta0.x = (a0.x - m0) * r0s * g4.x + b4.x;
            ta0.y = (a0.y - m0) * r0s * g4.y + b4.y;
            ta0.z = (a0.z - m0) * r0s * g4.z + b4.z;
            ta0.w = (a0.w - m0) * r0s * g4.w + b4.w;
            ta1.x = (a1.x - m1) * r1s * g4.x + b4.x;
            ta1.y = (a1.y - m1) * r1s * g4.y + b4.y;
            ta1.z = (a1.z - m1) * r1s * g4.z + b4.z;
            ta1.w = (a1.w - m1) * r1s * g4.w + b4.w;
        }
        uint2 u;
        u.x = h2(ta0.x, ta0.y); u.y = h2(ta0.z, ta0.w);
        *(uint2*)&Asm[0][so0] = u;
        u.x = h2(ta1.x, ta1.y); u.y = h2(ta1.z, ta1.w);
        *(uint2*)&Asm[0][so1] = u;
    }
    CPAW();
    __syncthreads();

    int buf = 0;
    int nk = Kdim >> 4;
    for (int s = 1;; s++) {
        bool more = (s < nk);
        if (more) {
            CPA16(wDst[buf ^ 1], Wp + s * 16);
            if (AHALF) CPA16(aDst[buf ^ 1], Ahp + s * 16);
            CPAC();
            if (!AHALF) {
                a0 = *(const float4*)(Ap0 + s * 16);
                a1 = *(const float4*)(Ap1 + s * 16);
                if (LNA) {
                    g4 = *(const float4*)(lng + s * 16 + c40);
                    b4 = *(const float4*)(lnb + s * 16 + c40);
                }
            }
        }
        // compute chunk in buf
        {
            uint32_t bo = buf ? 6144u : 0u;
            uint32_t af[2][4], bf[8][2];
            LDSMX4(af[0][0], af[0][1], af[0][2], af[0][3], aAddr + bo);
            LDSMX4(af[1][0], af[1][1], af[1][2], af[1][3], aAddr + bo + 768u);
#pragma unroll
            for (int j4 = 0; j4 < 4; j4++) {
                LDSMX4(bf[2 * j4][0], bf[2 * j4][1],
                       bf[2 * j4 + 1][0], bf[2 * j4 + 1][1], bAddr[j4] + bo);
            }
#pragma unroll
            for (int i = 0; i < 2; i++)
#pragma unroll
                for (int j = 0; j < 8; j++)
                    MMA_F16(acc[i][j], af[i], bf[j]);
        }
        if (!more) break;
        if (!AHALF) {
            float4 ta0 = a0, ta1 = a1;
            if (LNA) {
                ta0.x = (a0.x - m0) * r0s * g4.x + b4.x;
                ta0.y = (a0.y - m0) * r0s * g4.y + b4.y;
                ta0.z = (a0.z - m0) * r0s * g4.z + b4.z;
                ta0.w = (a0.w - m0) * r0s * g4.w + b4.w;
                ta1.x = (a1.x - m1) * r1s * g4.x + b4.x;
                ta1.y = (a1.y - m1) * r1s * g4.y + b4.y;
                ta1.z = (a1.z - m1) * r1s * g4.z + b4.z;
                ta1.w = (a1.w - m1) * r1s * g4.w + b4.w;
            }
            uint2 u;
            u.x = h2(ta0.x, ta0.y); u.y = h2(ta0.z, ta0.w);
            *(uint2*)&Asm[buf ^ 1][so0] = u;
            u.x = h2(ta1.x, ta1.y); u.y = h2(ta1.z, ta1.w);
            *(uint2*)&Asm[buf ^ 1][so1] = u;
        }
        CPAW();
        __syncthreads();
        buf ^= 1;
    }

    int r = lane >> 2, c = lane & 3;
#pragma unroll
    for (int i = 0; i < 2; i++) {
        int m0i = bm + wm + i * 16 + r;
#pragma unroll
        for (int j = 0; j < 8; j++) {
            int n0 = bn + wn + j * 8 + 2 * c;
            float2 b2 = *(const float2*)(bias + n0);
            float v0 = acc[i][j][0] + b2.x;
            float v1 = acc[i][j][1] + b2.y;
            float v2 = acc[i][j][2] + b2.x;
            float v3 = acc[i][j][3] + b2.y;
            if (RELU) {
                v0 = fmaxf(v0, 0.f); v1 = fmaxf(v1, 0.f);
                v2 = fmaxf(v2, 0.f); v3 = fmaxf(v3, 0.f);
            }
            if (RES) {
                float2 r0v = *(const float2*)(res + (size_t)m0i * Ndim + n0);
                float2 r1v = *(const float2*)(res + (size_t)(m0i + 8) * Ndim + n0);
                v0 += r0v.x; v1 += r0v.y; v2 += r1v.x; v3 += r1v.y;
            }
            if (OUTH) {
                __half* oh = (__half*)outv;
                *(uint32_t*)(oh + (size_t)m0i * Ndim + n0) = h2(v0, v1);
                *(uint32_t*)(oh + (size_t)(m0i + 8) * Ndim + n0) = h2(v2, v3);
            } else {
                float* of = (float*)outv;
                float2 o0 = {v0, v1}, o1 = {v2, v3};
                *(float2*)(of + (size_t)m0i * Ndim + n0) = o0;
                *(float2*)(of + (size_t)(m0i + 8) * Ndim + n0) = o1;
            }
        }
    }
}

// ---------------- attention (unchanged from R16-passing) ----------------
#define TQ    32
#define QSTP  36
#define KSTP  36
#define SCHP  520
#define EBST  72
#define RDST  40

__global__ void __launch_bounds__(256)
attn_kernel(const __half* __restrict__ QKV, const float* __restrict__ EK,
            const float* __restrict__ EV, __half* __restrict__ O) {
    int qt = blockIdx.x, h = blockIdx.y, b = blockIdx.z;
    int q0 = qt * TQ;
    extern __shared__ float sm[];
    uint32_t* qsu  = (uint32_t*)sm;             // [0, 1152)
    __half*   sch  = (__half*)(sm + 1152);      // [1152, 9472)  8320 w
    uint32_t* ktu  = (uint32_t*)(sm + 9472);    // [9472, 18688) 9216 w
    uint32_t* ebku = (uint32_t*)(sm + 18688);   // [18688, 20128) 1440 w
    float*    ebv  = sm + 20128;                // [20128, 23008) 2880 w
    float*    rdot = sm + 23008;                // [23008, 24288) 1280 w
    float*    wsum = sm + 24288;                // [24288, 25568) 1280 w
    float*    rsum = sm + 25568;                // [25568, 25600) 32 w

    int tid = threadIdx.x;
    int w = tid >> 5, lane = tid & 31;
    int r = lane >> 2, c = lane & 3;
    int tr = lane & 7, ts = lane >> 3;

    size_t bh_in  = ((size_t)b * SS) * RS3 + h * DK;
    size_t bh_out = ((size_t)b * SS) * HH  + h * DK;

#pragma unroll
    for (int i = 0; i < 2; i++) {
        int f = tid + (i << 8);
        int row = f >> 4, c4 = (f & 15) << 2;
        uint2 v = *(const uint2*)(QKV + bh_in + (size_t)(q0 + row) * RS3 + c4);
        uint32_t* d = qsu + row * QSTP + (c4 >> 1);
        d[0] = v.x; d[1] = v.y;
    }
    for (int f = tid; f < 40 * 16; f += 256) {
        int row = f >> 4, c4 = (f & 15) << 2;
        float4 vk = {0.f, 0.f, 0.f, 0.f}, vv = {0.f, 0.f, 0.f, 0.f};
        if (row < NV) {
            vk = *(const float4*)(EK + row * DK + c4);
            vv = *(const float4*)(EV + row * DK + c4);
        }
        uint32_t* dk = ebku + row * QSTP + (c4 >> 1);
        dk[0] = h2(vk.x, vk.y); dk[1] = h2(vk.z, vk.w);
        *(float4*)(ebv + row * EBST + c4) = vv;
    }
    for (int f = tid; f < 32 * RDST; f += 256) wsum[f] = 0.f;
    __syncthreads();

    if (w < 5) {
        float acc[2][4] = {{0.f, 0.f, 0.f, 0.f}, {0.f, 0.f, 0.f, 0.f}};
#pragma unroll
        for (int ks = 0; ks < 4; ks++) {
            uint32_t a[2][4], bf[2];
#pragma unroll
            for (int i = 0; i < 2; i++) {
                const uint32_t* p = qsu + (i * 16 + r) * QSTP + ks * 8 + c;
                a[i][0] = p[0]; a[i][1] = p[8 * QSTP];
                a[i][2] = p[4]; a[i][3] = p[8 * QSTP + 4];
            }
            const uint32_t* pb = ebku + (w * 8 + r) * QSTP + ks * 8 + c;
            bf[0] = pb[0]; bf[1] = pb[4];
            MMA_F16(acc[0], a[0], bf);
            MMA_F16(acc[1], a[1], bf);
        }
#pragma unroll
        for (int i = 0; i < 2; i++) {
            int row = i * 16 + r;
            rdot[row * RDST + w * 8 + 2 * c]           = acc[i][0];
            rdot[row * RDST + w * 8 + 2 * c + 1]       = acc[i][1];
            rdot[(row + 8) * RDST + w * 8 + 2 * c]     = acc[i][2];
            rdot[(row + 8) * RDST + w * 8 + 2 * c + 1] = acc[i][3];
        }
    }
    __syncthreads();

    uint32_t qAddr = sptr(qsu) +
        (((((ts & 1) << 3) + tr) * QSTP + ((ts >> 1) << 2)) << 2);
    uint32_t kAddr0 = sptr(ktu) +
        (((w * 32 + 8 * (ts >> 1) + tr) * KSTP + ((ts & 1) << 2)) << 2);
    uint32_t kAddr1 = kAddr0 + ((16 * KSTP) << 2);
    uint32_t pAddr = sptr(sch) +
        ((((ts & 1) << 3) + tr) * SCHP + ((ts >> 1) << 3)) * 2;
    uint32_t vAddr = sptr(ktu) + (((lane & 15) * KSTP + w * 4) << 2);

    for (int kt0 = 0; kt0 < SS; kt0 += 256) {
#pragma unroll
        for (int i = 0; i < 16; i++) {
            int f = tid + (i << 8);
            int rr = f >> 4, c4 = (f & 15) << 2;
            uint2 v = *(const uint2*)(QKV + bh_in + HH + (size_t)(kt0 + rr) * RS3 + c4);
            uint32_t* d = ktu + rr * KSTP + (c4 >> 1);
            d[0] = v.x; d[1] = v.y;
        }
        __syncthreads();
        float acc[2][4][4];
#pragma unroll
        for (int i = 0; i < 2; i++)
#pragma unroll
            for (int j = 0; j < 4; j++)
#pragma unroll
                for (int q = 0; q < 4; q++) acc[i][j][q] = 0.f;
#pragma unroll
        for (int ks = 0; ks < 4; ks++) {
            uint32_t kso = ks * 32;
            uint32_t a[2][4], bf[4][2];
            LDSMX4(a[0][0], a[0][1], a[0][2], a[0][3], qAddr + kso);
            LDSMX4(a[1][0], a[1][1], a[1][2], a[1][3],
                   qAddr + ((16 * QSTP) << 2) + kso);
            LDSMX4(bf[0][0], bf[0][1], bf[1][0], bf[1][1], kAddr0 + kso);
            LDSMX4(bf[2][0], bf[2][1], bf[3][0], bf[3][1], kAddr1 + kso);
#pragma unroll
            for (int jn = 0; jn < 4; jn++) {
                MMA_F16(acc[0][jn], a[0], bf[jn]);
                MMA_F16(acc[1][jn], a[1], bf[jn]);
            }
        }
#pragma unroll
        for (int i = 0; i < 2; i++) {
#pragma unroll
            for (int jn = 0; jn < 4; jn++) {
                int colb = kt0 + w * 32 + jn * 8 + 2 * c;
                int row0 = i * 16 + r, row1 = row0 + 8;
                int qg0 = q0 + row0, qg1 = q0 + row1;
                int d00 = colb - qg0;     d00 = d00 < -16 ? -16 : (d00 > 16 ? 16 : d00);
                int d01 = colb + 1 - qg0; d01 = d01 < -16 ? -16 : (d01 > 16 ? 16 : d01);
                int d10 = colb - qg1;     d10 = d10 < -16 ? -16 : (d10 > 16 ? 16 : d10);
                int d11 = colb + 1 - qg1; d11 = d11 < -16 ? -16 : (d11 > 16 ? 16 : d11);
                float v0 = acc[i][jn][0] + rdot[row0 * RDST + d00 + 16];
                float v1 = acc[i][jn][1] + rdot[row0 * RDST + d01 + 16];
                float v2 = acc[i][jn][2] + rdot[row1 * RDST + d10 + 16];
                float v3 = acc[i][jn][3] + rdot[row1 * RDST + d11 + 16];
                *(uint32_t*)(sch + row0 * SCHP + colb) = h2(v0, v1);
                *(uint32_t*)(sch + row1 * SCHP + colb) = h2(v2, v3);
            }
        }
        __syncthreads();
    }

    {
        const float L2E = 1.4426950408889634f;
        for (int rr = w; rr < TQ; rr += 8) {
            __half2* hrow = (__half2*)(sch + rr * SCHP);
            int qg = q0 + rr;
            float mx = -1e30f;
#pragma unroll
            for (int i = 0; i < 8; i++) {
                float2 f = __half22float2(hrow[lane + 32 * i]);
                mx = fmaxf(mx, fmaxf(f.x, f.y));
            }
#pragma unroll
            for (int o = 16; o > 0; o >>= 1)
                mx = fmaxf(mx, __shfl_xor_sync(0xffffffffu, mx, o));
            float sum = 0.f, w0 = 0.f, w32 = 0.f;
#pragma unroll
            for (int i = 0; i < 8; i++) {
                int kp = lane + 32 * i;
                float2 f = __half22float2(hrow[kp]);
                uint32_t packed = h2((f.x - mx) * L2E, (f.y - mx) * L2E);
                uint32_t er;
                asm("ex2.approx.f16x2 %0, %1;" : "=r"(er) : "r"(packed));
                hrow[kp] = *reinterpret_cast<__half2*>(&er);
                float2 e = __half22float2(*reinterpret_cast<__half2*>(&er));
                sum += e.x + e.y;
                int k0 = 2 * kp, k1 = k0 + 1;
                if (k0 <= qg - 16) w0 += e.x;
                if (k1 <= qg - 16) w0 += e.y;
                if (k0 >= qg + 16) w32 += e.x;
                if (k1 >= qg + 16) w32 += e.y;
            }
#pragma unroll
            for (int o = 16; o > 0; o >>= 1) {
                sum += __shfl_xor_sync(0xffffffffu, sum, o);
                w0  += __shfl_xor_sync(0xffffffffu, w0, o);
                w32 += __shfl_xor_sync(0xffffffffu, w32, o);
            }
            __syncwarp();
            if (lane == 0) {
                rsum[rr] = sum;
                wsum[rr * RDST + 0] = w0;
                wsum[rr * RDST + 32] = w32;
            } else {
                int k = qg + lane - 16;
                wsum[rr * RDST + lane] =
                    (k >= 0 && k < SS) ? __half2float(((__half*)hrow)[k]) : 0.f;
            }
        }
    }
    __syncthreads();

    {
        float acc[2][4];
#pragma unroll
        for (int i = 0; i < 2; i++)
#pragma unroll
            for (int q = 0; q < 4; q++) acc[i][q] = 0.f;

#pragma unroll
        for (int ks = 0; ks < 5; ks++) {
            uint32_t a[2][4], bf[2];
#pragma unroll
            for (int i = 0; i < 2; i++) {
                int base = (i * 16 + r) * RDST + ks * 8 + c;
                a[i][0] = U(wsum[base]);
                a[i][1] = U(wsum[base + 8 * RDST]);
                a[i][2] = U(wsum[base + 4]);
                a[i][3] = U(wsum[base + 8 * RDST + 4]);
            }
            int pb = (ks * 8 + c) * EBST + w * 8 + r;
            bf[0] = U(ebv[pb]); bf[1] = U(ebv[pb + 4 * EBST]);
            MMA_TF32(acc[0], a[0], bf);
            MMA_TF32(acc[1], a[1], bf);
        }

        for (int kt0 = 0; kt0 < SS; kt0 += 256) {
#pragma unroll
            for (int i = 0; i < 16; i++) {
                int f = tid + (i << 8);
                int rr = f >> 4, c4 = (f & 15) << 2;
                uint2 v = *(const uint2*)(QKV + bh_in + 2 * HH +
                                          (size_t)(kt0 + rr) * RS3 + c4);
                uint32_t* d = ktu + rr * KSTP + (c4 >> 1);
                d[0] = v.x; d[1] = v.y;
            }
            __syncthreads();
#pragma unroll 4
            for (int ks = 0; ks < 16; ks++) {
                uint32_t a[2][4], bf[2];
                uint32_t po = (uint32_t)(kt0 + ks * 16) * 2;
                LDSMX4(a[0][0], a[0][1], a[0][2], a[0][3], pAddr + po);
                LDSMX4(a[1][0], a[1][1], a[1][2], a[1][3],
                       pAddr + (16 * SCHP) * 2 + po);
                LDSMX2T(bf[0], bf[1], vAddr + ((ks * 16 * KSTP) << 2));
                MMA_F16(acc[0], a[0], bf);
                MMA_F16(acc[1], a[1], bf);
            }
            __syncthreads();
        }

#pragma unroll
        for (int i = 0; i < 2; i++) {
            int row0 = i * 16 + r, row1 = row0 + 8;
            float inv0 = 1.f / rsum[row0];
            float inv1 = 1.f / rsum[row1];
            int col = w * 8 + 2 * c;
            *(uint32_t*)(O + bh_out + (size_t)(q0 + row0) * HH + col) =
                h2(acc[i][0] * inv0, acc[i][1] * inv0);
            *(uint32_t*)(O + bh_out + (size_t)(q0 + row1) * HH + col) =
                h2(acc[i][2] * inv1, acc[i][3] * inv1);
        }
    }
}

// ---------------- launcher ----------------
extern "C" void kernel_launch(void* const* d_in, const int* in_sizes, int n_in,
                              void* d_out, int out_size) {
    const float* x    = (const float*)d_in[0];
    const int*   mask = (const int*)d_in[1];
    const float* dw_w = (const float*)d_in[2];
    const float* dw_b = (const float*)d_in[3];
    const float* pw_w = (const float*)d_in[4];
    const float* pw_b = (const float*)d_in[5];
    const float* lcg  = (const float*)d_in[6];
    const float* lcb  = (const float*)d_in[7];
    const float* wq   = (const float*)d_in[8];
    const float* bq   = (const float*)d_in[9];
    const float* wk   = (const float*)d_in[10];
    const float* bk   = (const float*)d_in[11];
    const float* wv   = (const float*)d_in[12];
    const float* bv   = (const float*)d_in[13];
    const float* wo   = (const float*)d_in[14];
    const float* bo   = (const float*)d_in[15];
    const float* ek   = (const float*)d_in[16];
    const float* ev   = (const float*)d_in[17];
    const float* lag  = (const float*)d_in[18];
    const float* lab  = (const float*)d_in[19];
    const float* wff  = (const float*)d_in[20];
    const float* bff  = (const float*)d_in[21];
    const float* lfg  = (const float*)d_in[22];
    const float* lfb  = (const float*)d_in[23];
    float* xo = (float*)d_out;

    float *phf, *pqkv, *pbqkv, *ppe, *pst;
    __half* pwh;
    cudaGetSymbolAddress((void**)&phf, g_h);
    cudaGetSymbolAddress((void**)&pqkv, g_qkv);
    cudaGetSymbolAddress((void**)&pwh, g_wh);
    cudaGetSymbolAddress((void**)&pbqkv, g_bqkv);
    cudaGetSymbolAddress((void**)&ppe, g_pe);
    cudaGetSymbolAddress((void**)&pst, g_stats);

    __half* ph_h   = (__half*)phf;
    __half* pqkv_h = (__half*)pqkv;
    float*  px     = pqkv + (size_t)ROWS * RS3 / 2;

    cudaMemcpyAsync(pbqkv,          bq, HH * 4, cudaMemcpyDeviceToDevice);
    cudaMemcpyAsync(pbqkv + HH,     bk, HH * 4, cudaMemcpyDeviceToDevice);
    cudaMemcpyAsync(pbqkv + 2 * HH, bv, HH * 4, cudaMemcpyDeviceToDevice);

    const int ATTN_SMEM = 25600 * 4;   // 100KB -> 2 blocks/SM
    cudaFuncSetAttribute((const void*)attn_kernel,
                         cudaFuncAttributeMaxDynamicSharedMemorySize, ATTN_SMEM);

    dim3 gemm_grid(HH / 128, ROWS / 128);
    dim3 qkv_grid(RS3 / 128, ROWS / 128);
    dim3 dw_grid(8, 4, 32);

    wconv_kernel<<<dim3(HH * HH / 256, 7), 256>>>(pw_w, wq, wk, wv, wo, wff, pwh);
    pe_kernel<<<(SS * HH) / 256, 256>>>(ppe);

    // fused: xo = x + pe*mask, stats for first LN
    pos_add_ln<<<ROWS / 8, 256>>>(x, mask, ppe, xo, pst);

    for (int i = 0; i < 2; i++) {
        if (i) ln_stats<<<ROWS / 8, 256>>>(xo, pst);
        dwconv_kernel<<<dw_grid, 256>>>(xo, pst, lcg + i * HH, lcb + i * HH,
                                        dw_w + i * HH * KW, dw_b + i * HH, ph_h);
        tgemm<true, false, false, true, true><<<gemm_grid, 256>>>(
            ph_h, pwh + (size_t)i * HH * HH, pw_b + i * HH, xo,
            nullptr, nullptr, nullptr, xo, HH, HH);
    }

    ln_stats<<<ROWS / 8, 256>>>(xo, pst);
    tgemm<false, true, true, false, false><<<qkv_grid, 256>>>(
        xo, pwh + (size_t)2 * HH * HH, pbqkv, nullptr,
        pst, lag, lab, pqkv_h, RS3, HH);

    attn_kernel<<<dim3(SS / TQ, NHD, BB), 256, ATTN_SMEM>>>(pqkv_h, ek, ev, ph_h);

    tgemm<true, false, false, false, true><<<gemm_grid, 256>>>(
        ph_h, pwh + (size_t)5 * HH * HH, bo, xo,
        nullptr, nullptr, nullptr, px, HH, HH);

    ln_stats<<<ROWS / 8, 256>>>(px, pst);
    tgemm<false, true, false, true, true><<<gemm_grid, 256>>>(
        px, pwh + (size_t)6 * HH * HH, bff, px,
        pst, lfg, lfb, xo, HH, HH);
}